// round 10
// baseline (speedup 1.0000x reference)
#include <cuda_runtime.h>
#include <cuda_bf16.h>
#include <math.h>
#include <stdint.h>

// ---------------- problem constants ----------------
#define B_    32
#define LT_   64
#define LS_   256
#define NTOK  320      // LT + LS
#define DIM_  768
#define H_    12
#define DH    64
#define LK_   180
#define LR_   76
#define N2    244      // LT + LK

#if defined(__CUDA_ARCH__) && defined(__CUDA_ARCH_FEAT_SM103_ALL)
#define HAS_TCGEN05 1
#else
#define HAS_TCGEN05 0
#endif

typedef __nv_bfloat16 bf16;

// padded sizes for tile-OOB-safe reads
#define QKVS_ROWS (B_ * NTOK + 64)                          // +64 token rows
#define PSZ  ((size_t)B_ * H_ * NTOK * NTOK + 64 * NTOK)    // +64 P rows
#define VTSZ ((size_t)B_ * H_ * DH * NTOK + 64 * NTOK)      // +64 Vt rows

// ---------------- scratch (per-branch duplicated) ----------------
__device__ float g_XLN [2][B_ * NTOK * DIM_];
__device__ float g_QKV [2][B_ * NTOK * 3 * DIM_];
__device__ float g_Q64 [2][B_ * LT_ * DIM_];
__device__ float g_ATTN[2][(size_t)B_ * H_ * NTOK * NTOK];
__device__ float g_X1  [2][B_ * NTOK * DIM_];
__device__ float g_S   [2][B_ * LS_];
__device__ int   g_ORD [2][B_ * LS_];
__device__ float g_X2  [2][B_ * N2 * DIM_];
__device__ float g_XLN2[2][B_ * N2 * DIM_];

__device__ unsigned short g_XLNh [2][B_ * NTOK * DIM_];
__device__ unsigned short g_XLNl [2][B_ * NTOK * DIM_];
__device__ unsigned short g_QKVh [2][QKVS_ROWS * 3 * DIM_];
__device__ unsigned short g_QKVl [2][QKVS_ROWS * 3 * DIM_];
__device__ unsigned short g_Ph   [2][PSZ];
__device__ unsigned short g_Pl   [2][PSZ];
__device__ unsigned short g_Vth  [2][VTSZ];
__device__ unsigned short g_Vtl  [2][VTSZ];
__device__ unsigned short g_Oh   [2][B_ * NTOK * DIM_];
__device__ unsigned short g_Ol   [2][B_ * NTOK * DIM_];
__device__ unsigned short g_XLN2h[2][B_ * N2 * DIM_];
__device__ unsigned short g_XLN2l[2][B_ * N2 * DIM_];
__device__ unsigned short g_H1h  [2][B_ * N2 * 4 * DIM_];
__device__ unsigned short g_H1l  [2][B_ * N2 * 4 * DIM_];

// shared weight splits
__device__ unsigned short g_WqkvTh[3 * DIM_ * DIM_];
__device__ unsigned short g_WqkvTl[3 * DIM_ * DIM_];
__device__ unsigned short g_WprojTh[DIM_ * DIM_];
__device__ unsigned short g_WprojTl[DIM_ * DIM_];
__device__ unsigned short g_W1Th [4 * DIM_ * DIM_];
__device__ unsigned short g_W1Tl [4 * DIM_ * DIM_];
__device__ unsigned short g_W2Th [4 * DIM_ * DIM_];
__device__ unsigned short g_W2Tl [4 * DIM_ * DIM_];

__device__ __forceinline__ void split_bf16(float v, bf16& h, bf16& l) {
    h = __float2bfloat16(v);
    l = __float2bfloat16(v - __bfloat162float(h));
}

// =====================================================================
// tcgen05 helpers
// =====================================================================
#if HAS_TCGEN05
__device__ __forceinline__ uint32_t elect_one_pred() {
    uint32_t pred;
    asm volatile(
        "{\n\t.reg .pred p;\n\telect.sync _|p, 0xFFFFFFFF;\n\tselp.b32 %0, 1, 0, p;\n\t}"
        : "=r"(pred));
    return pred;
}
__device__ __forceinline__ uint32_t smem_to_u32(const void* smem_ptr) {
    uint32_t addr;
    asm("{ .reg .u64 tmp; cvta.to.shared.u64 tmp, %1; cvt.u32.u64 %0, tmp; }"
        : "=r"(addr) : "l"(smem_ptr));
    return addr;
}
__device__ __forceinline__ void cp16(uint32_t s, const void* g) {
    asm volatile("cp.async.cg.shared.global [%0], [%1], 16;" :: "r"(s), "l"(g) : "memory");
}
#define CP_COMMIT() asm volatile("cp.async.commit_group;" ::: "memory")
#define CP_WAIT(n)  asm volatile("cp.async.wait_group %0;" :: "n"(n) : "memory")

#define TCGEN05_ALLOC(a, n) \
    asm volatile("tcgen05.alloc.cta_group::1.sync.aligned.shared::cta.b32 [%0], %1;" \
        :: "r"((uint32_t)(a)), "r"((uint32_t)(n)) : "memory")
#define TCGEN05_DEALLOC(t, n) \
    asm volatile("tcgen05.dealloc.cta_group::1.sync.aligned.b32 %0, %1;" \
        :: "r"(t), "r"((uint32_t)(n)))
#define TCGEN05_RELINQUISH_ALLOC_PERMIT() \
    asm volatile("tcgen05.relinquish_alloc_permit.cta_group::1.sync.aligned;")
#define TCGEN05_COMMIT(m) \
    asm volatile("tcgen05.commit.cta_group::1.mbarrier::arrive::one.shared::cluster.b64 [%0];" \
        :: "r"((uint32_t)(m)) : "memory")
#define TCGEN05_WAIT_LD()  asm volatile("tcgen05.wait::ld.sync.aligned;" ::: "memory")
#define TCGEN05_FENCE_BEFORE() asm volatile("tcgen05.fence::before_thread_sync;" ::: "memory")
#define TCGEN05_FENCE_AFTER()  asm volatile("tcgen05.fence::after_thread_sync;" ::: "memory")
#define FENCE_PROXY_ASYNC_SHARED_CTA() asm volatile("fence.proxy.async.shared::cta;" ::: "memory")
#define MBARRIER_INIT(m, c) \
    asm volatile("mbarrier.init.shared.b64 [%0], %1;" :: "r"((uint32_t)(m)), "r"((uint32_t)(c)) : "memory")
#define MBARRIER_INVAL(m) \
    asm volatile("mbarrier.inval.shared.b64 [%0];" :: "r"((uint32_t)(m)) : "memory")

#define MBARRIER_WAIT_PARITY(mb, pp) do { \
    uint32_t _mbar = (uint32_t)(mb); \
    uint32_t _parity = (uint32_t)(pp); \
    uint32_t _done; \
    asm volatile( \
        "{\n\t.reg .pred p;\n\t" \
        "mbarrier.try_wait.parity.acquire.cta.shared::cta.b64 p, [%1], %2;\n\t" \
        "selp.b32 %0, 1, 0, p;\n\t}" \
        : "=r"(_done) : "r"(_mbar), "r"(_parity) : "memory"); \
    if (!_done) { \
        asm volatile( \
            "{\n\t.reg .pred P1;\n\t" \
            "WAIT_LOOP_%=:\n\t" \
            "mbarrier.try_wait.parity.acquire.cta.shared::cta.b64 P1, [%0], %1, 0x989680;\n\t" \
            "@P1 bra.uni WAIT_DONE_%=;\n\t" \
            "bra.uni WAIT_LOOP_%=;\n\t" \
            "WAIT_DONE_%=:\n\t}" \
            :: "r"(_mbar), "r"(_parity) : "memory"); \
    } \
} while(0)

#define TCGEN05_LD_32X32B_X32(r, tmem_addr) \
    asm volatile( \
        "tcgen05.ld.sync.aligned.32x32b.x32.b32 " \
        "{%0, %1, %2, %3, %4, %5, %6, %7, " \
        " %8, %9, %10, %11, %12, %13, %14, %15, " \
        " %16, %17, %18, %19, %20, %21, %22, %23, " \
        " %24, %25, %26, %27, %28, %29, %30, %31}, [%32];" \
        : "=r"((r)[0]),  "=r"((r)[1]),  "=r"((r)[2]),  "=r"((r)[3]), \
          "=r"((r)[4]),  "=r"((r)[5]),  "=r"((r)[6]),  "=r"((r)[7]), \
          "=r"((r)[8]),  "=r"((r)[9]),  "=r"((r)[10]), "=r"((r)[11]), \
          "=r"((r)[12]), "=r"((r)[13]), "=r"((r)[14]), "=r"((r)[15]), \
          "=r"((r)[16]), "=r"((r)[17]), "=r"((r)[18]), "=r"((r)[19]), \
          "=r"((r)[20]), "=r"((r)[21]), "=r"((r)[22]), "=r"((r)[23]), \
          "=r"((r)[24]), "=r"((r)[25]), "=r"((r)[26]), "=r"((r)[27]), \
          "=r"((r)[28]), "=r"((r)[29]), "=r"((r)[30]), "=r"((r)[31]) \
        : "r"(tmem_addr))

static constexpr uint64_t SMEM_DESC_BASE_SW128 =
    (uint64_t(2)  << 61) | (uint64_t(1) << 46) | (uint64_t(64) << 32) | (uint64_t(1) << 16);
#define MAKE_SMEM_DESC(base_addr) \
    (SMEM_DESC_BASE_SW128 | ((uint64_t)((base_addr) >> 4) & 0x3FFF))

__device__ __forceinline__ void tc_mma_f16_ss(uint32_t d, uint64_t a, uint64_t b,
                                              uint32_t idesc, uint32_t en)
{
    asm volatile(
        "{\n\t.reg .pred p;\n\tsetp.ne.u32 p, %5, 0;\n\t"
        "tcgen05.mma.cta_group::1.kind::f16 [%0], %1, %2, %3, {%4, %4, %4, %4}, p;\n\t}"
        :: "r"(d), "l"(a), "l"(b), "r"(idesc), "r"(0u), "r"(en) : "memory");
}
#endif // HAS_TCGEN05

#define TC_THREADS 256
#define TC_SMEM_TOTAL (1024 + 2 * 4 * 16384)   // 132096 bytes
#define TC_IDESC 0x8200490u   // F32 accum, bf16 x bf16, N=128, M=128

// =====================================================================
// tc_gemm2: C[M,N] = act(A@B^T + bias + Res), pre-split bf16 hi/lo inputs.
// cp.async pipelined. (unchanged from round 9 except C nullable w/ OUTSPLIT)
// =====================================================================
template<int ACT, bool OUTSPLIT>
__global__ __launch_bounds__(TC_THREADS)
void tc_gemm2(const bf16* __restrict__ Ah, const bf16* __restrict__ Al, int lda,
              const bf16* __restrict__ Bh, const bf16* __restrict__ Bl, int ldb,
              float* __restrict__ C, int ldc,
              bf16* __restrict__ Ch, bf16* __restrict__ Cl,
              const float* __restrict__ bias,
              const float* __restrict__ Res, int ldr,
              int K)
{
#if HAS_TCGEN05
    extern __shared__ char smem[];
    const uint32_t sb = smem_to_u32(smem);
    const int tid = threadIdx.x;
    const int wid = tid >> 5;
    const int lid = tid & 31;
    const int m0 = blockIdx.y * 128;
    const int n0 = blockIdx.x * 128;

    if (wid == 0) {
        TCGEN05_ALLOC(sb + 0, 128);
        TCGEN05_RELINQUISH_ALLOC_PERMIT();
    }
    if (tid == 0) { MBARRIER_INIT(sb + 16, 1); MBARRIER_INIT(sb + 24, 1); }
    __syncthreads();
    uint32_t tmem;
    asm volatile("ld.shared.b32 %0, [%1];" : "=r"(tmem) : "r"(sb));

    const int nk = K >> 6;
    const int lr  = tid >> 3;
    const int lcq = (tid & 7) * 8;

    #define TC_ISSUE_CHUNK(ktv)  do {                                              \
        const int _buf = (ktv) & 1;                                                \
        uint32_t _db = sb + 1024 + _buf * 65536;                                   \
        const bf16* _Agh = Ah + (long long)m0 * lda + (ktv) * 64;                  \
        const bf16* _Agl = Al + (long long)m0 * lda + (ktv) * 64;                  \
        const bf16* _Bgh = Bh + (long long)n0 * ldb + (ktv) * 64;                  \
        const bf16* _Bgl = Bl + (long long)n0 * ldb + (ktv) * 64;                  \
        _Pragma("unroll")                                                          \
        for (int _i = 0; _i < 4; _i++) {                                           \
            int _r = lr + _i * 32;                                                 \
            uint32_t _bo = _r * 128 + lcq * 2;                                     \
            uint32_t _so = _bo ^ ((_bo >> 3) & 0x70);                              \
            cp16(_db + _so,          _Agh + (long long)_r * lda + lcq);            \
            cp16(_db + 16384 + _so,  _Agl + (long long)_r * lda + lcq);            \
            cp16(_db + 32768 + _so,  _Bgh + (long long)_r * ldb + lcq);            \
            cp16(_db + 49152 + _so,  _Bgl + (long long)_r * ldb + lcq);            \
        }                                                                          \
        CP_COMMIT();                                                               \
    } while (0)

    TC_ISSUE_CHUNK(0);
    for (int kt = 0; kt < nk; kt++) {
        if (kt + 1 < nk) {
            if (kt >= 1)
                MBARRIER_WAIT_PARITY(sb + 16 + 8 * ((kt - 1) & 1), ((kt - 1) >> 1) & 1);
            TC_ISSUE_CHUNK(kt + 1);
            CP_WAIT(1);
        } else {
            CP_WAIT(0);
        }
        FENCE_PROXY_ASYNC_SHARED_CTA();
        __syncthreads();

        if (wid == 0) {
            if (elect_one_pred()) {
                uint32_t ab = sb + 1024 + (kt & 1) * 65536;
                uint64_t dAh = MAKE_SMEM_DESC(ab);
                uint64_t dAl = MAKE_SMEM_DESC(ab + 16384);
                uint64_t dBh = MAKE_SMEM_DESC(ab + 32768);
                uint64_t dBl = MAKE_SMEM_DESC(ab + 49152);
                #pragma unroll
                for (int k = 0; k < 4; k++)
                    tc_mma_f16_ss(tmem, dAh + k * 2, dBh + k * 2, TC_IDESC,
                                  (kt == 0 && k == 0) ? 0u : 1u);
                #pragma unroll
                for (int k = 0; k < 4; k++)
                    tc_mma_f16_ss(tmem, dAh + k * 2, dBl + k * 2, TC_IDESC, 1u);
                #pragma unroll
                for (int k = 0; k < 4; k++)
                    tc_mma_f16_ss(tmem, dAl + k * 2, dBh + k * 2, TC_IDESC, 1u);
                TCGEN05_COMMIT(sb + 16 + 8 * (kt & 1));
            }
        }
    }
    #undef TC_ISSUE_CHUNK

    if (nk >= 2)
        MBARRIER_WAIT_PARITY(sb + 16 + 8 * ((nk - 2) & 1), ((nk - 2) >> 1) & 1);
    MBARRIER_WAIT_PARITY(sb + 16 + 8 * ((nk - 1) & 1), ((nk - 1) >> 1) & 1);
    TCGEN05_FENCE_AFTER();

    if (wid < 4) {
        int m = m0 + wid * 32 + lid;
        float* Crow = C ? (C + (long long)m * ldc + n0) : (float*)0;
        bf16* Chrow = OUTSPLIT ? (Ch + (long long)m * ldc + n0) : (bf16*)0;
        bf16* Clrow = OUTSPLIT ? (Cl + (long long)m * ldc + n0) : (bf16*)0;
        const float* Rrow = Res ? (Res + (long long)m * ldr + n0) : (const float*)0;
        #pragma unroll
        for (int cb = 0; cb < 128; cb += 32) {
            uint32_t d[32];
            TCGEN05_LD_32X32B_X32(d, tmem + cb);
            TCGEN05_WAIT_LD();
            float vout[32];
            #pragma unroll
            for (int j = 0; j < 32; j++) {
                float v = __uint_as_float(d[j]);
                if (bias) v += bias[n0 + cb + j];
                if (Rrow) v += Rrow[cb + j];
                if (ACT == 1) v = 0.5f * v * (1.0f + erff(v * 0.70710678118654752f));
                vout[j] = v;
            }
            if (Crow) {
                #pragma unroll
                for (int q = 0; q < 32; q += 4)
                    *(float4*)&Crow[cb + q] = *(float4*)&vout[q];
            }
            if (OUTSPLIT) {
                #pragma unroll
                for (int q = 0; q < 32; q += 2) {
                    bf16 h0, l0, h1, l1;
                    split_bf16(vout[q], h0, l0);
                    split_bf16(vout[q + 1], h1, l1);
                    unsigned int hw = (unsigned int)__bfloat16_as_ushort(h0) |
                                      ((unsigned int)__bfloat16_as_ushort(h1) << 16);
                    unsigned int lw = (unsigned int)__bfloat16_as_ushort(l0) |
                                      ((unsigned int)__bfloat16_as_ushort(l1) << 16);
                    *(unsigned int*)&Chrow[cb + q] = hw;
                    *(unsigned int*)&Clrow[cb + q] = lw;
                }
            }
        }
        TCGEN05_FENCE_BEFORE();
    }
    __syncthreads();
    if (tid == 0) { MBARRIER_INVAL(sb + 16); MBARRIER_INVAL(sb + 24); }
    __syncthreads();
    if (wid == 0) TCGEN05_DEALLOC(tmem, 128);
#else
    // fp32 fallback (never runs on GB300)
    const int tid = threadIdx.x;
    const int m0 = blockIdx.y * 128;
    const int n0 = blockIdx.x * 128;
    for (int e = tid; e < 128 * 128; e += TC_THREADS) {
        int mi = e >> 7, ni = e & 127;
        int m = m0 + mi, n = n0 + ni;
        float s = 0.f;
        for (int k = 0; k < K; k++)
            s += (__bfloat162float(Ah[(long long)m * lda + k]) + __bfloat162float(Al[(long long)m * lda + k])) *
                 (__bfloat162float(Bh[(long long)n * ldb + k]) + __bfloat162float(Bl[(long long)n * ldb + k]));
        if (bias) s += bias[n];
        if (Res)  s += Res[(long long)m * ldr + n];
        if (ACT == 1) s = 0.5f * s * (1.0f + erff(s * 0.70710678118654752f));
        if (C) C[(long long)m * ldc + n] = s;
        if (OUTSPLIT) {
            bf16 h, l; split_bf16(s, h, l);
            Ch[(long long)m * ldc + n] = h;
            Cl[(long long)m * ldc + n] = l;
        }
    }
#endif
}

// =====================================================================
// tc_bgemm: batched C[z][M,N] = alpha * A[z] @ B[z]^T  (split-bf16 inputs)
// grid (Ntiles, Mtiles, Z). z -> ob=z/bdiv, ib=z%bdiv offsets.
// Store-guarded (mvalid/nvalid); pad reads are in-bounds via over-allocation.
// =====================================================================
template<bool OUTSPLIT>
__global__ __launch_bounds__(TC_THREADS)
void tc_bgemm(const bf16* __restrict__ Ah, const bf16* __restrict__ Al, int lda,
              long long sA1, long long sA2,
              const bf16* __restrict__ Bh, const bf16* __restrict__ Bl, int ldb,
              long long sB1, long long sB2,
              float* __restrict__ C, int ldc, long long sC1, long long sC2,
              bf16* __restrict__ Ch, bf16* __restrict__ Cl, int ldcs,
              long long sCs1, long long sCs2,
              int K, int bdiv, float alpha, int mvalid, int nvalid)
{
    int z = blockIdx.z;
    int ob = z / bdiv, ib = z - ob * bdiv;
    Ah += ob * sA1 + ib * sA2;  Al += ob * sA1 + ib * sA2;
    Bh += ob * sB1 + ib * sB2;  Bl += ob * sB1 + ib * sB2;
    if (C) C += ob * sC1 + ib * sC2;
    if (OUTSPLIT) { Ch += ob * sCs1 + ib * sCs2; Cl += ob * sCs1 + ib * sCs2; }

#if HAS_TCGEN05
    extern __shared__ char smem[];
    const uint32_t sb = smem_to_u32(smem);
    const int tid = threadIdx.x;
    const int wid = tid >> 5;
    const int lid = tid & 31;
    const int m0 = blockIdx.y * 128;
    const int n0 = blockIdx.x * 128;

    if (wid == 0) {
        TCGEN05_ALLOC(sb + 0, 128);
        TCGEN05_RELINQUISH_ALLOC_PERMIT();
    }
    if (tid == 0) { MBARRIER_INIT(sb + 16, 1); MBARRIER_INIT(sb + 24, 1); }
    __syncthreads();
    uint32_t tmem;
    asm volatile("ld.shared.b32 %0, [%1];" : "=r"(tmem) : "r"(sb));

    const int nk = K >> 6;
    const int lr  = tid >> 3;
    const int lcq = (tid & 7) * 8;

    #define TCB_ISSUE(ktv)  do {                                                   \
        const int _buf = (ktv) & 1;                                                \
        uint32_t _db = sb + 1024 + _buf * 65536;                                   \
        const bf16* _Agh = Ah + (long long)m0 * lda + (ktv) * 64;                  \
        const bf16* _Agl = Al + (long long)m0 * lda + (ktv) * 64;                  \
        const bf16* _Bgh = Bh + (long long)n0 * ldb + (ktv) * 64;                  \
        const bf16* _Bgl = Bl + (long long)n0 * ldb + (ktv) * 64;                  \
        _Pragma("unroll")                                                          \
        for (int _i = 0; _i < 4; _i++) {                                           \
            int _r = lr + _i * 32;                                                 \
            uint32_t _bo = _r * 128 + lcq * 2;                                     \
            uint32_t _so = _bo ^ ((_bo >> 3) & 0x70);                              \
            cp16(_db + _so,          _Agh + (long long)_r * lda + lcq);            \
            cp16(_db + 16384 + _so,  _Agl + (long long)_r * lda + lcq);            \
            cp16(_db + 32768 + _so,  _Bgh + (long long)_r * ldb + lcq);            \
            cp16(_db + 49152 + _so,  _Bgl + (long long)_r * ldb + lcq);            \
        }                                                                          \
        CP_COMMIT();                                                               \
    } while (0)

    TCB_ISSUE(0);
    for (int kt = 0; kt < nk; kt++) {
        if (kt + 1 < nk) {
            if (kt >= 1)
                MBARRIER_WAIT_PARITY(sb + 16 + 8 * ((kt - 1) & 1), ((kt - 1) >> 1) & 1);
            TCB_ISSUE(kt + 1);
            CP_WAIT(1);
        } else {
            CP_WAIT(0);
        }
        FENCE_PROXY_ASYNC_SHARED_CTA();
        __syncthreads();

        if (wid == 0) {
            if (elect_one_pred()) {
                uint32_t ab = sb + 1024 + (kt & 1) * 65536;
                uint64_t dAh = MAKE_SMEM_DESC(ab);
                uint64_t dAl = MAKE_SMEM_DESC(ab + 16384);
                uint64_t dBh = MAKE_SMEM_DESC(ab + 32768);
                uint64_t dBl = MAKE_SMEM_DESC(ab + 49152);
                #pragma unroll
                for (int k = 0; k < 4; k++)
                    tc_mma_f16_ss(tmem, dAh + k * 2, dBh + k * 2, TC_IDESC,
                                  (kt == 0 && k == 0) ? 0u : 1u);
                #pragma unroll
                for (int k = 0; k < 4; k++)
                    tc_mma_f16_ss(tmem, dAh + k * 2, dBl + k * 2, TC_IDESC, 1u);
                #pragma unroll
                for (int k = 0; k < 4; k++)
                    tc_mma_f16_ss(tmem, dAl + k * 2, dBh + k * 2, TC_IDESC, 1u);
                TCGEN05_COMMIT(sb + 16 + 8 * (kt & 1));
            }
        }
    }
    #undef TCB_ISSUE

    if (nk >= 2)
        MBARRIER_WAIT_PARITY(sb + 16 + 8 * ((nk - 2) & 1), ((nk - 2) >> 1) & 1);
    MBARRIER_WAIT_PARITY(sb + 16 + 8 * ((nk - 1) & 1), ((nk - 1) >> 1) & 1);
    TCGEN05_FENCE_AFTER();

    if (wid < 4) {
        int m = m0 + wid * 32 + lid;
        bool mok = (m < mvalid);
        #pragma unroll
        for (int cb = 0; cb < 128; cb += 32) {
            uint32_t d[32];
            TCGEN05_LD_32X32B_X32(d, tmem + cb);
            TCGEN05_WAIT_LD();
            if (mok) {
                #pragma unroll
                for (int j = 0; j < 32; j++) {
                    int n = n0 + cb + j;
                    if (n < nvalid) {
                        float v = alpha * __uint_as_float(d[j]);
                        if (OUTSPLIT) {
                            bf16 h, l; split_bf16(v, h, l);
                            Ch[(long long)m * ldcs + n] = h;
                            Cl[(long long)m * ldcs + n] = l;
                        } else {
                            C[(long long)m * ldc + n] = v;
                        }
                    }
                }
            }
        }
        TCGEN05_FENCE_BEFORE();
    }
    __syncthreads();
    if (tid == 0) { MBARRIER_INVAL(sb + 16); MBARRIER_INVAL(sb + 24); }
    __syncthreads();
    if (wid == 0) TCGEN05_DEALLOC(tmem, 128);
#else
    const int tid = threadIdx.x;
    const int m0 = blockIdx.y * 128;
    const int n0 = blockIdx.x * 128;
    for (int e = tid; e < 128 * 128; e += TC_THREADS) {
        int mi = e >> 7, ni = e & 127;
        int m = m0 + mi, n = n0 + ni;
        if (m >= mvalid || n >= nvalid) continue;
        float s = 0.f;
        for (int k = 0; k < K; k++)
            s += (__bfloat162float(Ah[(long long)m * lda + k]) + __bfloat162float(Al[(long long)m * lda + k])) *
                 (__bfloat162float(Bh[(long long)n * ldb + k]) + __bfloat162float(Bl[(long long)n * ldb + k]));
        s *= alpha;
        if (OUTSPLIT) {
            bf16 h, l; split_bf16(s, h, l);
            Ch[(long long)m * ldcs + n] = h;
            Cl[(long long)m * ldcs + n] = l;
        } else {
            C[(long long)m * ldc + n] = s;
        }
    }
#endif
}

// ================= 64x64 GEMM (Kahan-capable, batched, opt split-out) =================
#define BM 64
#define BN 64
#define BK 16

template<bool TRANSB, int ACT, bool KAHAN, bool OUTSPLIT>
__global__ __launch_bounds__(256)
void gemm_kernel(const float* __restrict__ A, int lda, long long sA1, long long sA2,
                 const float* __restrict__ Bm, int ldb, long long sB1, long long sB2,
                 float* __restrict__ C, int ldc, long long sC1, long long sC2,
                 bf16* __restrict__ Ch, bf16* __restrict__ Cl,
                 const float* __restrict__ bias,
                 const float* __restrict__ Res, int ldr, long long sR1, long long sR2,
                 int K, int bdiv, float alpha)
{
    __shared__ float As[BK][BM + 4];
    __shared__ float Bs[BK][BN + 4];

    int bz = blockIdx.z;
    int ob = bz / bdiv;
    int ib = bz - ob * bdiv;
    A  += ob * sA1 + ib * sA2;
    Bm += ob * sB1 + ib * sB2;
    C  += ob * sC1 + ib * sC2;
    if (OUTSPLIT) { Ch += ob * sC1 + ib * sC2; Cl += ob * sC1 + ib * sC2; }
    if (Res) Res += ob * sR1 + ib * sR2;

    int bm = blockIdx.y * BM;
    int bn = blockIdx.x * BN;
    int tid = threadIdx.x;
    int tx = tid & 15, ty = tid >> 4;

    float acc[4][4] = {};
    float cmp[4][4] = {};

    for (int k0 = 0; k0 < K; k0 += BK) {
        #pragma unroll
        for (int i = 0; i < 4; i++) {
            int idx = tid + i * 256;
            int m  = idx >> 4;
            int kk = idx & 15;
            As[kk][m] = A[(long long)(bm + m) * lda + k0 + kk];
        }
        if (TRANSB) {
            #pragma unroll
            for (int i = 0; i < 4; i++) {
                int idx = tid + i * 256;
                int n  = idx >> 4;
                int kk = idx & 15;
                Bs[kk][n] = Bm[(long long)(bn + n) * ldb + k0 + kk];
            }
        } else {
            #pragma unroll
            for (int i = 0; i < 4; i++) {
                int idx = tid + i * 256;
                int kk = idx >> 6;
                int n  = idx & 63;
                Bs[kk][n] = Bm[(long long)(k0 + kk) * ldb + bn + n];
            }
        }
        __syncthreads();

        #pragma unroll
        for (int kk = 0; kk < BK; kk++) {
            float4 av = *(const float4*)&As[kk][ty * 4];
            float4 bv = *(const float4*)&Bs[kk][tx * 4];
            float a4[4] = {av.x, av.y, av.z, av.w};
            float b4[4] = {bv.x, bv.y, bv.z, bv.w};
            #pragma unroll
            for (int i = 0; i < 4; i++)
                #pragma unroll
                for (int j = 0; j < 4; j++) {
                    if (KAHAN) {
                        float y = __fmaf_rn(a4[i], b4[j], -cmp[i][j]);
                        float t = acc[i][j] + y;
                        cmp[i][j] = (t - acc[i][j]) - y;
                        acc[i][j] = t;
                    } else {
                        acc[i][j] = __fmaf_rn(a4[i], b4[j], acc[i][j]);
                    }
                }
        }
        __syncthreads();
    }

    #pragma unroll
    for (int i = 0; i < 4; i++) {
        int m = bm + ty * 4 + i;
        #pragma unroll
        for (int j = 0; j < 4; j++) {
            int n = bn + tx * 4 + j;
            float v = acc[i][j] * alpha;
            if (bias) v += bias[n];
            if (Res)  v += Res[(long long)m * ldr + n];
            if (ACT == 1) v = 0.5f * v * (1.0f + erff(v * 0.70710678118654752f));
            C[(long long)m * ldc + n] = v;
            if (OUTSPLIT) {
                bf16 h, l;
                split_bf16(v, h, l);
                Ch[(long long)m * ldc + n] = h;
                Cl[(long long)m * ldc + n] = l;
            }
        }
    }
}

// ---------------- transpose + split (weights) ----------------
__global__ __launch_bounds__(256)
void tsplit_kernel(const float* __restrict__ in, int K, int N,
                   bf16* __restrict__ oh, bf16* __restrict__ ol)
{
    __shared__ float tile[32][33];
    int nb = blockIdx.x * 32, kb = blockIdx.y * 32;
    int tx = threadIdx.x & 31, ty = threadIdx.x >> 5;
    #pragma unroll
    for (int i = 0; i < 32; i += 8)
        tile[ty + i][tx] = in[(long long)(kb + ty + i) * N + nb + tx];
    __syncthreads();
    #pragma unroll
    for (int i = 0; i < 32; i += 8) {
        int n = nb + ty + i, k = kb + tx;
        float v = tile[tx][ty + i];
        bf16 h, l;
        split_bf16(v, h, l);
        oh[(long long)n * K + k] = h;
        ol[(long long)n * K + k] = l;
    }
}

// ---------------- V transpose + split: QKV v-slab -> Vt[B,H,64,320] ----------------
__global__ __launch_bounds__(256)
void vtsplit_kernel(const float* __restrict__ QKV,
                    bf16* __restrict__ vth, bf16* __restrict__ vtl)
{
    __shared__ float tile[32][65];
    int z = blockIdx.x;                 // b*H + h
    int b = z / H_, h = z % H_;
    int t0 = blockIdx.y * 32;           // token tile
    int tid = threadIdx.x;
    // read: 32 tokens x 64 dims (v slab cols 1536 + h*64 ..)
    const float* src = QKV + ((long long)b * NTOK + t0) * (3 * DIM_) + 2 * DIM_ + h * DH;
    #pragma unroll
    for (int i = 0; i < 8; i++) {
        int idx = tid + i * 256;        // 0..2047
        int t = idx >> 6;               // 0..31 token
        int d = idx & 63;               // dim
        tile[t][d] = src[(long long)t * (3 * DIM_) + d];
    }
    __syncthreads();
    // write: 64 dims x 32 tokens
    bf16* dsth = vth + ((long long)z * DH) * NTOK + t0;
    bf16* dstl = vtl + ((long long)z * DH) * NTOK + t0;
    #pragma unroll
    for (int i = 0; i < 8; i++) {
        int idx = tid + i * 256;
        int d = idx >> 5;               // 0..63
        int t = idx & 31;               // token
        float v = tile[t][d];
        bf16 hh, ll;
        split_bf16(v, hh, ll);
        dsth[(long long)d * NTOK + t] = hh;
        dstl[(long long)d * NTOK + t] = ll;
    }
}

// ---------------- LayerNorm, fp64 stats, fp32 + split out ----------------
__global__ __launch_bounds__(256)
void ln_kernel(const float* __restrict__ x, const float* __restrict__ g,
               const float* __restrict__ b, float* __restrict__ y,
               bf16* __restrict__ yh, bf16* __restrict__ yl)
{
    long long row = blockIdx.x;
    const float* xr = x + row * DIM_;
    float* yr = y + row * DIM_;
    bf16* yhr = yh + row * DIM_;
    bf16* ylr = yl + row * DIM_;
    int t = threadIdx.x;
    float v0 = xr[t], v1 = xr[t + 256], v2 = xr[t + 512];
    double s = (double)v0 + (double)v1 + (double)v2;
    double q = (double)v0 * v0 + (double)v1 * v1 + (double)v2 * v2;
    __shared__ double sh[16];
    __shared__ float  par[2];
    #pragma unroll
    for (int o = 16; o > 0; o >>= 1) {
        s += __shfl_down_sync(~0u, s, o);
        q += __shfl_down_sync(~0u, q, o);
    }
    int wid = t >> 5, lane = t & 31;
    if (lane == 0) { sh[wid] = s; sh[wid + 8] = q; }
    __syncthreads();
    if (t == 0) {
        double ss = 0., qq = 0.;
        #pragma unroll
        for (int i = 0; i < 8; i++) { ss += sh[i]; qq += sh[i + 8]; }
        double mu = ss / DIM_;
        double var = qq / DIM_ - mu * mu;
        par[0] = (float)mu;
        par[1] = (float)(1.0 / sqrt(var + 1e-5));
    }
    __syncthreads();
    float mu = par[0], r = par[1];
    #pragma unroll
    for (int i = 0; i < 3; i++) {
        int c = t + i * 256;
        float vv = (i == 0 ? v0 : (i == 1 ? v1 : v2));
        float o = (vv - mu) * r * g[c] + b[c];
        yr[c] = o;
        bf16 h, l;
        split_bf16(o, h, l);
        yhr[c] = h;
        ylr[c] = l;
    }
}

// ---------------- row softmax over 320 (fp32 out + split P out) ----------------
__global__ __launch_bounds__(128)
void softmax_kernel(float* __restrict__ attn,
                    bf16* __restrict__ ph, bf16* __restrict__ pl)
{
    long long row = blockIdx.x;
    int t_q = (int)(row % NTOK);
    float* p = attn + row * NTOK;
    bf16* phr = ph + row * NTOK;
    bf16* plr = pl + row * NTOK;
    int t = threadIdx.x;
    float v[3];
    float m = -1e30f;
    #pragma unroll
    for (int i = 0; i < 3; i++) {
        int c = t + i * 128;
        v[i] = (c < NTOK) ? p[c] : -1e30f;
        m = fmaxf(m, v[i]);
    }
    __shared__ float shm[4];
    __shared__ double shd[4];
    #pragma unroll
    for (int o = 16; o > 0; o >>= 1) m = fmaxf(m, __shfl_xor_sync(~0u, m, o));
    if ((t & 31) == 0) shm[t >> 5] = m;
    __syncthreads();
    m = fmaxf(fmaxf(shm[0], shm[1]), fmaxf(shm[2], shm[3]));
    __syncthreads();

    if (t_q < LT_) {
        double e[3];
        double s = 0.0;
        #pragma unroll
        for (int i = 0; i < 3; i++) {
            int c = t + i * 128;
            if (c < NTOK) { e[i] = exp((double)v[i] - (double)m); s += e[i]; }
            else e[i] = 0.0;
        }
        #pragma unroll
        for (int o = 16; o > 0; o >>= 1) s += __shfl_xor_sync(~0u, s, o);
        if ((t & 31) == 0) shd[t >> 5] = s;
        __syncthreads();
        s = shd[0] + shd[1] + shd[2] + shd[3];
        double inv = 1.0 / s;
        #pragma unroll
        for (int i = 0; i < 3; i++) {
            int c = t + i * 128;
            if (c < NTOK) {
                float pv = (float)(e[i] * inv);
                p[c] = pv;
                bf16 h, l;
                split_bf16(pv, h, l);
                phr[c] = h;
                plr[c] = l;
            }
        }
    } else {
        float e[3];
        float s = 0.0f;
        #pragma unroll
        for (int i = 0; i < 3; i++) {
            int c = t + i * 128;
            if (c < NTOK) { e[i] = __expf(v[i] - m); s += e[i]; }
            else e[i] = 0.0f;
        }
        #pragma unroll
        for (int o = 16; o > 0; o >>= 1) s += __shfl_xor_sync(~0u, s, o);
        if ((t & 31) == 0) shm[t >> 5] = s;
        __syncthreads();
        s = shm[0] + shm[1] + shm[2] + shm[3];
        float inv = 1.0f / s;
        #pragma unroll
        for (int i = 0; i < 3; i++) {
            int c = t + i * 128;
            if (c < NTOK) {
                float pv = e[i] * inv;
                p[c] = pv;
                bf16 h, l;
                split_bf16(pv, h, l);
                phr[c] = h;
                plr[c] = l;
            }
        }
    }
}

// ---------------- CE scores (fp64) ----------------
__global__ __launch_bounds__(256)
void ce_score_kernel(const float* __restrict__ attn, const unsigned char* __restrict__ maskp,
                     float* __restrict__ S)
{
    int b = blockIdx.x;
    int j = threadIdx.x;
    __shared__ float mf[LT_];
    __shared__ double cntsh;
    __shared__ int mode;
    if (j == 0) {
        const unsigned int* w = (const unsigned int*)maskp;
        bool all_int = true, all_flt = true;
        for (int i = 0; i < 512; i++) {
            unsigned int v = w[i];
            if (v != 0u && v != 1u) all_int = false;
            if (v != 0u && v != 0x3F800000u) all_flt = false;
        }
        mode = all_int ? 0 : (all_flt ? 1 : 2);
    }
    __syncthreads();
    if (j < LT_) {
        int mv;
        if (mode == 0)      mv = ((const int*)maskp)[b * LT_ + j] != 0;
        else if (mode == 1) mv = ((const float*)maskp)[b * LT_ + j] != 0.0f;
        else                mv = maskp[b * LT_ + j] != 0;
        mf[j] = mv ? 1.0f : 0.0f;
    }
    __syncthreads();
    if (j == 0) {
        double c = 0.;
        for (int t = 0; t < LT_; t++) c += (double)mf[t];
        cntsh = c;
    }
    __syncthreads();
    double cnt = cntsh;
    double stot = 0.0;
    const float* base = attn + (long long)b * H_ * NTOK * NTOK + LT_ + j;
    for (int h = 0; h < H_; h++) {
        const float* ph = base + (long long)h * NTOK * NTOK;
        double sh = 0.0;
        #pragma unroll 4
        for (int t = 0; t < LT_; t++)
            sh += (double)ph[(long long)t * NTOK] * (double)mf[t];
        stot += sh / cnt;
    }
    S[b * LS_ + j] = (float)(stot / H_);
}

// ---------------- bitonic sort ----------------
__global__ __launch_bounds__(256)
void sort_kernel(const float* __restrict__ S, int* __restrict__ order)
{
    int b = blockIdx.x, t = threadIdx.x;
    __shared__ float val[256];
    __shared__ int   idx[256];
    val[t] = S[b * LS_ + t];
    idx[t] = t;
    __syncthreads();
    for (int k = 2; k <= 256; k <<= 1) {
        for (int j = k >> 1; j > 0; j >>= 1) {
            int p = t ^ j;
            if (p > t) {
                bool desc = ((t & k) == 0);
                float va = val[t], vb = val[p];
                int ia = idx[t], ib = idx[p];
                bool aFirst = (va > vb) || (va == vb && ia < ib);
                if (aFirst != desc) {
                    val[t] = vb; val[p] = va;
                    idx[t] = ib; idx[p] = ia;
                }
            }
            __syncthreads();
        }
    }
    order[b * LS_ + t] = idx[t];
}

// ---------------- gather ----------------
__global__ __launch_bounds__(256)
void gather_kernel(const float* __restrict__ X1, const int* __restrict__ ord,
                   float* __restrict__ X2)
{
    int b = blockIdx.x, t = blockIdx.y;
    int src = (t < LT_) ? t : (LT_ + ord[b * LS_ + (t - LT_)]);
    const float* s = X1 + ((long long)b * NTOK + src) * DIM_;
    float* d = X2 + ((long long)b * N2 + t) * DIM_;
    int i = threadIdx.x;
    d[i] = s[i];
    d[i + 256] = s[i + 256];
    d[i + 512] = s[i + 512];
}

// ---------------- index outputs ----------------
__global__ __launch_bounds__(256)
void indices_kernel(const int* __restrict__ ord, const int* __restrict__ gsi,
                    float* __restrict__ outK, float* __restrict__ outR)
{
    int b = blockIdx.x, t = threadIdx.x;
    if (t < LK_) outK[b * LK_ + t] = (float)gsi[b * LS_ + ord[b * LS_ + t]];
    if (t < LR_) outR[b * LR_ + t] = (float)gsi[b * LS_ + ord[b * LS_ + LK_ + t]];
}

__global__ __launch_bounds__(256)
void git_kernel(const int* __restrict__ git, float* __restrict__ out)
{
    int i = blockIdx.x * 256 + threadIdx.x;
    if (i < B_ * LT_) out[i] = (float)git[i];
}

// ---------------- streams/events (created pre-main) ----------------
struct StreamPool {
    cudaStream_t f0, m1, f1;
    cudaEvent_t evFork, evLN0, evF0, evLN1, evF1, evEnd1;
    StreamPool() {
        cudaStreamCreateWithFlags(&f0, cudaStreamNonBlocking);
        cudaStreamCreateWithFlags(&m1, cudaStreamNonBlocking);
        cudaStreamCreateWithFlags(&f1, cudaStreamNonBlocking);
        cudaEventCreateWithFlags(&evFork, cudaEventDisableTiming);
        cudaEventCreateWithFlags(&evLN0, cudaEventDisableTiming);
        cudaEventCreateWithFlags(&evF0,  cudaEventDisableTiming);
        cudaEventCreateWithFlags(&evLN1, cudaEventDisableTiming);
        cudaEventCreateWithFlags(&evF1,  cudaEventDisableTiming);
        cudaEventCreateWithFlags(&evEnd1, cudaEventDisableTiming);
    }
};
static StreamPool g_sp;

// ---------------- per-branch buffers ----------------
struct BranchBufs {
    float *XLN, *QKV, *Q64, *ATTN, *X1, *S, *X2, *XLN2;
    int* ORD;
    bf16 *XLNh, *XLNl, *QKVh, *QKVl, *Ph, *Pl, *Vth, *Vtl, *Oh, *Ol,
         *XLN2h, *XLN2l, *H1h, *H1l;
};
struct Weights {
    bf16 *WqkvTh, *WqkvTl, *WprojTh, *WprojTl, *W1Th, *W1Tl, *W2Th, *W2Tl;
};

static void run_branch(cudaStream_t m, cudaStream_t f,
                       cudaEvent_t evLN, cudaEvent_t evF,
                       const float* x, const int* gsi, const unsigned char* mask,
                       const float* g1, const float* b1,
                       const float* Wqkv, const float* bqkv,
                       const float* bproj,
                       const float* g2, const float* b2,
                       const float* bm1, const float* bm2,
                       float* outX, float* outK, float* outR,
                       const BranchBufs& bu, const Weights& w)
{
    // LN1 (fp32 + split) on m, then fork f
    ln_kernel<<<B_ * NTOK, 256, 0, m>>>(x, g1, b1, bu.XLN, bu.XLNh, bu.XLNl);
    cudaEventRecord(evLN, m);
    cudaStreamWaitEvent(f, evLN, 0);

    // ---- tensor lane (m): tc q (split-only out), tc v (fp32 out), vtsplit ----
    tc_gemm2<0, true><<<dim3(DIM_ / 128, B_ * NTOK / 128), TC_THREADS, TC_SMEM_TOTAL, m>>>(
        bu.XLNh, bu.XLNl, DIM_, w.WqkvTh, w.WqkvTl, DIM_,
        nullptr, 3 * DIM_, bu.QKVh, bu.QKVl, bqkv, nullptr, 0, DIM_);
    tc_gemm2<0, false><<<dim3(DIM_ / 128, B_ * NTOK / 128), TC_THREADS, TC_SMEM_TOTAL, m>>>(
        bu.XLNh, bu.XLNl, DIM_,
        w.WqkvTh + 2 * DIM_ * DIM_, w.WqkvTl + 2 * DIM_ * DIM_, DIM_,
        bu.QKV + 2 * DIM_, 3 * DIM_, nullptr, nullptr, bqkv + 2 * DIM_, nullptr, 0, DIM_);
    vtsplit_kernel<<<dim3(B_ * H_, NTOK / 32), 256, 0, m>>>(bu.QKV, bu.Vth, bu.Vtl);

    // ---- fma lane (f): Kahan k (fp32 + split out), Kahan q64, Kahan logits rows<64 ----
    gemm_kernel<false, 0, true, true><<<dim3(DIM_ / BN, B_ * NTOK / BM, 1), 256, 0, f>>>(
        bu.XLN, DIM_, 0, 0,
        Wqkv + DIM_, 3 * DIM_, 0, 0,
        bu.QKV + DIM_, 3 * DIM_, 0, 0,
        bu.QKVh + DIM_, bu.QKVl + DIM_,
        bqkv + DIM_, nullptr, 0, 0, 0,
        DIM_, 1, 1.0f);
    gemm_kernel<false, 0, true, false><<<dim3(DIM_ / BN, 1, B_), 256, 0, f>>>(
        bu.XLN, DIM_, 0, (long long)NTOK * DIM_,
        Wqkv, 3 * DIM_, 0, 0,
        bu.Q64, DIM_, 0, (long long)LT_ * DIM_,
        nullptr, nullptr,
        bqkv, nullptr, 0, 0, 0,
        DIM_, B_, 1.0f);
    gemm_kernel<true, 0, true, false><<<dim3(NTOK / BN, 1, B_ * H_), 256, 0, f>>>(
        bu.Q64,        DIM_,     (long long)LT_ * DIM_,       DH,
        bu.QKV + DIM_, 3 * DIM_, (long long)NTOK * 3 * DIM_,  DH,
        bu.ATTN, NTOK, (long long)H_ * NTOK * NTOK, (long long)NTOK * NTOK,
        nullptr, nullptr,
        nullptr, nullptr, 0, 0, 0,
        DH, H_, 0.125f);
    cudaEventRecord(evF, f);
    cudaStreamWaitEvent(m, evF, 0);

    // ---- m: logits rows 64..319 on tensor cores (batched, split inputs) ----
    tc_bgemm<false><<<dim3(3, 2, B_ * H_), TC_THREADS, TC_SMEM_TOTAL, m>>>(
        bu.QKVh + (long long)LT_ * 3 * DIM_, bu.QKVl + (long long)LT_ * 3 * DIM_,
        3 * DIM_, (long long)NTOK * 3 * DIM_, DH,
        bu.QKVh + DIM_, bu.QKVl + DIM_,
        3 * DIM_, (long long)NTOK * 3 * DIM_, DH,
        bu.ATTN + (long long)LT_ * NTOK, NTOK,
        (long long)H_ * NTOK * NTOK, (long long)NTOK * NTOK,
        nullptr, nullptr, 0, 0, 0,
        DH, H_, 0.125f, LS_ /*mvalid=256*/, NTOK /*nvalid=320*/);

    softmax_kernel<<<B_ * H_ * NTOK, 128, 0, m>>>(bu.ATTN, bu.Ph, bu.Pl);

    // ---- m: O = P @ V on tensor cores (batched, split out for proj) ----
    tc_bgemm<true><<<dim3(1, 3, B_ * H_), TC_THREADS, TC_SMEM_TOTAL, m>>>(
        bu.Ph, bu.Pl, NTOK, (long long)H_ * NTOK * NTOK, (long long)NTOK * NTOK,
        bu.Vth, bu.Vtl, NTOK, (long long)H_ * DH * NTOK, (long long)DH * NTOK,
        nullptr, 0, 0, 0,
        bu.Oh, bu.Ol, DIM_, (long long)NTOK * DIM_, DH,
        NTOK /*K=320*/, H_, 1.0f, NTOK /*mvalid=320*/, DH /*nvalid=64*/);

    // X1 = x + O @ Wproj + bproj (tc)
    tc_gemm2<0, false><<<dim3(DIM_ / 128, B_ * NTOK / 128), TC_THREADS, TC_SMEM_TOTAL, m>>>(
        bu.Oh, bu.Ol, DIM_, w.WprojTh, w.WprojTl, DIM_,
        bu.X1, DIM_, nullptr, nullptr, bproj, x, DIM_, DIM_);

    // CE
    ce_score_kernel<<<B_, 256, 0, m>>>(bu.ATTN, mask, bu.S);
    sort_kernel<<<B_, 256, 0, m>>>(bu.S, bu.ORD);
    gather_kernel<<<dim3(B_, N2), 256, 0, m>>>(bu.X1, bu.ORD, bu.X2);
    indices_kernel<<<B_, 256, 0, m>>>(bu.ORD, gsi, outK, outR);

    // LN2
    ln_kernel<<<B_ * N2, 256, 0, m>>>(bu.X2, g2, b2, bu.XLN2, bu.XLN2h, bu.XLN2l);

    // MLP1 (tc, split-only out)
    tc_gemm2<1, true><<<dim3(4 * DIM_ / 128, B_ * N2 / 128), TC_THREADS, TC_SMEM_TOTAL, m>>>(
        bu.XLN2h, bu.XLN2l, DIM_, w.W1Th, w.W1Tl, DIM_,
        nullptr, 4 * DIM_, bu.H1h, bu.H1l, bm1, nullptr, 0, DIM_);

    // MLP2 (tc)
    tc_gemm2<0, false><<<dim3(DIM_ / 128, B_ * N2 / 128), TC_THREADS, TC_SMEM_TOTAL, m>>>(
        bu.H1h, bu.H1l, 4 * DIM_, w.W2Th, w.W2Tl, 4 * DIM_,
        outX, DIM_, nullptr, nullptr, bm2, bu.X2, DIM_, 4 * DIM_);
}

static void get_branch_bufs(int br, BranchBufs& bu)
{
    char* p;
    cudaGetSymbolAddress((void**)&p, g_XLN);  bu.XLN  = (float*)p + (size_t)br * B_ * NTOK * DIM_;
    cudaGetSymbolAddress((void**)&p, g_QKV);  bu.QKV  = (float*)p + (size_t)br * B_ * NTOK * 3 * DIM_;
    cudaGetSymbolAddress((void**)&p, g_Q64);  bu.Q64  = (float*)p + (size_t)br * B_ * LT_ * DIM_;
    cudaGetSymbolAddress((void**)&p, g_ATTN); bu.ATTN = (float*)p + (size_t)br * B_ * H_ * NTOK * NTOK;
    cudaGetSymbolAddress((void**)&p, g_X1);   bu.X1   = (float*)p + (size_t)br * B_ * NTOK * DIM_;
    cudaGetSymbolAddress((void**)&p, g_S);    bu.S    = (float*)p + (size_t)br * B_ * LS_;
    cudaGetSymbolAddress((void**)&p, g_ORD);  bu.ORD  = (int*)p   + (size_t)br * B_ * LS_;
    cudaGetSymbolAddress((void**)&p, g_X2);   bu.X2   = (float*)p + (size_t)br * B_ * N2 * DIM_;
    cudaGetSymbolAddress((void**)&p, g_XLN2); bu.XLN2 = (float*)p + (size_t)br * B_ * N2 * DIM_;
    cudaGetSymbolAddress((void**)&p, g_XLNh); bu.XLNh = (bf16*)p + (size_t)br * B_ * NTOK * DIM_;
    cudaGetSymbolAddress((void**)&p, g_XLNl); bu.XLNl = (bf16*)p + (size_t)br * B_ * NTOK * DIM_;
    cudaGetSymbolAddress((void**)&p, g_QKVh); bu.QKVh = (bf16*)p + (size_t)br * QKVS_ROWS * 3 * DIM_;
    cudaGetSymbolAddress((void**)&p, g_QKVl); bu.QKVl = (bf16*)p + (size_t)br * QKVS_ROWS * 3 * DIM_;
    cudaGetSymbolAddress((void**)&p, g_Ph);   bu.Ph   = (bf16*)p + (size_t)br * PSZ;
    cudaGetSymbolAddress((void**)&p, g_Pl);   bu.Pl   = (bf16*)p + (size_t)br * PSZ;
    cudaGetSymbolAddress((void**)&p, g_Vth);  bu.Vth  = (bf16*)p + (size_t)br * VTSZ;
    cudaGetSymbolAddress((void**)&p, g_Vtl);  bu.Vtl  = (bf16*)p + (size_t)br * VTSZ;
    cudaGetSymbolAddress((void**)&p, g_Oh);   bu.Oh   = (bf16*)p + (size_t)br * B_ * NTOK * DIM_;
    cudaGetSymbolAddress((void**)&p, g_Ol);   bu.Ol   = (bf16*)p + (size_t)br * B_ * NTOK * DIM_;
    cudaGetSymbolAddress((void**)&p, g_XLN2h); bu.XLN2h = (bf16*)p + (size_t)br * B_ * N2 * DIM_;
    cudaGetSymbolAddress((void**)&p, g_XLN2l); bu.XLN2l = (bf16*)p + (size_t)br * B_ * N2 * DIM_;
    cudaGetSymbolAddress((void**)&p, g_H1h);  bu.H1h  = (bf16*)p + (size_t)br * B_ * N2 * 4 * DIM_;
    cudaGetSymbolAddress((void**)&p, g_H1l);  bu.H1l  = (bf16*)p + (size_t)br * B_ * N2 * 4 * DIM_;
}

extern "C" void kernel_launch(void* const* d_in, const int* in_sizes, int n_in,
                              void* d_out, int out_size)
{
    const float* x_rgb  = (const float*)d_in[0];
    const float* x_dte  = (const float*)d_in[1];
    const int*   git    = (const int*)d_in[2];
    const int*   gsi_rgb = (const int*)d_in[3];
    const int*   gsi_dte = (const int*)d_in[4];
    const unsigned char* mask = (const unsigned char*)d_in[5];
    const float* g1    = (const float*)d_in[6];
    const float* b1    = (const float*)d_in[7];
    const float* Wqkv  = (const float*)d_in[8];
    const float* bqkv  = (const float*)d_in[9];
    const float* Wproj = (const float*)d_in[10];
    const float* bproj = (const float*)d_in[11];
    const float* g2    = (const float*)d_in[12];
    const float* b2    = (const float*)d_in[13];
    const float* W1    = (const float*)d_in[14];
    const float* bm1   = (const float*)d_in[15];
    const float* W2    = (const float*)d_in[16];
    const float* bm2   = (const float*)d_in[17];

    float* out = (float*)d_out;

    cudaFuncSetAttribute(tc_gemm2<0, false>, cudaFuncAttributeMaxDynamicSharedMemorySize, TC_SMEM_TOTAL);
    cudaFuncSetAttribute(tc_gemm2<0, true>,  cudaFuncAttributeMaxDynamicSharedMemorySize, TC_SMEM_TOTAL);
    cudaFuncSetAttribute(tc_gemm2<1, true>,  cudaFuncAttributeMaxDynamicSharedMemorySize, TC_SMEM_TOTAL);
    cudaFuncSetAttribute(tc_bgemm<false>, cudaFuncAttributeMaxDynamicSharedMemorySize, TC_SMEM_TOTAL);
    cudaFuncSetAttribute(tc_bgemm<true>,  cudaFuncAttributeMaxDynamicSharedMemorySize, TC_SMEM_TOTAL);

    Weights w;
    {
        char* p;
        cudaGetSymbolAddress((void**)&p, g_WqkvTh);  w.WqkvTh  = (bf16*)p;
        cudaGetSymbolAddress((void**)&p, g_WqkvTl);  w.WqkvTl  = (bf16*)p;
        cudaGetSymbolAddress((void**)&p, g_WprojTh); w.WprojTh = (bf16*)p;
        cudaGetSymbolAddress((void**)&p, g_WprojTl); w.WprojTl = (bf16*)p;
        cudaGetSymbolAddress((void**)&p, g_W1Th);    w.W1Th    = (bf16*)p;
        cudaGetSymbolAddress((void**)&p, g_W1Tl);    w.W1Tl    = (bf16*)p;
        cudaGetSymbolAddress((void**)&p, g_W2Th);    w.W2Th    = (bf16*)p;
        cudaGetSymbolAddress((void**)&p, g_W2Tl);    w.W2Tl    = (bf16*)p;
    }
    BranchBufs bu0, bu1;
    get_branch_bufs(0, bu0);
    get_branch_bufs(1, bu1);

    const long long XSZ     = (long long)B_ * N2 * DIM_;
    const long long GIT_OFF = 2 * XSZ;
    const long long K0_OFF  = GIT_OFF + (long long)B_ * LT_;
    const long long K1_OFF  = K0_OFF + (long long)B_ * LK_;
    const long long R0_OFF  = K1_OFF + (long long)B_ * LK_;
    const long long R1_OFF  = R0_OFF + (long long)B_ * LR_;

    // shared prologue on the origin stream
    git_kernel<<<(B_ * LT_ + 255) / 256, 256>>>(git, out + GIT_OFF);
    tsplit_kernel<<<dim3(3 * DIM_ / 32, DIM_ / 32), 256>>>(Wqkv, DIM_, 3 * DIM_, w.WqkvTh, w.WqkvTl);
    tsplit_kernel<<<dim3(DIM_ / 32, DIM_ / 32), 256>>>(Wproj, DIM_, DIM_, w.WprojTh, w.WprojTl);
    tsplit_kernel<<<dim3(4 * DIM_ / 32, DIM_ / 32), 256>>>(W1, DIM_, 4 * DIM_, w.W1Th, w.W1Tl);
    tsplit_kernel<<<dim3(DIM_ / 32, 4 * DIM_ / 32), 256>>>(W2, 4 * DIM_, DIM_, w.W2Th, w.W2Tl);

    // fork branch 1 immediately (no skew)
    cudaEventRecord(g_sp.evFork, (cudaStream_t)0);
    cudaStreamWaitEvent(g_sp.m1, g_sp.evFork, 0);

    run_branch((cudaStream_t)0, g_sp.f0, g_sp.evLN0, g_sp.evF0,
               x_rgb, gsi_rgb, mask, g1, b1, Wqkv, bqkv, bproj,
               g2, b2, bm1, bm2,
               out, out + K0_OFF, out + R0_OFF, bu0, w);

    run_branch(g_sp.m1, g_sp.f1, g_sp.evLN1, g_sp.evF1,
               x_dte, gsi_dte, mask, g1, b1, Wqkv, bqkv, bproj,
               g2, b2, bm1, bm2,
               out + XSZ, out + K1_OFF, out + R1_OFF, bu1, w);

    // join
    cudaEventRecord(g_sp.evEnd1, g_sp.m1);
    cudaStreamWaitEvent((cudaStream_t)0, g_sp.evEnd1, 0);
}

// round 11
// speedup vs baseline: 1.1718x; 1.1718x over previous
#include <cuda_runtime.h>
#include <cuda_bf16.h>
#include <math.h>
#include <stdint.h>

// ---------------- problem constants ----------------
#define B_    32
#define LT_   64
#define LS_   256
#define NTOK  320      // LT + LS
#define DIM_  768
#define H_    12
#define DH    64
#define LK_   180
#define LR_   76
#define N2    244      // LT + LK

#if defined(__CUDA_ARCH__) && defined(__CUDA_ARCH_FEAT_SM103_ALL)
#define HAS_TCGEN05 1
#else
#define HAS_TCGEN05 0
#endif

typedef __nv_bfloat16 bf16;

// ---------------- scratch (per-branch duplicated) ----------------
__device__ float g_XLN [2][B_ * NTOK * DIM_];
__device__ float g_QKV [2][B_ * NTOK * 3 * DIM_];
__device__ float g_Q64 [2][B_ * LT_ * DIM_];
__device__ float g_ATTN[2][(size_t)B_ * H_ * NTOK * NTOK];
__device__ float g_O   [2][B_ * NTOK * DIM_];
__device__ float g_X1  [2][B_ * NTOK * DIM_];
__device__ float g_S   [2][B_ * LS_];
__device__ int   g_ORD [2][B_ * LS_];
__device__ float g_X2  [2][B_ * N2 * DIM_];
__device__ float g_XLN2[2][B_ * N2 * DIM_];

__device__ unsigned short g_XLNh [2][B_ * NTOK * DIM_];
__device__ unsigned short g_XLNl [2][B_ * NTOK * DIM_];
__device__ unsigned short g_Oh   [2][B_ * NTOK * DIM_];
__device__ unsigned short g_Ol   [2][B_ * NTOK * DIM_];
__device__ unsigned short g_XLN2h[2][B_ * N2 * DIM_];
__device__ unsigned short g_XLN2l[2][B_ * N2 * DIM_];
__device__ unsigned short g_H1h  [2][B_ * N2 * 4 * DIM_];
__device__ unsigned short g_H1l  [2][B_ * N2 * 4 * DIM_];

// shared weight splits
__device__ unsigned short g_WqkvTh[3 * DIM_ * DIM_];
__device__ unsigned short g_WqkvTl[3 * DIM_ * DIM_];
__device__ unsigned short g_WprojTh[DIM_ * DIM_];
__device__ unsigned short g_WprojTl[DIM_ * DIM_];
__device__ unsigned short g_W1Th [4 * DIM_ * DIM_];
__device__ unsigned short g_W1Tl [4 * DIM_ * DIM_];
__device__ unsigned short g_W2Th [4 * DIM_ * DIM_];
__device__ unsigned short g_W2Tl [4 * DIM_ * DIM_];

__device__ __forceinline__ void split_bf16(float v, bf16& h, bf16& l) {
    h = __float2bfloat16(v);
    l = __float2bfloat16(v - __bfloat162float(h));
}

// =====================================================================
// tcgen05 helpers (sm_103a pass only)
// =====================================================================
#if HAS_TCGEN05
__device__ __forceinline__ uint32_t elect_one_pred() {
    uint32_t pred;
    asm volatile(
        "{\n\t.reg .pred p;\n\telect.sync _|p, 0xFFFFFFFF;\n\tselp.b32 %0, 1, 0, p;\n\t}"
        : "=r"(pred));
    return pred;
}
__device__ __forceinline__ uint32_t smem_to_u32(const void* smem_ptr) {
    uint32_t addr;
    asm("{ .reg .u64 tmp; cvta.to.shared.u64 tmp, %1; cvt.u32.u64 %0, tmp; }"
        : "=r"(addr) : "l"(smem_ptr));
    return addr;
}
__device__ __forceinline__ void cp16(uint32_t s, const void* g) {
    asm volatile("cp.async.cg.shared.global [%0], [%1], 16;" :: "r"(s), "l"(g) : "memory");
}
#define CP_COMMIT() asm volatile("cp.async.commit_group;" ::: "memory")
#define CP_WAIT(n)  asm volatile("cp.async.wait_group %0;" :: "n"(n) : "memory")

#define TCGEN05_ALLOC(a, n) \
    asm volatile("tcgen05.alloc.cta_group::1.sync.aligned.shared::cta.b32 [%0], %1;" \
        :: "r"((uint32_t)(a)), "r"((uint32_t)(n)) : "memory")
#define TCGEN05_DEALLOC(t, n) \
    asm volatile("tcgen05.dealloc.cta_group::1.sync.aligned.b32 %0, %1;" \
        :: "r"(t), "r"((uint32_t)(n)))
#define TCGEN05_RELINQUISH_ALLOC_PERMIT() \
    asm volatile("tcgen05.relinquish_alloc_permit.cta_group::1.sync.aligned;")
#define TCGEN05_COMMIT(m) \
    asm volatile("tcgen05.commit.cta_group::1.mbarrier::arrive::one.shared::cluster.b64 [%0];" \
        :: "r"((uint32_t)(m)) : "memory")
#define TCGEN05_WAIT_LD()  asm volatile("tcgen05.wait::ld.sync.aligned;" ::: "memory")
#define TCGEN05_FENCE_BEFORE() asm volatile("tcgen05.fence::before_thread_sync;" ::: "memory")
#define TCGEN05_FENCE_AFTER()  asm volatile("tcgen05.fence::after_thread_sync;" ::: "memory")
#define FENCE_PROXY_ASYNC_SHARED_CTA() asm volatile("fence.proxy.async.shared::cta;" ::: "memory")
#define MBARRIER_INIT(m, c) \
    asm volatile("mbarrier.init.shared.b64 [%0], %1;" :: "r"((uint32_t)(m)), "r"((uint32_t)(c)) : "memory")
#define MBARRIER_INVAL(m) \
    asm volatile("mbarrier.inval.shared.b64 [%0];" :: "r"((uint32_t)(m)) : "memory")

#define MBARRIER_WAIT_PARITY(mb, pp) do { \
    uint32_t _mbar = (uint32_t)(mb); \
    uint32_t _parity = (uint32_t)(pp); \
    uint32_t _done; \
    asm volatile( \
        "{\n\t.reg .pred p;\n\t" \
        "mbarrier.try_wait.parity.acquire.cta.shared::cta.b64 p, [%1], %2;\n\t" \
        "selp.b32 %0, 1, 0, p;\n\t}" \
        : "=r"(_done) : "r"(_mbar), "r"(_parity) : "memory"); \
    if (!_done) { \
        asm volatile( \
            "{\n\t.reg .pred P1;\n\t" \
            "WAIT_LOOP_%=:\n\t" \
            "mbarrier.try_wait.parity.acquire.cta.shared::cta.b64 P1, [%0], %1, 0x989680;\n\t" \
            "@P1 bra.uni WAIT_DONE_%=;\n\t" \
            "bra.uni WAIT_LOOP_%=;\n\t" \
            "WAIT_DONE_%=:\n\t}" \
            :: "r"(_mbar), "r"(_parity) : "memory"); \
    } \
} while(0)

#define TCGEN05_LD_32X32B_X32(r, tmem_addr) \
    asm volatile( \
        "tcgen05.ld.sync.aligned.32x32b.x32.b32 " \
        "{%0, %1, %2, %3, %4, %5, %6, %7, " \
        " %8, %9, %10, %11, %12, %13, %14, %15, " \
        " %16, %17, %18, %19, %20, %21, %22, %23, " \
        " %24, %25, %26, %27, %28, %29, %30, %31}, [%32];" \
        : "=r"((r)[0]),  "=r"((r)[1]),  "=r"((r)[2]),  "=r"((r)[3]), \
          "=r"((r)[4]),  "=r"((r)[5]),  "=r"((r)[6]),  "=r"((r)[7]), \
          "=r"((r)[8]),  "=r"((r)[9]),  "=r"((r)[10]), "=r"((r)[11]), \
          "=r"((r)[12]), "=r"((r)[13]), "=r"((r)[14]), "=r"((r)[15]), \
          "=r"((r)[16]), "=r"((r)[17]), "=r"((r)[18]), "=r"((r)[19]), \
          "=r"((r)[20]), "=r"((r)[21]), "=r"((r)[22]), "=r"((r)[23]), \
          "=r"((r)[24]), "=r"((r)[25]), "=r"((r)[26]), "=r"((r)[27]), \
          "=r"((r)[28]), "=r"((r)[29]), "=r"((r)[30]), "=r"((r)[31]) \
        : "r"(tmem_addr))

static constexpr uint64_t SMEM_DESC_BASE_SW128 =
    (uint64_t(2)  << 61) | (uint64_t(1) << 46) | (uint64_t(64) << 32) | (uint64_t(1) << 16);
#define MAKE_SMEM_DESC(base_addr) \
    (SMEM_DESC_BASE_SW128 | ((uint64_t)((base_addr) >> 4) & 0x3FFF))

__device__ __forceinline__ void tc_mma_f16_ss(uint32_t d, uint64_t a, uint64_t b,
                                              uint32_t idesc, uint32_t en)
{
    asm volatile(
        "{\n\t.reg .pred p;\n\tsetp.ne.u32 p, %5, 0;\n\t"
        "tcgen05.mma.cta_group::1.kind::f16 [%0], %1, %2, %3, {%4, %4, %4, %4}, p;\n\t}"
        :: "r"(d), "l"(a), "l"(b), "r"(idesc), "r"(0u), "r"(en) : "memory");
}
#endif // HAS_TCGEN05

// =====================================================================
// tc_gemm2 (round-9 proven): cp.async pipelined split-bf16 tc GEMM
// =====================================================================
#define TC_THREADS 256
#define TC_SMEM_TOTAL (1024 + 2 * 4 * 16384)   // 132096 bytes
#define TC_IDESC 0x8200490u

template<int ACT, bool OUTSPLIT>
__global__ __launch_bounds__(TC_THREADS)
void tc_gemm2(const bf16* __restrict__ Ah, const bf16* __restrict__ Al, int lda,
              const bf16* __restrict__ Bh, const bf16* __restrict__ Bl, int ldb,
              float* __restrict__ C, int ldc,
              bf16* __restrict__ Ch, bf16* __restrict__ Cl,
              const float* __restrict__ bias,
              const float* __restrict__ Res, int ldr,
              int K)
{
#if HAS_TCGEN05
    extern __shared__ char smem[];
    const uint32_t sb = smem_to_u32(smem);
    const int tid = threadIdx.x;
    const int wid = tid >> 5;
    const int lid = tid & 31;
    const int m0 = blockIdx.y * 128;
    const int n0 = blockIdx.x * 128;

    if (wid == 0) {
        TCGEN05_ALLOC(sb + 0, 128);
        TCGEN05_RELINQUISH_ALLOC_PERMIT();
    }
    if (tid == 0) { MBARRIER_INIT(sb + 16, 1); MBARRIER_INIT(sb + 24, 1); }
    __syncthreads();
    uint32_t tmem;
    asm volatile("ld.shared.b32 %0, [%1];" : "=r"(tmem) : "r"(sb));

    const int nk = K >> 6;
    const int lr  = tid >> 3;
    const int lcq = (tid & 7) * 8;

    #define TC_ISSUE_CHUNK(ktv)  do {                                              \
        const int _buf = (ktv) & 1;                                                \
        uint32_t _db = sb + 1024 + _buf * 65536;                                   \
        const bf16* _Agh = Ah + (long long)m0 * lda + (ktv) * 64;                  \
        const bf16* _Agl = Al + (long long)m0 * lda + (ktv) * 64;                  \
        const bf16* _Bgh = Bh + (long long)n0 * ldb + (ktv) * 64;                  \
        const bf16* _Bgl = Bl + (long long)n0 * ldb + (ktv) * 64;                  \
        _Pragma("unroll")                                                          \
        for (int _i = 0; _i < 4; _i++) {                                           \
            int _r = lr + _i * 32;                                                 \
            uint32_t _bo = _r * 128 + lcq * 2;                                     \
            uint32_t _so = _bo ^ ((_bo >> 3) & 0x70);                              \
            cp16(_db + _so,          _Agh + (long long)_r * lda + lcq);            \
            cp16(_db + 16384 + _so,  _Agl + (long long)_r * lda + lcq);            \
            cp16(_db + 32768 + _so,  _Bgh + (long long)_r * ldb + lcq);            \
            cp16(_db + 49152 + _so,  _Bgl + (long long)_r * ldb + lcq);            \
        }                                                                          \
        CP_COMMIT();                                                               \
    } while (0)

    TC_ISSUE_CHUNK(0);
    for (int kt = 0; kt < nk; kt++) {
        if (kt + 1 < nk) {
            if (kt >= 1)
                MBARRIER_WAIT_PARITY(sb + 16 + 8 * ((kt - 1) & 1), ((kt - 1) >> 1) & 1);
            TC_ISSUE_CHUNK(kt + 1);
            CP_WAIT(1);
        } else {
            CP_WAIT(0);
        }
        FENCE_PROXY_ASYNC_SHARED_CTA();
        __syncthreads();

        if (wid == 0) {
            if (elect_one_pred()) {
                uint32_t ab = sb + 1024 + (kt & 1) * 65536;
                uint64_t dAh = MAKE_SMEM_DESC(ab);
                uint64_t dAl = MAKE_SMEM_DESC(ab + 16384);
                uint64_t dBh = MAKE_SMEM_DESC(ab + 32768);
                uint64_t dBl = MAKE_SMEM_DESC(ab + 49152);
                #pragma unroll
                for (int k = 0; k < 4; k++)
                    tc_mma_f16_ss(tmem, dAh + k * 2, dBh + k * 2, TC_IDESC,
                                  (kt == 0 && k == 0) ? 0u : 1u);
                #pragma unroll
                for (int k = 0; k < 4; k++)
                    tc_mma_f16_ss(tmem, dAh + k * 2, dBl + k * 2, TC_IDESC, 1u);
                #pragma unroll
                for (int k = 0; k < 4; k++)
                    tc_mma_f16_ss(tmem, dAl + k * 2, dBh + k * 2, TC_IDESC, 1u);
                TCGEN05_COMMIT(sb + 16 + 8 * (kt & 1));
            }
        }
    }
    #undef TC_ISSUE_CHUNK

    if (nk >= 2)
        MBARRIER_WAIT_PARITY(sb + 16 + 8 * ((nk - 2) & 1), ((nk - 2) >> 1) & 1);
    MBARRIER_WAIT_PARITY(sb + 16 + 8 * ((nk - 1) & 1), ((nk - 1) >> 1) & 1);
    TCGEN05_FENCE_AFTER();

    if (wid < 4) {
        int m = m0 + wid * 32 + lid;
        float* Crow = C ? (C + (long long)m * ldc + n0) : (float*)0;
        bf16* Chrow = OUTSPLIT ? (Ch + (long long)m * ldc + n0) : (bf16*)0;
        bf16* Clrow = OUTSPLIT ? (Cl + (long long)m * ldc + n0) : (bf16*)0;
        const float* Rrow = Res ? (Res + (long long)m * ldr + n0) : (const float*)0;
        #pragma unroll
        for (int cb = 0; cb < 128; cb += 32) {
            uint32_t d[32];
            TCGEN05_LD_32X32B_X32(d, tmem + cb);
            TCGEN05_WAIT_LD();
            float vout[32];
            #pragma unroll
            for (int j = 0; j < 32; j++) {
                float v = __uint_as_float(d[j]);
                if (bias) v += bias[n0 + cb + j];
                if (Rrow) v += Rrow[cb + j];
                if (ACT == 1) v = 0.5f * v * (1.0f + erff(v * 0.70710678118654752f));
                vout[j] = v;
            }
            if (Crow) {
                #pragma unroll
                for (int q = 0; q < 32; q += 4)
                    *(float4*)&Crow[cb + q] = *(float4*)&vout[q];
            }
            if (OUTSPLIT) {
                #pragma unroll
                for (int q = 0; q < 32; q += 2) {
                    bf16 h0, l0, h1, l1;
                    split_bf16(vout[q], h0, l0);
                    split_bf16(vout[q + 1], h1, l1);
                    unsigned int hw = (unsigned int)__bfloat16_as_ushort(h0) |
                                      ((unsigned int)__bfloat16_as_ushort(h1) << 16);
                    unsigned int lw = (unsigned int)__bfloat16_as_ushort(l0) |
                                      ((unsigned int)__bfloat16_as_ushort(l1) << 16);
                    *(unsigned int*)&Chrow[cb + q] = hw;
                    *(unsigned int*)&Clrow[cb + q] = lw;
                }
            }
        }
        TCGEN05_FENCE_BEFORE();
    }
    __syncthreads();
    if (tid == 0) { MBARRIER_INVAL(sb + 16); MBARRIER_INVAL(sb + 24); }
    __syncthreads();
    if (wid == 0) TCGEN05_DEALLOC(tmem, 128);
#else
    // fp32 fallback (never runs on GB300)
    const int tid = threadIdx.x;
    const int m0 = blockIdx.y * 128;
    const int n0 = blockIdx.x * 128;
    for (int e = tid; e < 128 * 128; e += TC_THREADS) {
        int mi = e >> 7, ni = e & 127;
        int m = m0 + mi, n = n0 + ni;
        float s = 0.f;
        for (int k = 0; k < K; k++)
            s += (__bfloat162float(Ah[(long long)m * lda + k]) + __bfloat162float(Al[(long long)m * lda + k])) *
                 (__bfloat162float(Bh[(long long)n * ldb + k]) + __bfloat162float(Bl[(long long)n * ldb + k]));
        if (bias) s += bias[n];
        if (Res)  s += Res[(long long)m * ldr + n];
        if (ACT == 1) s = 0.5f * s * (1.0f + erff(s * 0.70710678118654752f));
        if (C) C[(long long)m * ldc + n] = s;
        if (OUTSPLIT) {
            bf16 h, l; split_bf16(s, h, l);
            Ch[(long long)m * ldc + n] = h;
            Cl[(long long)m * ldc + n] = l;
        }
    }
#endif
}

// ================= 64x64 GEMM (Kahan-capable, batched, opt split-out) =================
#define BM 64
#define BN 64
#define BK 16

template<bool TRANSB, int ACT, bool KAHAN, bool OUTSPLIT>
__global__ __launch_bounds__(256)
void gemm_kernel(const float* __restrict__ A, int lda, long long sA1, long long sA2,
                 const float* __restrict__ Bm, int ldb, long long sB1, long long sB2,
                 float* __restrict__ C, int ldc, long long sC1, long long sC2,
                 bf16* __restrict__ Ch, bf16* __restrict__ Cl,
                 const float* __restrict__ bias,
                 const float* __restrict__ Res, int ldr, long long sR1, long long sR2,
                 int K, int bdiv, float alpha)
{
    __shared__ float As[BK][BM + 4];
    __shared__ float Bs[BK][BN + 4];

    int bz = blockIdx.z;
    int ob = bz / bdiv;
    int ib = bz - ob * bdiv;
    A  += ob * sA1 + ib * sA2;
    Bm += ob * sB1 + ib * sB2;
    C  += ob * sC1 + ib * sC2;
    if (OUTSPLIT) { Ch += ob * sC1 + ib * sC2; Cl += ob * sC1 + ib * sC2; }
    if (Res) Res += ob * sR1 + ib * sR2;

    int bm = blockIdx.y * BM;
    int bn = blockIdx.x * BN;
    int tid = threadIdx.x;
    int tx = tid & 15, ty = tid >> 4;

    float acc[4][4] = {};
    float cmp[4][4] = {};

    for (int k0 = 0; k0 < K; k0 += BK) {
        #pragma unroll
        for (int i = 0; i < 4; i++) {
            int idx = tid + i * 256;
            int m  = idx >> 4;
            int kk = idx & 15;
            As[kk][m] = A[(long long)(bm + m) * lda + k0 + kk];
        }
        if (TRANSB) {
            #pragma unroll
            for (int i = 0; i < 4; i++) {
                int idx = tid + i * 256;
                int n  = idx >> 4;
                int kk = idx & 15;
                Bs[kk][n] = Bm[(long long)(bn + n) * ldb + k0 + kk];
            }
        } else {
            #pragma unroll
            for (int i = 0; i < 4; i++) {
                int idx = tid + i * 256;
                int kk = idx >> 6;
                int n  = idx & 63;
                Bs[kk][n] = Bm[(long long)(k0 + kk) * ldb + bn + n];
            }
        }
        __syncthreads();

        #pragma unroll
        for (int kk = 0; kk < BK; kk++) {
            float4 av = *(const float4*)&As[kk][ty * 4];
            float4 bv = *(const float4*)&Bs[kk][tx * 4];
            float a4[4] = {av.x, av.y, av.z, av.w};
            float b4[4] = {bv.x, bv.y, bv.z, bv.w};
            #pragma unroll
            for (int i = 0; i < 4; i++)
                #pragma unroll
                for (int j = 0; j < 4; j++) {
                    if (KAHAN) {
                        float y = __fmaf_rn(a4[i], b4[j], -cmp[i][j]);
                        float t = acc[i][j] + y;
                        cmp[i][j] = (t - acc[i][j]) - y;
                        acc[i][j] = t;
                    } else {
                        acc[i][j] = __fmaf_rn(a4[i], b4[j], acc[i][j]);
                    }
                }
        }
        __syncthreads();
    }

    #pragma unroll
    for (int i = 0; i < 4; i++) {
        int m = bm + ty * 4 + i;
        #pragma unroll
        for (int j = 0; j < 4; j++) {
            int n = bn + tx * 4 + j;
            float v = acc[i][j] * alpha;
            if (bias) v += bias[n];
            if (Res)  v += Res[(long long)m * ldr + n];
            if (ACT == 1) v = 0.5f * v * (1.0f + erff(v * 0.70710678118654752f));
            C[(long long)m * ldc + n] = v;
            if (OUTSPLIT) {
                bf16 h, l;
                split_bf16(v, h, l);
                Ch[(long long)m * ldc + n] = h;
                Cl[(long long)m * ldc + n] = l;
            }
        }
    }
}

// ---------------- transpose + split (weights) ----------------
__global__ __launch_bounds__(256)
void tsplit_kernel(const float* __restrict__ in, int K, int N,
                   bf16* __restrict__ oh, bf16* __restrict__ ol)
{
    __shared__ float tile[32][33];
    int nb = blockIdx.x * 32, kb = blockIdx.y * 32;
    int tx = threadIdx.x & 31, ty = threadIdx.x >> 5;
    #pragma unroll
    for (int i = 0; i < 32; i += 8)
        tile[ty + i][tx] = in[(long long)(kb + ty + i) * N + nb + tx];
    __syncthreads();
    #pragma unroll
    for (int i = 0; i < 32; i += 8) {
        int n = nb + ty + i, k = kb + tx;
        float v = tile[tx][ty + i];
        bf16 h, l;
        split_bf16(v, h, l);
        oh[(long long)n * K + k] = h;
        ol[(long long)n * K + k] = l;
    }
}

// ---------------- LayerNorm, fp64 stats, fp32 + split out ----------------
__global__ __launch_bounds__(256)
void ln_kernel(const float* __restrict__ x, const float* __restrict__ g,
               const float* __restrict__ b, float* __restrict__ y,
               bf16* __restrict__ yh, bf16* __restrict__ yl)
{
    long long row = blockIdx.x;
    const float* xr = x + row * DIM_;
    float* yr = y + row * DIM_;
    bf16* yhr = yh + row * DIM_;
    bf16* ylr = yl + row * DIM_;
    int t = threadIdx.x;
    float v0 = xr[t], v1 = xr[t + 256], v2 = xr[t + 512];
    double s = (double)v0 + (double)v1 + (double)v2;
    double q = (double)v0 * v0 + (double)v1 * v1 + (double)v2 * v2;
    __shared__ double sh[16];
    __shared__ float  par[2];
    #pragma unroll
    for (int o = 16; o > 0; o >>= 1) {
        s += __shfl_down_sync(~0u, s, o);
        q += __shfl_down_sync(~0u, q, o);
    }
    int wid = t >> 5, lane = t & 31;
    if (lane == 0) { sh[wid] = s; sh[wid + 8] = q; }
    __syncthreads();
    if (t == 0) {
        double ss = 0., qq = 0.;
        #pragma unroll
        for (int i = 0; i < 8; i++) { ss += sh[i]; qq += sh[i + 8]; }
        double mu = ss / DIM_;
        double var = qq / DIM_ - mu * mu;
        par[0] = (float)mu;
        par[1] = (float)(1.0 / sqrt(var + 1e-5));
    }
    __syncthreads();
    float mu = par[0], r = par[1];
    #pragma unroll
    for (int i = 0; i < 3; i++) {
        int c = t + i * 256;
        float vv = (i == 0 ? v0 : (i == 1 ? v1 : v2));
        float o = (vv - mu) * r * g[c] + b[c];
        yr[c] = o;
        bf16 h, l;
        split_bf16(o, h, l);
        yhr[c] = h;
        ylr[c] = l;
    }
}

// ---------------- row softmax over 320 ----------------
__global__ __launch_bounds__(128)
void softmax_kernel(float* __restrict__ attn)
{
    long long row = blockIdx.x;
    int t_q = (int)(row % NTOK);
    float* p = attn + row * NTOK;
    int t = threadIdx.x;
    float v[3];
    float m = -1e30f;
    #pragma unroll
    for (int i = 0; i < 3; i++) {
        int c = t + i * 128;
        v[i] = (c < NTOK) ? p[c] : -1e30f;
        m = fmaxf(m, v[i]);
    }
    __shared__ float shm[4];
    __shared__ double shd[4];
    #pragma unroll
    for (int o = 16; o > 0; o >>= 1) m = fmaxf(m, __shfl_xor_sync(~0u, m, o));
    if ((t & 31) == 0) shm[t >> 5] = m;
    __syncthreads();
    m = fmaxf(fmaxf(shm[0], shm[1]), fmaxf(shm[2], shm[3]));
    __syncthreads();

    if (t_q < LT_) {
        double e[3];
        double s = 0.0;
        #pragma unroll
        for (int i = 0; i < 3; i++) {
            int c = t + i * 128;
            if (c < NTOK) { e[i] = exp((double)v[i] - (double)m); s += e[i]; }
            else e[i] = 0.0;
        }
        #pragma unroll
        for (int o = 16; o > 0; o >>= 1) s += __shfl_xor_sync(~0u, s, o);
        if ((t & 31) == 0) shd[t >> 5] = s;
        __syncthreads();
        s = shd[0] + shd[1] + shd[2] + shd[3];
        double inv = 1.0 / s;
        #pragma unroll
        for (int i = 0; i < 3; i++) {
            int c = t + i * 128;
            if (c < NTOK) p[c] = (float)(e[i] * inv);
        }
    } else {
        float e[3];
        float s = 0.0f;
        #pragma unroll
        for (int i = 0; i < 3; i++) {
            int c = t + i * 128;
            if (c < NTOK) { e[i] = __expf(v[i] - m); s += e[i]; }
            else e[i] = 0.0f;
        }
        #pragma unroll
        for (int o = 16; o > 0; o >>= 1) s += __shfl_xor_sync(~0u, s, o);
        if ((t & 31) == 0) shm[t >> 5] = s;
        __syncthreads();
        s = shm[0] + shm[1] + shm[2] + shm[3];
        float inv = 1.0f / s;
        #pragma unroll
        for (int i = 0; i < 3; i++) {
            int c = t + i * 128;
            if (c < NTOK) p[c] = e[i] * inv;
        }
    }
}

// ---------------- CE scores (fp64) ----------------
__global__ __launch_bounds__(256)
void ce_score_kernel(const float* __restrict__ attn, const unsigned char* __restrict__ maskp,
                     float* __restrict__ S)
{
    int b = blockIdx.x;
    int j = threadIdx.x;
    __shared__ float mf[LT_];
    __shared__ double cntsh;
    __shared__ int mode;
    if (j == 0) {
        const unsigned int* w = (const unsigned int*)maskp;
        bool all_int = true, all_flt = true;
        for (int i = 0; i < 512; i++) {
            unsigned int v = w[i];
            if (v != 0u && v != 1u) all_int = false;
            if (v != 0u && v != 0x3F800000u) all_flt = false;
        }
        mode = all_int ? 0 : (all_flt ? 1 : 2);
    }
    __syncthreads();
    if (j < LT_) {
        int mv;
        if (mode == 0)      mv = ((const int*)maskp)[b * LT_ + j] != 0;
        else if (mode == 1) mv = ((const float*)maskp)[b * LT_ + j] != 0.0f;
        else                mv = maskp[b * LT_ + j] != 0;
        mf[j] = mv ? 1.0f : 0.0f;
    }
    __syncthreads();
    if (j == 0) {
        double c = 0.;
        for (int t = 0; t < LT_; t++) c += (double)mf[t];
        cntsh = c;
    }
    __syncthreads();
    double cnt = cntsh;
    double stot = 0.0;
    const float* base = attn + (long long)b * H_ * NTOK * NTOK + LT_ + j;
    for (int h = 0; h < H_; h++) {
        const float* ph = base + (long long)h * NTOK * NTOK;
        double sh = 0.0;
        #pragma unroll 4
        for (int t = 0; t < LT_; t++)
            sh += (double)ph[(long long)t * NTOK] * (double)mf[t];
        stot += sh / cnt;
    }
    S[b * LS_ + j] = (float)(stot / H_);
}

// ---------------- bitonic sort ----------------
__global__ __launch_bounds__(256)
void sort_kernel(const float* __restrict__ S, int* __restrict__ order)
{
    int b = blockIdx.x, t = threadIdx.x;
    __shared__ float val[256];
    __shared__ int   idx[256];
    val[t] = S[b * LS_ + t];
    idx[t] = t;
    __syncthreads();
    for (int k = 2; k <= 256; k <<= 1) {
        for (int j = k >> 1; j > 0; j >>= 1) {
            int p = t ^ j;
            if (p > t) {
                bool desc = ((t & k) == 0);
                float va = val[t], vb = val[p];
                int ia = idx[t], ib = idx[p];
                bool aFirst = (va > vb) || (va == vb && ia < ib);
                if (aFirst != desc) {
                    val[t] = vb; val[p] = va;
                    idx[t] = ib; idx[p] = ia;
                }
            }
            __syncthreads();
        }
    }
    order[b * LS_ + t] = idx[t];
}

// ---------------- gather ----------------
__global__ __launch_bounds__(256)
void gather_kernel(const float* __restrict__ X1, const int* __restrict__ ord,
                   float* __restrict__ X2)
{
    int b = blockIdx.x, t = blockIdx.y;
    int src = (t < LT_) ? t : (LT_ + ord[b * LS_ + (t - LT_)]);
    const float* s = X1 + ((long long)b * NTOK + src) * DIM_;
    float* d = X2 + ((long long)b * N2 + t) * DIM_;
    int i = threadIdx.x;
    d[i] = s[i];
    d[i + 256] = s[i + 256];
    d[i + 512] = s[i + 512];
}

// ---------------- index outputs ----------------
__global__ __launch_bounds__(256)
void indices_kernel(const int* __restrict__ ord, const int* __restrict__ gsi,
                    float* __restrict__ outK, float* __restrict__ outR)
{
    int b = blockIdx.x, t = threadIdx.x;
    if (t < LK_) outK[b * LK_ + t] = (float)gsi[b * LS_ + ord[b * LS_ + t]];
    if (t < LR_) outR[b * LR_ + t] = (float)gsi[b * LS_ + ord[b * LS_ + LK_ + t]];
}

__global__ __launch_bounds__(256)
void git_kernel(const int* __restrict__ git, float* __restrict__ out)
{
    int i = blockIdx.x * 256 + threadIdx.x;
    if (i < B_ * LT_) out[i] = (float)git[i];
}

// ---------------- streams/events (created pre-main) ----------------
struct StreamPool {
    cudaStream_t f, m1;                 // single SHARED fma stream + branch-1 main
    cudaEvent_t evFork, evLN0, evLN1, evF0, evF1, evEnd1;
    StreamPool() {
        cudaStreamCreateWithFlags(&f,  cudaStreamNonBlocking);
        cudaStreamCreateWithFlags(&m1, cudaStreamNonBlocking);
        cudaEventCreateWithFlags(&evFork, cudaEventDisableTiming);
        cudaEventCreateWithFlags(&evLN0, cudaEventDisableTiming);
        cudaEventCreateWithFlags(&evLN1, cudaEventDisableTiming);
        cudaEventCreateWithFlags(&evF0,  cudaEventDisableTiming);
        cudaEventCreateWithFlags(&evF1,  cudaEventDisableTiming);
        cudaEventCreateWithFlags(&evEnd1, cudaEventDisableTiming);
    }
};
static StreamPool g_sp;

// ---------------- per-branch buffers ----------------
struct BranchBufs {
    float *XLN, *QKV, *Q64, *ATTN, *O, *X1, *S, *X2, *XLN2;
    int* ORD;
    bf16 *XLNh, *XLNl, *Oh, *Ol, *XLN2h, *XLN2l, *H1h, *H1l;
};
struct Weights {
    bf16 *WqkvTh, *WqkvTl, *WprojTh, *WprojTl, *W1Th, *W1Tl, *W2Th, *W2Tl;
};

// Kahan score-path chain for one branch, enqueued on the SHARED fma stream
static void enqueue_kahan_chain(cudaStream_t f, const float* Wqkv, const float* bqkv,
                                const BranchBufs& bu)
{
    // Kahan k (all rows)
    gemm_kernel<false, 0, true, false><<<dim3(DIM_ / BN, B_ * NTOK / BM, 1), 256, 0, f>>>(
        bu.XLN, DIM_, 0, 0,
        Wqkv + DIM_, 3 * DIM_, 0, 0,
        bu.QKV + DIM_, 3 * DIM_, 0, 0,
        nullptr, nullptr,
        bqkv + DIM_, nullptr, 0, 0, 0,
        DIM_, 1, 1.0f);
    // Kahan q rows<64 -> Q64
    gemm_kernel<false, 0, true, false><<<dim3(DIM_ / BN, 1, B_), 256, 0, f>>>(
        bu.XLN, DIM_, 0, (long long)NTOK * DIM_,
        Wqkv, 3 * DIM_, 0, 0,
        bu.Q64, DIM_, 0, (long long)LT_ * DIM_,
        nullptr, nullptr,
        bqkv, nullptr, 0, 0, 0,
        DIM_, B_, 1.0f);
    // Kahan logits rows<64
    gemm_kernel<true, 0, true, false><<<dim3(NTOK / BN, 1, B_ * H_), 256, 0, f>>>(
        bu.Q64,        DIM_,     (long long)LT_ * DIM_,       DH,
        bu.QKV + DIM_, 3 * DIM_, (long long)NTOK * 3 * DIM_,  DH,
        bu.ATTN, NTOK, (long long)H_ * NTOK * NTOK, (long long)NTOK * NTOK,
        nullptr, nullptr,
        nullptr, nullptr, 0, 0, 0,
        DH, H_, 0.125f);
}

// tensor-lane prologue (tc q + tc v), enqueued on the branch's main stream
static void enqueue_qv(cudaStream_t m, const float* bqkv,
                       const BranchBufs& bu, const Weights& w)
{
    tc_gemm2<0, false><<<dim3(DIM_ / 128, B_ * NTOK / 128), TC_THREADS, TC_SMEM_TOTAL, m>>>(
        bu.XLNh, bu.XLNl, DIM_, w.WqkvTh, w.WqkvTl, DIM_,
        bu.QKV, 3 * DIM_, nullptr, nullptr, bqkv, nullptr, 0, DIM_);
    tc_gemm2<0, false><<<dim3(DIM_ / 128, B_ * NTOK / 128), TC_THREADS, TC_SMEM_TOTAL, m>>>(
        bu.XLNh, bu.XLNl, DIM_,
        w.WqkvTh + 2 * DIM_ * DIM_, w.WqkvTl + 2 * DIM_ * DIM_, DIM_,
        bu.QKV + 2 * DIM_, 3 * DIM_, nullptr, nullptr, bqkv + 2 * DIM_, nullptr, 0, DIM_);
}

// post-Kahan tail for one branch on its main stream
static void enqueue_tail(cudaStream_t m,
                         const float* x, const int* gsi, const unsigned char* mask,
                         const float* bproj,
                         const float* g2, const float* b2,
                         const float* bm1, const float* bm2,
                         float* outX, float* outK, float* outR,
                         const BranchBufs& bu, const Weights& w)
{
    // plain logits rows 64..319 (fp32)
    gemm_kernel<true, 0, false, false><<<dim3(NTOK / BN, 4, B_ * H_), 256, 0, m>>>(
        bu.QKV + (long long)LT_ * 3 * DIM_, 3 * DIM_, (long long)NTOK * 3 * DIM_, DH,
        bu.QKV + DIM_,                      3 * DIM_, (long long)NTOK * 3 * DIM_, DH,
        bu.ATTN + (long long)LT_ * NTOK, NTOK, (long long)H_ * NTOK * NTOK, (long long)NTOK * NTOK,
        nullptr, nullptr,
        nullptr, nullptr, 0, 0, 0,
        DH, H_, 0.125f);

    softmax_kernel<<<B_ * H_ * NTOK, 128, 0, m>>>(bu.ATTN);

    // O = P @ V (fp32, split out)
    gemm_kernel<false, 0, false, true><<<dim3(DH / BN, NTOK / BM, B_ * H_), 256, 0, m>>>(
        bu.ATTN, NTOK, (long long)H_ * NTOK * NTOK, (long long)NTOK * NTOK,
        bu.QKV + 2 * DIM_, 3 * DIM_, (long long)NTOK * 3 * DIM_, DH,
        bu.O, DIM_, (long long)NTOK * DIM_, DH,
        bu.Oh, bu.Ol,
        nullptr, nullptr, 0, 0, 0,
        NTOK, H_, 1.0f);

    // X1 = x + O @ Wproj + bproj (tc)
    tc_gemm2<0, false><<<dim3(DIM_ / 128, B_ * NTOK / 128), TC_THREADS, TC_SMEM_TOTAL, m>>>(
        bu.Oh, bu.Ol, DIM_, w.WprojTh, w.WprojTl, DIM_,
        bu.X1, DIM_, nullptr, nullptr, bproj, x, DIM_, DIM_);

    // CE
    ce_score_kernel<<<B_, 256, 0, m>>>(bu.ATTN, mask, bu.S);
    sort_kernel<<<B_, 256, 0, m>>>(bu.S, bu.ORD);
    gather_kernel<<<dim3(B_, N2), 256, 0, m>>>(bu.X1, bu.ORD, bu.X2);
    indices_kernel<<<B_, 256, 0, m>>>(bu.ORD, gsi, outK, outR);

    // LN2
    ln_kernel<<<B_ * N2, 256, 0, m>>>(bu.X2, g2, b2, bu.XLN2, bu.XLN2h, bu.XLN2l);

    // MLP1 (tc, split-only out)
    tc_gemm2<1, true><<<dim3(4 * DIM_ / 128, B_ * N2 / 128), TC_THREADS, TC_SMEM_TOTAL, m>>>(
        bu.XLN2h, bu.XLN2l, DIM_, w.W1Th, w.W1Tl, DIM_,
        nullptr, 4 * DIM_, bu.H1h, bu.H1l, bm1, nullptr, 0, DIM_);

    // MLP2 (tc)
    tc_gemm2<0, false><<<dim3(DIM_ / 128, B_ * N2 / 128), TC_THREADS, TC_SMEM_TOTAL, m>>>(
        bu.H1h, bu.H1l, 4 * DIM_, w.W2Th, w.W2Tl, 4 * DIM_,
        outX, DIM_, nullptr, nullptr, bm2, bu.X2, DIM_, 4 * DIM_);
}

static void get_branch_bufs(int br, BranchBufs& bu)
{
    char* p;
    cudaGetSymbolAddress((void**)&p, g_XLN);  bu.XLN  = (float*)p + (size_t)br * B_ * NTOK * DIM_;
    cudaGetSymbolAddress((void**)&p, g_QKV);  bu.QKV  = (float*)p + (size_t)br * B_ * NTOK * 3 * DIM_;
    cudaGetSymbolAddress((void**)&p, g_Q64);  bu.Q64  = (float*)p + (size_t)br * B_ * LT_ * DIM_;
    cudaGetSymbolAddress((void**)&p, g_ATTN); bu.ATTN = (float*)p + (size_t)br * B_ * H_ * NTOK * NTOK;
    cudaGetSymbolAddress((void**)&p, g_O);    bu.O    = (float*)p + (size_t)br * B_ * NTOK * DIM_;
    cudaGetSymbolAddress((void**)&p, g_X1);   bu.X1   = (float*)p + (size_t)br * B_ * NTOK * DIM_;
    cudaGetSymbolAddress((void**)&p, g_S);    bu.S    = (float*)p + (size_t)br * B_ * LS_;
    cudaGetSymbolAddress((void**)&p, g_ORD);  bu.ORD  = (int*)p   + (size_t)br * B_ * LS_;
    cudaGetSymbolAddress((void**)&p, g_X2);   bu.X2   = (float*)p + (size_t)br * B_ * N2 * DIM_;
    cudaGetSymbolAddress((void**)&p, g_XLN2); bu.XLN2 = (float*)p + (size_t)br * B_ * N2 * DIM_;
    cudaGetSymbolAddress((void**)&p, g_XLNh); bu.XLNh = (bf16*)p + (size_t)br * B_ * NTOK * DIM_;
    cudaGetSymbolAddress((void**)&p, g_XLNl); bu.XLNl = (bf16*)p + (size_t)br * B_ * NTOK * DIM_;
    cudaGetSymbolAddress((void**)&p, g_Oh);   bu.Oh   = (bf16*)p + (size_t)br * B_ * NTOK * DIM_;
    cudaGetSymbolAddress((void**)&p, g_Ol);   bu.Ol   = (bf16*)p + (size_t)br * B_ * NTOK * DIM_;
    cudaGetSymbolAddress((void**)&p, g_XLN2h); bu.XLN2h = (bf16*)p + (size_t)br * B_ * N2 * DIM_;
    cudaGetSymbolAddress((void**)&p, g_XLN2l); bu.XLN2l = (bf16*)p + (size_t)br * B_ * N2 * DIM_;
    cudaGetSymbolAddress((void**)&p, g_H1h);  bu.H1h  = (bf16*)p + (size_t)br * B_ * N2 * 4 * DIM_;
    cudaGetSymbolAddress((void**)&p, g_H1l);  bu.H1l  = (bf16*)p + (size_t)br * B_ * N2 * 4 * DIM_;
}

extern "C" void kernel_launch(void* const* d_in, const int* in_sizes, int n_in,
                              void* d_out, int out_size)
{
    const float* x_rgb  = (const float*)d_in[0];
    const float* x_dte  = (const float*)d_in[1];
    const int*   git    = (const int*)d_in[2];
    const int*   gsi_rgb = (const int*)d_in[3];
    const int*   gsi_dte = (const int*)d_in[4];
    const unsigned char* mask = (const unsigned char*)d_in[5];
    const float* g1    = (const float*)d_in[6];
    const float* b1    = (const float*)d_in[7];
    const float* Wqkv  = (const float*)d_in[8];
    const float* bqkv  = (const float*)d_in[9];
    const float* Wproj = (const float*)d_in[10];
    const float* bproj = (const float*)d_in[11];
    const float* g2    = (const float*)d_in[12];
    const float* b2    = (const float*)d_in[13];
    const float* W1    = (const float*)d_in[14];
    const float* bm1   = (const float*)d_in[15];
    const float* W2    = (const float*)d_in[16];
    const float* bm2   = (const float*)d_in[17];

    float* out = (float*)d_out;

    cudaFuncSetAttribute(tc_gemm2<0, false>, cudaFuncAttributeMaxDynamicSharedMemorySize, TC_SMEM_TOTAL);
    cudaFuncSetAttribute(tc_gemm2<1, true>,  cudaFuncAttributeMaxDynamicSharedMemorySize, TC_SMEM_TOTAL);

    Weights w;
    {
        char* p;
        cudaGetSymbolAddress((void**)&p, g_WqkvTh);  w.WqkvTh  = (bf16*)p;
        cudaGetSymbolAddress((void**)&p, g_WqkvTl);  w.WqkvTl  = (bf16*)p;
        cudaGetSymbolAddress((void**)&p, g_WprojTh); w.WprojTh = (bf16*)p;
        cudaGetSymbolAddress((void**)&p, g_WprojTl); w.WprojTl = (bf16*)p;
        cudaGetSymbolAddress((void**)&p, g_W1Th);    w.W1Th    = (bf16*)p;
        cudaGetSymbolAddress((void**)&p, g_W1Tl);    w.W1Tl    = (bf16*)p;
        cudaGetSymbolAddress((void**)&p, g_W2Th);    w.W2Th    = (bf16*)p;
        cudaGetSymbolAddress((void**)&p, g_W2Tl);    w.W2Tl    = (bf16*)p;
    }
    BranchBufs bu0, bu1;
    get_branch_bufs(0, bu0);
    get_branch_bufs(1, bu1);

    const long long XSZ     = (long long)B_ * N2 * DIM_;
    const long long GIT_OFF = 2 * XSZ;
    const long long K0_OFF  = GIT_OFF + (long long)B_ * LT_;
    const long long K1_OFF  = K0_OFF + (long long)B_ * LK_;
    const long long R0_OFF  = K1_OFF + (long long)B_ * LK_;
    const long long R1_OFF  = R0_OFF + (long long)B_ * LR_;

    // shared prologue on the origin (default) stream
    git_kernel<<<(B_ * LT_ + 255) / 256, 256>>>(git, out + GIT_OFF);
    tsplit_kernel<<<dim3(3 * DIM_ / 32, DIM_ / 32), 256>>>(Wqkv, DIM_, 3 * DIM_, w.WqkvTh, w.WqkvTl);
    tsplit_kernel<<<dim3(DIM_ / 32, DIM_ / 32), 256>>>(Wproj, DIM_, DIM_, w.WprojTh, w.WprojTl);
    tsplit_kernel<<<dim3(4 * DIM_ / 32, DIM_ / 32), 256>>>(W1, DIM_, 4 * DIM_, w.W1Th, w.W1Tl);
    tsplit_kernel<<<dim3(DIM_ / 32, 4 * DIM_ / 32), 256>>>(W2, 4 * DIM_, DIM_, w.W2Th, w.W2Tl);

    // fork branch 1 main stream right after weights
    cudaEventRecord(g_sp.evFork, (cudaStream_t)0);
    cudaStreamWaitEvent(g_sp.m1, g_sp.evFork, 0);

    // LN1 for both branches (on their own main streams)
    ln_kernel<<<B_ * NTOK, 256, 0, (cudaStream_t)0>>>(x_rgb, g1, b1, bu0.XLN, bu0.XLNh, bu0.XLNl);
    cudaEventRecord(g_sp.evLN0, (cudaStream_t)0);
    ln_kernel<<<B_ * NTOK, 256, 0, g_sp.m1>>>(x_dte, g1, b1, bu1.XLN, bu1.XLNh, bu1.XLNl);
    cudaEventRecord(g_sp.evLN1, g_sp.m1);

    // tensor q/v on each branch's main stream (overlaps Kahan chain below)
    enqueue_qv((cudaStream_t)0, bqkv, bu0, w);
    enqueue_qv(g_sp.m1,          bqkv, bu1, w);

    // SHARED fma stream: b0 Kahan chain, then b1 Kahan chain (FMA pipe is serial anyway)
    cudaStreamWaitEvent(g_sp.f, g_sp.evLN0, 0);
    enqueue_kahan_chain(g_sp.f, Wqkv, bqkv, bu0);
    cudaEventRecord(g_sp.evF0, g_sp.f);
    cudaStreamWaitEvent(g_sp.f, g_sp.evLN1, 0);
    enqueue_kahan_chain(g_sp.f, Wqkv, bqkv, bu1);
    cudaEventRecord(g_sp.evF1, g_sp.f);

    // each branch's tail starts as soon as ITS Kahan chain finished
    cudaStreamWaitEvent((cudaStream_t)0, g_sp.evF0, 0);
    enqueue_tail((cudaStream_t)0, x_rgb, gsi_rgb, mask, bproj, g2, b2, bm1, bm2,
                 out, out + K0_OFF, out + R0_OFF, bu0, w);

    cudaStreamWaitEvent(g_sp.m1, g_sp.evF1, 0);
    enqueue_tail(g_sp.m1, x_dte, gsi_dte, mask, bproj, g2, b2, bm1, bm2,
                 out + XSZ, out + K1_OFF, out + R1_OFF, bu1, w);

    // join
    cudaEventRecord(g_sp.evEnd1, g_sp.m1);
    cudaStreamWaitEvent((cudaStream_t)0, g_sp.evEnd1, 0);
}

// round 12
// speedup vs baseline: 1.1778x; 1.0052x over previous
#include <cuda_runtime.h>
#include <cuda_bf16.h>
#include <math.h>
#include <stdint.h>

// ---------------- problem constants ----------------
#define B_    32
#define LT_   64
#define LS_   256
#define NTOK  320      // LT + LS
#define DIM_  768
#define H_    12
#define DH    64
#define LK_   180
#define LR_   76
#define N2    244      // LT + LK

#if defined(__CUDA_ARCH__) && defined(__CUDA_ARCH_FEAT_SM103_ALL)
#define HAS_TCGEN05 1
#else
#define HAS_TCGEN05 0
#endif

typedef __nv_bfloat16 bf16;

// ---------------- scratch (per-branch duplicated) ----------------
__device__ float g_XLN [2][B_ * NTOK * DIM_];
__device__ float g_QKV [2][B_ * NTOK * 3 * DIM_];
__device__ float g_Q64 [2][B_ * LT_ * DIM_];
__device__ float g_ATTN[2][(size_t)B_ * H_ * NTOK * NTOK];
__device__ float g_O   [2][B_ * NTOK * DIM_];
__device__ float g_X1  [2][B_ * NTOK * DIM_];
__device__ float g_S   [2][B_ * LS_];
__device__ int   g_ORD [2][B_ * LS_];
__device__ float g_X2  [2][B_ * N2 * DIM_];
__device__ float g_XLN2[2][B_ * N2 * DIM_];

__device__ unsigned short g_XLNh [2][B_ * NTOK * DIM_];
__device__ unsigned short g_XLNl [2][B_ * NTOK * DIM_];
__device__ unsigned short g_Oh   [2][B_ * NTOK * DIM_];
__device__ unsigned short g_Ol   [2][B_ * NTOK * DIM_];
__device__ unsigned short g_XLN2h[2][B_ * N2 * DIM_];
__device__ unsigned short g_XLN2l[2][B_ * N2 * DIM_];
__device__ unsigned short g_H1h  [2][B_ * N2 * 4 * DIM_];
__device__ unsigned short g_H1l  [2][B_ * N2 * 4 * DIM_];

// shared weight splits
__device__ unsigned short g_WqkvTh[3 * DIM_ * DIM_];
__device__ unsigned short g_WqkvTl[3 * DIM_ * DIM_];
__device__ unsigned short g_WprojTh[DIM_ * DIM_];
__device__ unsigned short g_WprojTl[DIM_ * DIM_];
__device__ unsigned short g_W1Th [4 * DIM_ * DIM_];
__device__ unsigned short g_W1Tl [4 * DIM_ * DIM_];
__device__ unsigned short g_W2Th [4 * DIM_ * DIM_];
__device__ unsigned short g_W2Tl [4 * DIM_ * DIM_];

__device__ __forceinline__ void split_bf16(float v, bf16& h, bf16& l) {
    h = __float2bfloat16(v);
    l = __float2bfloat16(v - __bfloat162float(h));
}

// =====================================================================
// tcgen05 helpers (sm_103a pass only)
// =====================================================================
#if HAS_TCGEN05
__device__ __forceinline__ uint32_t elect_one_pred() {
    uint32_t pred;
    asm volatile(
        "{\n\t.reg .pred p;\n\telect.sync _|p, 0xFFFFFFFF;\n\tselp.b32 %0, 1, 0, p;\n\t}"
        : "=r"(pred));
    return pred;
}
__device__ __forceinline__ uint32_t smem_to_u32(const void* smem_ptr) {
    uint32_t addr;
    asm("{ .reg .u64 tmp; cvta.to.shared.u64 tmp, %1; cvt.u32.u64 %0, tmp; }"
        : "=r"(addr) : "l"(smem_ptr));
    return addr;
}
__device__ __forceinline__ void cp16(uint32_t s, const void* g) {
    asm volatile("cp.async.cg.shared.global [%0], [%1], 16;" :: "r"(s), "l"(g) : "memory");
}
#define CP_COMMIT() asm volatile("cp.async.commit_group;" ::: "memory")
#define CP_WAIT(n)  asm volatile("cp.async.wait_group %0;" :: "n"(n) : "memory")

#define TCGEN05_ALLOC(a, n) \
    asm volatile("tcgen05.alloc.cta_group::1.sync.aligned.shared::cta.b32 [%0], %1;" \
        :: "r"((uint32_t)(a)), "r"((uint32_t)(n)) : "memory")
#define TCGEN05_DEALLOC(t, n) \
    asm volatile("tcgen05.dealloc.cta_group::1.sync.aligned.b32 %0, %1;" \
        :: "r"(t), "r"((uint32_t)(n)))
#define TCGEN05_RELINQUISH_ALLOC_PERMIT() \
    asm volatile("tcgen05.relinquish_alloc_permit.cta_group::1.sync.aligned;")
#define TCGEN05_COMMIT(m) \
    asm volatile("tcgen05.commit.cta_group::1.mbarrier::arrive::one.shared::cluster.b64 [%0];" \
        :: "r"((uint32_t)(m)) : "memory")
#define TCGEN05_WAIT_LD()  asm volatile("tcgen05.wait::ld.sync.aligned;" ::: "memory")
#define TCGEN05_FENCE_BEFORE() asm volatile("tcgen05.fence::before_thread_sync;" ::: "memory")
#define TCGEN05_FENCE_AFTER()  asm volatile("tcgen05.fence::after_thread_sync;" ::: "memory")
#define FENCE_PROXY_ASYNC_SHARED_CTA() asm volatile("fence.proxy.async.shared::cta;" ::: "memory")
#define MBARRIER_INIT(m, c) \
    asm volatile("mbarrier.init.shared.b64 [%0], %1;" :: "r"((uint32_t)(m)), "r"((uint32_t)(c)) : "memory")
#define MBARRIER_INVAL(m) \
    asm volatile("mbarrier.inval.shared.b64 [%0];" :: "r"((uint32_t)(m)) : "memory")

#define MBARRIER_WAIT_PARITY(mb, pp) do { \
    uint32_t _mbar = (uint32_t)(mb); \
    uint32_t _parity = (uint32_t)(pp); \
    uint32_t _done; \
    asm volatile( \
        "{\n\t.reg .pred p;\n\t" \
        "mbarrier.try_wait.parity.acquire.cta.shared::cta.b64 p, [%1], %2;\n\t" \
        "selp.b32 %0, 1, 0, p;\n\t}" \
        : "=r"(_done) : "r"(_mbar), "r"(_parity) : "memory"); \
    if (!_done) { \
        asm volatile( \
            "{\n\t.reg .pred P1;\n\t" \
            "WAIT_LOOP_%=:\n\t" \
            "mbarrier.try_wait.parity.acquire.cta.shared::cta.b64 P1, [%0], %1, 0x989680;\n\t" \
            "@P1 bra.uni WAIT_DONE_%=;\n\t" \
            "bra.uni WAIT_LOOP_%=;\n\t" \
            "WAIT_DONE_%=:\n\t}" \
            :: "r"(_mbar), "r"(_parity) : "memory"); \
    } \
} while(0)

#define TCGEN05_LD_32X32B_X32(r, tmem_addr) \
    asm volatile( \
        "tcgen05.ld.sync.aligned.32x32b.x32.b32 " \
        "{%0, %1, %2, %3, %4, %5, %6, %7, " \
        " %8, %9, %10, %11, %12, %13, %14, %15, " \
        " %16, %17, %18, %19, %20, %21, %22, %23, " \
        " %24, %25, %26, %27, %28, %29, %30, %31}, [%32];" \
        : "=r"((r)[0]),  "=r"((r)[1]),  "=r"((r)[2]),  "=r"((r)[3]), \
          "=r"((r)[4]),  "=r"((r)[5]),  "=r"((r)[6]),  "=r"((r)[7]), \
          "=r"((r)[8]),  "=r"((r)[9]),  "=r"((r)[10]), "=r"((r)[11]), \
          "=r"((r)[12]), "=r"((r)[13]), "=r"((r)[14]), "=r"((r)[15]), \
          "=r"((r)[16]), "=r"((r)[17]), "=r"((r)[18]), "=r"((r)[19]), \
          "=r"((r)[20]), "=r"((r)[21]), "=r"((r)[22]), "=r"((r)[23]), \
          "=r"((r)[24]), "=r"((r)[25]), "=r"((r)[26]), "=r"((r)[27]), \
          "=r"((r)[28]), "=r"((r)[29]), "=r"((r)[30]), "=r"((r)[31]) \
        : "r"(tmem_addr))

static constexpr uint64_t SMEM_DESC_BASE_SW128 =
    (uint64_t(2)  << 61) | (uint64_t(1) << 46) | (uint64_t(64) << 32) | (uint64_t(1) << 16);
#define MAKE_SMEM_DESC(base_addr) \
    (SMEM_DESC_BASE_SW128 | ((uint64_t)((base_addr) >> 4) & 0x3FFF))

__device__ __forceinline__ void tc_mma_f16_ss(uint32_t d, uint64_t a, uint64_t b,
                                              uint32_t idesc, uint32_t en)
{
    asm volatile(
        "{\n\t.reg .pred p;\n\tsetp.ne.u32 p, %5, 0;\n\t"
        "tcgen05.mma.cta_group::1.kind::f16 [%0], %1, %2, %3, {%4, %4, %4, %4}, p;\n\t}"
        :: "r"(d), "l"(a), "l"(b), "r"(idesc), "r"(0u), "r"(en) : "memory");
}
#endif // HAS_TCGEN05

// =====================================================================
// tc_gemm2: cp.async pipelined split-bf16 tc GEMM.
// qv mode: blocks with n0 >= DIM_ shift B rows and C cols by +DIM_
// (merged q|v GEMM against the full WqkvT buffer; skips the k slab).
// =====================================================================
#define TC_THREADS 256
#define TC_SMEM_TOTAL (1024 + 2 * 4 * 16384)   // 132096 bytes
#define TC_IDESC 0x8200490u

template<int ACT, bool OUTSPLIT>
__global__ __launch_bounds__(TC_THREADS)
void tc_gemm2(const bf16* __restrict__ Ah, const bf16* __restrict__ Al, int lda,
              const bf16* __restrict__ Bh, const bf16* __restrict__ Bl, int ldb,
              float* __restrict__ C, int ldc,
              bf16* __restrict__ Ch, bf16* __restrict__ Cl,
              const float* __restrict__ bias,
              const float* __restrict__ Res, int ldr,
              int K, int qv)
{
    const int n0_raw = blockIdx.x * 128;
    int cshift = (qv && n0_raw >= DIM_) ? DIM_ : 0;
    Bh += (long long)cshift * ldb;
    Bl += (long long)cshift * ldb;
#if HAS_TCGEN05
    extern __shared__ char smem[];
    const uint32_t sb = smem_to_u32(smem);
    const int tid = threadIdx.x;
    const int wid = tid >> 5;
    const int lid = tid & 31;
    const int m0 = blockIdx.y * 128;
    const int n0 = n0_raw;

    if (wid == 0) {
        TCGEN05_ALLOC(sb + 0, 128);
        TCGEN05_RELINQUISH_ALLOC_PERMIT();
    }
    if (tid == 0) { MBARRIER_INIT(sb + 16, 1); MBARRIER_INIT(sb + 24, 1); }
    __syncthreads();
    uint32_t tmem;
    asm volatile("ld.shared.b32 %0, [%1];" : "=r"(tmem) : "r"(sb));

    const int nk = K >> 6;
    const int lr  = tid >> 3;
    const int lcq = (tid & 7) * 8;

    #define TC_ISSUE_CHUNK(ktv)  do {                                              \
        const int _buf = (ktv) & 1;                                                \
        uint32_t _db = sb + 1024 + _buf * 65536;                                   \
        const bf16* _Agh = Ah + (long long)m0 * lda + (ktv) * 64;                  \
        const bf16* _Agl = Al + (long long)m0 * lda + (ktv) * 64;                  \
        const bf16* _Bgh = Bh + (long long)n0 * ldb + (ktv) * 64;                  \
        const bf16* _Bgl = Bl + (long long)n0 * ldb + (ktv) * 64;                  \
        _Pragma("unroll")                                                          \
        for (int _i = 0; _i < 4; _i++) {                                           \
            int _r = lr + _i * 32;                                                 \
            uint32_t _bo = _r * 128 + lcq * 2;                                     \
            uint32_t _so = _bo ^ ((_bo >> 3) & 0x70);                              \
            cp16(_db + _so,          _Agh + (long long)_r * lda + lcq);            \
            cp16(_db + 16384 + _so,  _Agl + (long long)_r * lda + lcq);            \
            cp16(_db + 32768 + _so,  _Bgh + (long long)_r * ldb + lcq);            \
            cp16(_db + 49152 + _so,  _Bgl + (long long)_r * ldb + lcq);            \
        }                                                                          \
        CP_COMMIT();                                                               \
    } while (0)

    TC_ISSUE_CHUNK(0);
    for (int kt = 0; kt < nk; kt++) {
        if (kt + 1 < nk) {
            if (kt >= 1)
                MBARRIER_WAIT_PARITY(sb + 16 + 8 * ((kt - 1) & 1), ((kt - 1) >> 1) & 1);
            TC_ISSUE_CHUNK(kt + 1);
            CP_WAIT(1);
        } else {
            CP_WAIT(0);
        }
        FENCE_PROXY_ASYNC_SHARED_CTA();
        __syncthreads();

        if (wid == 0) {
            if (elect_one_pred()) {
                uint32_t ab = sb + 1024 + (kt & 1) * 65536;
                uint64_t dAh = MAKE_SMEM_DESC(ab);
                uint64_t dAl = MAKE_SMEM_DESC(ab + 16384);
                uint64_t dBh = MAKE_SMEM_DESC(ab + 32768);
                uint64_t dBl = MAKE_SMEM_DESC(ab + 49152);
                #pragma unroll
                for (int k = 0; k < 4; k++)
                    tc_mma_f16_ss(tmem, dAh + k * 2, dBh + k * 2, TC_IDESC,
                                  (kt == 0 && k == 0) ? 0u : 1u);
                #pragma unroll
                for (int k = 0; k < 4; k++)
                    tc_mma_f16_ss(tmem, dAh + k * 2, dBl + k * 2, TC_IDESC, 1u);
                #pragma unroll
                for (int k = 0; k < 4; k++)
                    tc_mma_f16_ss(tmem, dAl + k * 2, dBh + k * 2, TC_IDESC, 1u);
                TCGEN05_COMMIT(sb + 16 + 8 * (kt & 1));
            }
        }
    }
    #undef TC_ISSUE_CHUNK

    if (nk >= 2)
        MBARRIER_WAIT_PARITY(sb + 16 + 8 * ((nk - 2) & 1), ((nk - 2) >> 1) & 1);
    MBARRIER_WAIT_PARITY(sb + 16 + 8 * ((nk - 1) & 1), ((nk - 1) >> 1) & 1);
    TCGEN05_FENCE_AFTER();

    if (wid < 4) {
        int m = m0 + wid * 32 + lid;
        float* Crow = C ? (C + (long long)m * ldc + n0 + cshift) : (float*)0;
        bf16* Chrow = OUTSPLIT ? (Ch + (long long)m * ldc + n0) : (bf16*)0;
        bf16* Clrow = OUTSPLIT ? (Cl + (long long)m * ldc + n0) : (bf16*)0;
        const float* Rrow = Res ? (Res + (long long)m * ldr + n0) : (const float*)0;
        #pragma unroll
        for (int cb = 0; cb < 128; cb += 32) {
            uint32_t d[32];
            TCGEN05_LD_32X32B_X32(d, tmem + cb);
            TCGEN05_WAIT_LD();
            float vout[32];
            #pragma unroll
            for (int j = 0; j < 32; j++) {
                float v = __uint_as_float(d[j]);
                if (bias) v += bias[n0 + cshift + cb + j];
                if (Rrow) v += Rrow[cb + j];
                if (ACT == 1) v = 0.5f * v * (1.0f + erff(v * 0.70710678118654752f));
                vout[j] = v;
            }
            if (Crow) {
                #pragma unroll
                for (int q = 0; q < 32; q += 4)
                    *(float4*)&Crow[cb + q] = *(float4*)&vout[q];
            }
            if (OUTSPLIT) {
                #pragma unroll
                for (int q = 0; q < 32; q += 2) {
                    bf16 h0, l0, h1, l1;
                    split_bf16(vout[q], h0, l0);
                    split_bf16(vout[q + 1], h1, l1);
                    unsigned int hw = (unsigned int)__bfloat16_as_ushort(h0) |
                                      ((unsigned int)__bfloat16_as_ushort(h1) << 16);
                    unsigned int lw = (unsigned int)__bfloat16_as_ushort(l0) |
                                      ((unsigned int)__bfloat16_as_ushort(l1) << 16);
                    *(unsigned int*)&Chrow[cb + q] = hw;
                    *(unsigned int*)&Clrow[cb + q] = lw;
                }
            }
        }
        TCGEN05_FENCE_BEFORE();
    }
    __syncthreads();
    if (tid == 0) { MBARRIER_INVAL(sb + 16); MBARRIER_INVAL(sb + 24); }
    __syncthreads();
    if (wid == 0) TCGEN05_DEALLOC(tmem, 128);
#else
    // fp32 fallback (never runs on GB300)
    const int tid = threadIdx.x;
    const int m0 = blockIdx.y * 128;
    const int n0 = n0_raw;
    for (int e = tid; e < 128 * 128; e += TC_THREADS) {
        int mi = e >> 7, ni = e & 127;
        int m = m0 + mi, n = n0 + ni;
        float s = 0.f;
        for (int k = 0; k < K; k++)
            s += (__bfloat162float(Ah[(long long)m * lda + k]) + __bfloat162float(Al[(long long)m * lda + k])) *
                 (__bfloat162float(Bh[(long long)n * ldb + k]) + __bfloat162float(Bl[(long long)n * ldb + k]));
        if (bias) s += bias[n + cshift];
        if (Res)  s += Res[(long long)m * ldr + n];
        if (ACT == 1) s = 0.5f * s * (1.0f + erff(s * 0.70710678118654752f));
        if (C) C[(long long)m * ldc + n + cshift] = s;
        if (OUTSPLIT) {
            bf16 h, l; split_bf16(s, h, l);
            Ch[(long long)m * ldc + n] = h;
            Cl[(long long)m * ldc + n] = l;
        }
    }
#endif
}

// ================= 64x64 GEMM (Kahan-capable, batched, opt split-out) =================
#define BM 64
#define BN 64
#define BK 16

template<bool TRANSB, int ACT, bool KAHAN, bool OUTSPLIT>
__global__ __launch_bounds__(256)
void gemm_kernel(const float* __restrict__ A, int lda, long long sA1, long long sA2,
                 const float* __restrict__ Bm, int ldb, long long sB1, long long sB2,
                 float* __restrict__ C, int ldc, long long sC1, long long sC2,
                 bf16* __restrict__ Ch, bf16* __restrict__ Cl,
                 const float* __restrict__ bias,
                 const float* __restrict__ Res, int ldr, long long sR1, long long sR2,
                 int K, int bdiv, float alpha)
{
    __shared__ float As[BK][BM + 4];
    __shared__ float Bs[BK][BN + 4];

    int bz = blockIdx.z;
    int ob = bz / bdiv;
    int ib = bz - ob * bdiv;
    A  += ob * sA1 + ib * sA2;
    Bm += ob * sB1 + ib * sB2;
    C  += ob * sC1 + ib * sC2;
    if (OUTSPLIT) { Ch += ob * sC1 + ib * sC2; Cl += ob * sC1 + ib * sC2; }
    if (Res) Res += ob * sR1 + ib * sR2;

    int bm = blockIdx.y * BM;
    int bn = blockIdx.x * BN;
    int tid = threadIdx.x;
    int tx = tid & 15, ty = tid >> 4;

    float acc[4][4] = {};
    float cmp[4][4] = {};

    for (int k0 = 0; k0 < K; k0 += BK) {
        #pragma unroll
        for (int i = 0; i < 4; i++) {
            int idx = tid + i * 256;
            int m  = idx >> 4;
            int kk = idx & 15;
            As[kk][m] = A[(long long)(bm + m) * lda + k0 + kk];
        }
        if (TRANSB) {
            #pragma unroll
            for (int i = 0; i < 4; i++) {
                int idx = tid + i * 256;
                int n  = idx >> 4;
                int kk = idx & 15;
                Bs[kk][n] = Bm[(long long)(bn + n) * ldb + k0 + kk];
            }
        } else {
            #pragma unroll
            for (int i = 0; i < 4; i++) {
                int idx = tid + i * 256;
                int kk = idx >> 6;
                int n  = idx & 63;
                Bs[kk][n] = Bm[(long long)(k0 + kk) * ldb + bn + n];
            }
        }
        __syncthreads();

        #pragma unroll
        for (int kk = 0; kk < BK; kk++) {
            float4 av = *(const float4*)&As[kk][ty * 4];
            float4 bv = *(const float4*)&Bs[kk][tx * 4];
            float a4[4] = {av.x, av.y, av.z, av.w};
            float b4[4] = {bv.x, bv.y, bv.z, bv.w};
            #pragma unroll
            for (int i = 0; i < 4; i++)
                #pragma unroll
                for (int j = 0; j < 4; j++) {
                    if (KAHAN) {
                        float y = __fmaf_rn(a4[i], b4[j], -cmp[i][j]);
                        float t = acc[i][j] + y;
                        cmp[i][j] = (t - acc[i][j]) - y;
                        acc[i][j] = t;
                    } else {
                        acc[i][j] = __fmaf_rn(a4[i], b4[j], acc[i][j]);
                    }
                }
        }
        __syncthreads();
    }

    #pragma unroll
    for (int i = 0; i < 4; i++) {
        int m = bm + ty * 4 + i;
        #pragma unroll
        for (int j = 0; j < 4; j++) {
            int n = bn + tx * 4 + j;
            float v = acc[i][j] * alpha;
            if (bias) v += bias[n];
            if (Res)  v += Res[(long long)m * ldr + n];
            if (ACT == 1) v = 0.5f * v * (1.0f + erff(v * 0.70710678118654752f));
            C[(long long)m * ldc + n] = v;
            if (OUTSPLIT) {
                bf16 h, l;
                split_bf16(v, h, l);
                Ch[(long long)m * ldc + n] = h;
                Cl[(long long)m * ldc + n] = l;
            }
        }
    }
}

// ---------------- transpose + split (weights) ----------------
__global__ __launch_bounds__(256)
void tsplit_kernel(const float* __restrict__ in, int K, int N,
                   bf16* __restrict__ oh, bf16* __restrict__ ol)
{
    __shared__ float tile[32][33];
    int nb = blockIdx.x * 32, kb = blockIdx.y * 32;
    int tx = threadIdx.x & 31, ty = threadIdx.x >> 5;
    #pragma unroll
    for (int i = 0; i < 32; i += 8)
        tile[ty + i][tx] = in[(long long)(kb + ty + i) * N + nb + tx];
    __syncthreads();
    #pragma unroll
    for (int i = 0; i < 32; i += 8) {
        int n = nb + ty + i, k = kb + tx;
        float v = tile[tx][ty + i];
        bf16 h, l;
        split_bf16(v, h, l);
        oh[(long long)n * K + k] = h;
        ol[(long long)n * K + k] = l;
    }
}

// ---------------- LayerNorm, fp64 stats, fp32 + split out ----------------
__global__ __launch_bounds__(256)
void ln_kernel(const float* __restrict__ x, const float* __restrict__ g,
               const float* __restrict__ b, float* __restrict__ y,
               bf16* __restrict__ yh, bf16* __restrict__ yl)
{
    long long row = blockIdx.x;
    const float* xr = x + row * DIM_;
    float* yr = y + row * DIM_;
    bf16* yhr = yh + row * DIM_;
    bf16* ylr = yl + row * DIM_;
    int t = threadIdx.x;
    float v0 = xr[t], v1 = xr[t + 256], v2 = xr[t + 512];
    double s = (double)v0 + (double)v1 + (double)v2;
    double q = (double)v0 * v0 + (double)v1 * v1 + (double)v2 * v2;
    __shared__ double sh[16];
    __shared__ float  par[2];
    #pragma unroll
    for (int o = 16; o > 0; o >>= 1) {
        s += __shfl_down_sync(~0u, s, o);
        q += __shfl_down_sync(~0u, q, o);
    }
    int wid = t >> 5, lane = t & 31;
    if (lane == 0) { sh[wid] = s; sh[wid + 8] = q; }
    __syncthreads();
    if (t == 0) {
        double ss = 0., qq = 0.;
        #pragma unroll
        for (int i = 0; i < 8; i++) { ss += sh[i]; qq += sh[i + 8]; }
        double mu = ss / DIM_;
        double var = qq / DIM_ - mu * mu;
        par[0] = (float)mu;
        par[1] = (float)(1.0 / sqrt(var + 1e-5));
    }
    __syncthreads();
    float mu = par[0], r = par[1];
    #pragma unroll
    for (int i = 0; i < 3; i++) {
        int c = t + i * 256;
        float vv = (i == 0 ? v0 : (i == 1 ? v1 : v2));
        float o = (vv - mu) * r * g[c] + b[c];
        yr[c] = o;
        bf16 h, l;
        split_bf16(o, h, l);
        yhr[c] = h;
        ylr[c] = l;
    }
}

// ---------------- row softmax over 320, row subset [tbase, tbase+tcnt) ----------------
// per-row math identical to previous rounds (fp64 path iff t_q < LT_)
__global__ __launch_bounds__(128)
void softmax_kernel(float* __restrict__ attn, int tbase, int tcnt)
{
    int blk = blockIdx.x;
    int bh = blk / tcnt;
    int t_q = tbase + (blk - bh * tcnt);
    long long row = (long long)bh * NTOK + t_q;
    float* p = attn + row * NTOK;
    int t = threadIdx.x;
    float v[3];
    float m = -1e30f;
    #pragma unroll
    for (int i = 0; i < 3; i++) {
        int c = t + i * 128;
        v[i] = (c < NTOK) ? p[c] : -1e30f;
        m = fmaxf(m, v[i]);
    }
    __shared__ float shm[4];
    __shared__ double shd[4];
    #pragma unroll
    for (int o = 16; o > 0; o >>= 1) m = fmaxf(m, __shfl_xor_sync(~0u, m, o));
    if ((t & 31) == 0) shm[t >> 5] = m;
    __syncthreads();
    m = fmaxf(fmaxf(shm[0], shm[1]), fmaxf(shm[2], shm[3]));
    __syncthreads();

    if (t_q < LT_) {
        double e[3];
        double s = 0.0;
        #pragma unroll
        for (int i = 0; i < 3; i++) {
            int c = t + i * 128;
            if (c < NTOK) { e[i] = exp((double)v[i] - (double)m); s += e[i]; }
            else e[i] = 0.0;
        }
        #pragma unroll
        for (int o = 16; o > 0; o >>= 1) s += __shfl_xor_sync(~0u, s, o);
        if ((t & 31) == 0) shd[t >> 5] = s;
        __syncthreads();
        s = shd[0] + shd[1] + shd[2] + shd[3];
        double inv = 1.0 / s;
        #pragma unroll
        for (int i = 0; i < 3; i++) {
            int c = t + i * 128;
            if (c < NTOK) p[c] = (float)(e[i] * inv);
        }
    } else {
        float e[3];
        float s = 0.0f;
        #pragma unroll
        for (int i = 0; i < 3; i++) {
            int c = t + i * 128;
            if (c < NTOK) { e[i] = __expf(v[i] - m); s += e[i]; }
            else e[i] = 0.0f;
        }
        #pragma unroll
        for (int o = 16; o > 0; o >>= 1) s += __shfl_xor_sync(~0u, s, o);
        if ((t & 31) == 0) shm[t >> 5] = s;
        __syncthreads();
        s = shm[0] + shm[1] + shm[2] + shm[3];
        float inv = 1.0f / s;
        #pragma unroll
        for (int i = 0; i < 3; i++) {
            int c = t + i * 128;
            if (c < NTOK) p[c] = e[i] * inv;
        }
    }
}

// ---------------- CE scores (fp64) ----------------
__global__ __launch_bounds__(256)
void ce_score_kernel(const float* __restrict__ attn, const unsigned char* __restrict__ maskp,
                     float* __restrict__ S)
{
    int b = blockIdx.x;
    int j = threadIdx.x;
    __shared__ float mf[LT_];
    __shared__ double cntsh;
    __shared__ int mode;
    if (j == 0) {
        const unsigned int* w = (const unsigned int*)maskp;
        bool all_int = true, all_flt = true;
        for (int i = 0; i < 512; i++) {
            unsigned int v = w[i];
            if (v != 0u && v != 1u) all_int = false;
            if (v != 0u && v != 0x3F800000u) all_flt = false;
        }
        mode = all_int ? 0 : (all_flt ? 1 : 2);
    }
    __syncthreads();
    if (j < LT_) {
        int mv;
        if (mode == 0)      mv = ((const int*)maskp)[b * LT_ + j] != 0;
        else if (mode == 1) mv = ((const float*)maskp)[b * LT_ + j] != 0.0f;
        else                mv = maskp[b * LT_ + j] != 0;
        mf[j] = mv ? 1.0f : 0.0f;
    }
    __syncthreads();
    if (j == 0) {
        double c = 0.;
        for (int t = 0; t < LT_; t++) c += (double)mf[t];
        cntsh = c;
    }
    __syncthreads();
    double cnt = cntsh;
    double stot = 0.0;
    const float* base = attn + (long long)b * H_ * NTOK * NTOK + LT_ + j;
    for (int h = 0; h < H_; h++) {
        const float* ph = base + (long long)h * NTOK * NTOK;
        double sh = 0.0;
        #pragma unroll 4
        for (int t = 0; t < LT_; t++)
            sh += (double)ph[(long long)t * NTOK] * (double)mf[t];
        stot += sh / cnt;
    }
    S[b * LS_ + j] = (float)(stot / H_);
}

// ---------------- bitonic sort ----------------
__global__ __launch_bounds__(256)
void sort_kernel(const float* __restrict__ S, int* __restrict__ order)
{
    int b = blockIdx.x, t = threadIdx.x;
    __shared__ float val[256];
    __shared__ int   idx[256];
    val[t] = S[b * LS_ + t];
    idx[t] = t;
    __syncthreads();
    for (int k = 2; k <= 256; k <<= 1) {
        for (int j = k >> 1; j > 0; j >>= 1) {
            int p = t ^ j;
            if (p > t) {
                bool desc = ((t & k) == 0);
                float va = val[t], vb = val[p];
                int ia = idx[t], ib = idx[p];
                bool aFirst = (va > vb) || (va == vb && ia < ib);
                if (aFirst != desc) {
                    val[t] = vb; val[p] = va;
                    idx[t] = ib; idx[p] = ia;
                }
            }
            __syncthreads();
        }
    }
    order[b * LS_ + t] = idx[t];
}

// ---------------- gather ----------------
__global__ __launch_bounds__(256)
void gather_kernel(const float* __restrict__ X1, const int* __restrict__ ord,
                   float* __restrict__ X2)
{
    int b = blockIdx.x, t = blockIdx.y;
    int src = (t < LT_) ? t : (LT_ + ord[b * LS_ + (t - LT_)]);
    const float* s = X1 + ((long long)b * NTOK + src) * DIM_;
    float* d = X2 + ((long long)b * N2 + t) * DIM_;
    int i = threadIdx.x;
    d[i] = s[i];
    d[i + 256] = s[i + 256];
    d[i + 512] = s[i + 512];
}

// ---------------- index outputs ----------------
__global__ __launch_bounds__(256)
void indices_kernel(const int* __restrict__ ord, const int* __restrict__ gsi,
                    float* __restrict__ outK, float* __restrict__ outR)
{
    int b = blockIdx.x, t = threadIdx.x;
    if (t < LK_) outK[b * LK_ + t] = (float)gsi[b * LS_ + ord[b * LS_ + t]];
    if (t < LR_) outR[b * LR_ + t] = (float)gsi[b * LS_ + ord[b * LS_ + LK_ + t]];
}

__global__ __launch_bounds__(256)
void git_kernel(const int* __restrict__ git, float* __restrict__ out)
{
    int i = blockIdx.x * 256 + threadIdx.x;
    if (i < B_ * LT_) out[i] = (float)git[i];
}

// ---------------- streams/events (created pre-main) ----------------
struct StreamPool {
    cudaStream_t f, m1, s0, s1;
    cudaEvent_t evFork, evLN0, evLN1, evK0, evK1,
                evSM64_0, evSM64_1, evSORT0, evSORT1,
                evSEnd0, evSEnd1, evEnd1;
    StreamPool() {
        cudaStreamCreateWithFlags(&f,  cudaStreamNonBlocking);
        cudaStreamCreateWithFlags(&m1, cudaStreamNonBlocking);
        cudaStreamCreateWithFlags(&s0, cudaStreamNonBlocking);
        cudaStreamCreateWithFlags(&s1, cudaStreamNonBlocking);
        cudaEvent_t* evs[12] = {&evFork, &evLN0, &evLN1, &evK0, &evK1,
                                &evSM64_0, &evSM64_1, &evSORT0, &evSORT1,
                                &evSEnd0, &evSEnd1, &evEnd1};
        for (int i = 0; i < 12; i++)
            cudaEventCreateWithFlags(evs[i], cudaEventDisableTiming);
    }
};
static StreamPool g_sp;

// ---------------- per-branch buffers ----------------
struct BranchBufs {
    float *XLN, *QKV, *Q64, *ATTN, *O, *X1, *S, *X2, *XLN2;
    int* ORD;
    bf16 *XLNh, *XLNl, *Oh, *Ol, *XLN2h, *XLN2l, *H1h, *H1l;
};
struct Weights {
    bf16 *WqkvTh, *WqkvTl, *WprojTh, *WprojTl, *W1Th, *W1Tl, *W2Th, *W2Tl;
};

static void get_branch_bufs(int br, BranchBufs& bu)
{
    char* p;
    cudaGetSymbolAddress((void**)&p, g_XLN);  bu.XLN  = (float*)p + (size_t)br * B_ * NTOK * DIM_;
    cudaGetSymbolAddress((void**)&p, g_QKV);  bu.QKV  = (float*)p + (size_t)br * B_ * NTOK * 3 * DIM_;
    cudaGetSymbolAddress((void**)&p, g_Q64);  bu.Q64  = (float*)p + (size_t)br * B_ * LT_ * DIM_;
    cudaGetSymbolAddress((void**)&p, g_ATTN); bu.ATTN = (float*)p + (size_t)br * B_ * H_ * NTOK * NTOK;
    cudaGetSymbolAddress((void**)&p, g_O);    bu.O    = (float*)p + (size_t)br * B_ * NTOK * DIM_;
    cudaGetSymbolAddress((void**)&p, g_X1);   bu.X1   = (float*)p + (size_t)br * B_ * NTOK * DIM_;
    cudaGetSymbolAddress((void**)&p, g_S);    bu.S    = (float*)p + (size_t)br * B_ * LS_;
    cudaGetSymbolAddress((void**)&p, g_ORD);  bu.ORD  = (int*)p   + (size_t)br * B_ * LS_;
    cudaGetSymbolAddress((void**)&p, g_X2);   bu.X2   = (float*)p + (size_t)br * B_ * N2 * DIM_;
    cudaGetSymbolAddress((void**)&p, g_XLN2); bu.XLN2 = (float*)p + (size_t)br * B_ * N2 * DIM_;
    cudaGetSymbolAddress((void**)&p, g_XLNh); bu.XLNh = (bf16*)p + (size_t)br * B_ * NTOK * DIM_;
    cudaGetSymbolAddress((void**)&p, g_XLNl); bu.XLNl = (bf16*)p + (size_t)br * B_ * NTOK * DIM_;
    cudaGetSymbolAddress((void**)&p, g_Oh);   bu.Oh   = (bf16*)p + (size_t)br * B_ * NTOK * DIM_;
    cudaGetSymbolAddress((void**)&p, g_Ol);   bu.Ol   = (bf16*)p + (size_t)br * B_ * NTOK * DIM_;
    cudaGetSymbolAddress((void**)&p, g_XLN2h); bu.XLN2h = (bf16*)p + (size_t)br * B_ * N2 * DIM_;
    cudaGetSymbolAddress((void**)&p, g_XLN2l); bu.XLN2l = (bf16*)p + (size_t)br * B_ * N2 * DIM_;
    cudaGetSymbolAddress((void**)&p, g_H1h);  bu.H1h  = (bf16*)p + (size_t)br * B_ * N2 * 4 * DIM_;
    cudaGetSymbolAddress((void**)&p, g_H1l);  bu.H1l  = (bf16*)p + (size_t)br * B_ * N2 * 4 * DIM_;
}

extern "C" void kernel_launch(void* const* d_in, const int* in_sizes, int n_in,
                              void* d_out, int out_size)
{
    const float* x_rgb  = (const float*)d_in[0];
    const float* x_dte  = (const float*)d_in[1];
    const int*   git    = (const int*)d_in[2];
    const int*   gsi_rgb = (const int*)d_in[3];
    const int*   gsi_dte = (const int*)d_in[4];
    const unsigned char* mask = (const unsigned char*)d_in[5];
    const float* g1    = (const float*)d_in[6];
    const float* b1    = (const float*)d_in[7];
    const float* Wqkv  = (const float*)d_in[8];
    const float* bqkv  = (const float*)d_in[9];
    const float* Wproj = (const float*)d_in[10];
    const float* bproj = (const float*)d_in[11];
    const float* g2    = (const float*)d_in[12];
    const float* b2    = (const float*)d_in[13];
    const float* W1    = (const float*)d_in[14];
    const float* bm1   = (const float*)d_in[15];
    const float* W2    = (const float*)d_in[16];
    const float* bm2   = (const float*)d_in[17];

    float* out = (float*)d_out;

    cudaFuncSetAttribute(tc_gemm2<0, false>, cudaFuncAttributeMaxDynamicSharedMemorySize, TC_SMEM_TOTAL);
    cudaFuncSetAttribute(tc_gemm2<1, true>,  cudaFuncAttributeMaxDynamicSharedMemorySize, TC_SMEM_TOTAL);

    Weights w;
    {
        char* p;
        cudaGetSymbolAddress((void**)&p, g_WqkvTh);  w.WqkvTh  = (bf16*)p;
        cudaGetSymbolAddress((void**)&p, g_WqkvTl);  w.WqkvTl  = (bf16*)p;
        cudaGetSymbolAddress((void**)&p, g_WprojTh); w.WprojTh = (bf16*)p;
        cudaGetSymbolAddress((void**)&p, g_WprojTl); w.WprojTl = (bf16*)p;
        cudaGetSymbolAddress((void**)&p, g_W1Th);    w.W1Th    = (bf16*)p;
        cudaGetSymbolAddress((void**)&p, g_W1Tl);    w.W1Tl    = (bf16*)p;
        cudaGetSymbolAddress((void**)&p, g_W2Th);    w.W2Th    = (bf16*)p;
        cudaGetSymbolAddress((void**)&p, g_W2Tl);    w.W2Tl    = (bf16*)p;
    }
    BranchBufs bu[2];
    get_branch_bufs(0, bu[0]);
    get_branch_bufs(1, bu[1]);

    const long long XSZ     = (long long)B_ * N2 * DIM_;
    const long long GIT_OFF = 2 * XSZ;
    const long long K0_OFF  = GIT_OFF + (long long)B_ * LT_;
    const long long K1_OFF  = K0_OFF + (long long)B_ * LK_;
    const long long R0_OFF  = K1_OFF + (long long)B_ * LK_;
    const long long R1_OFF  = R0_OFF + (long long)B_ * LR_;

    cudaStream_t m0 = (cudaStream_t)0;
    cudaStream_t mS[2] = {m0, g_sp.m1};
    cudaStream_t sS[2] = {g_sp.s0, g_sp.s1};
    cudaEvent_t  evLN[2]   = {g_sp.evLN0, g_sp.evLN1};
    cudaEvent_t  evK[2]    = {g_sp.evK0, g_sp.evK1};
    cudaEvent_t  evSM64[2] = {g_sp.evSM64_0, g_sp.evSM64_1};
    cudaEvent_t  evSORT[2] = {g_sp.evSORT0, g_sp.evSORT1};
    cudaEvent_t  evSEnd[2] = {g_sp.evSEnd0, g_sp.evSEnd1};
    const float* xIn[2]    = {x_rgb, x_dte};
    const int*   gsiIn[2]  = {gsi_rgb, gsi_dte};
    float* outX[2] = {out, out + XSZ};
    float* outK[2] = {out + K0_OFF, out + K1_OFF};
    float* outR[2] = {out + R0_OFF, out + R1_OFF};

    // shared prologue on origin stream
    git_kernel<<<(B_ * LT_ + 255) / 256, 256>>>(git, out + GIT_OFF);
    tsplit_kernel<<<dim3(3 * DIM_ / 32, DIM_ / 32), 256>>>(Wqkv, DIM_, 3 * DIM_, w.WqkvTh, w.WqkvTl);
    tsplit_kernel<<<dim3(DIM_ / 32, DIM_ / 32), 256>>>(Wproj, DIM_, DIM_, w.WprojTh, w.WprojTl);
    tsplit_kernel<<<dim3(4 * DIM_ / 32, DIM_ / 32), 256>>>(W1, DIM_, 4 * DIM_, w.W1Th, w.W1Tl);
    tsplit_kernel<<<dim3(DIM_ / 32, 4 * DIM_ / 32), 256>>>(W2, 4 * DIM_, DIM_, w.W2Th, w.W2Tl);

    cudaEventRecord(g_sp.evFork, m0);
    cudaStreamWaitEvent(g_sp.m1, g_sp.evFork, 0);

    // LN1 + merged tc q|v on each main stream
    for (int br = 0; br < 2; br++) {
        ln_kernel<<<B_ * NTOK, 256, 0, mS[br]>>>(xIn[br], g1, b1,
                                                 bu[br].XLN, bu[br].XLNh, bu[br].XLNl);
        cudaEventRecord(evLN[br], mS[br]);
        // merged q|v GEMM: N=1536 (n0>=768 -> v slab, +768 shifts)
        tc_gemm2<0, false><<<dim3(2 * DIM_ / 128, B_ * NTOK / 128), TC_THREADS, TC_SMEM_TOTAL, mS[br]>>>(
            bu[br].XLNh, bu[br].XLNl, DIM_, w.WqkvTh, w.WqkvTl, DIM_,
            bu[br].QKV, 3 * DIM_, nullptr, nullptr, bqkv, nullptr, 0, DIM_, 1);
    }

    // shared f stream: the two Kahan k GEMMs back-to-back
    for (int br = 0; br < 2; br++) {
        cudaStreamWaitEvent(g_sp.f, evLN[br], 0);
        gemm_kernel<false, 0, true, false><<<dim3(DIM_ / BN, B_ * NTOK / BM, 1), 256, 0, g_sp.f>>>(
            bu[br].XLN, DIM_, 0, 0,
            Wqkv + DIM_, 3 * DIM_, 0, 0,
            bu[br].QKV + DIM_, 3 * DIM_, 0, 0,
            nullptr, nullptr,
            bqkv + DIM_, nullptr, 0, 0, 0,
            DIM_, 1, 1.0f);
        cudaEventRecord(evK[br], g_sp.f);
    }

    for (int br = 0; br < 2; br++) {
        cudaStream_t m = mS[br];
        cudaStream_t s = sS[br];

        // ---- score stream: Kahan q64 -> Kahan logits<64 -> softmax64 -> CE -> sort -> indices
        cudaStreamWaitEvent(s, evK[br], 0);
        gemm_kernel<false, 0, true, false><<<dim3(DIM_ / BN, 1, B_), 256, 0, s>>>(
            bu[br].XLN, DIM_, 0, (long long)NTOK * DIM_,
            Wqkv, 3 * DIM_, 0, 0,
            bu[br].Q64, DIM_, 0, (long long)LT_ * DIM_,
            nullptr, nullptr,
            bqkv, nullptr, 0, 0, 0,
            DIM_, B_, 1.0f);
        gemm_kernel<true, 0, true, false><<<dim3(NTOK / BN, 1, B_ * H_), 256, 0, s>>>(
            bu[br].Q64,        DIM_,     (long long)LT_ * DIM_,       DH,
            bu[br].QKV + DIM_, 3 * DIM_, (long long)NTOK * 3 * DIM_,  DH,
            bu[br].ATTN, NTOK, (long long)H_ * NTOK * NTOK, (long long)NTOK * NTOK,
            nullptr, nullptr,
            nullptr, nullptr, 0, 0, 0,
            DH, H_, 0.125f);
        softmax_kernel<<<B_ * H_ * LT_, 128, 0, s>>>(bu[br].ATTN, 0, LT_);
        cudaEventRecord(evSM64[br], s);
        ce_score_kernel<<<B_, 256, 0, s>>>(bu[br].ATTN, mask, bu[br].S);
        sort_kernel<<<B_, 256, 0, s>>>(bu[br].S, bu[br].ORD);
        cudaEventRecord(evSORT[br], s);
        indices_kernel<<<B_, 256, 0, s>>>(bu[br].ORD, gsiIn[br], outK[br], outR[br]);
        cudaEventRecord(evSEnd[br], s);

        // ---- main stream: value path ----
        cudaStreamWaitEvent(m, evK[br], 0);
        // plain logits rows 64..319 (needs tc q [m order] + Kahan k [evK])
        gemm_kernel<true, 0, false, false><<<dim3(NTOK / BN, 4, B_ * H_), 256, 0, m>>>(
            bu[br].QKV + (long long)LT_ * 3 * DIM_, 3 * DIM_, (long long)NTOK * 3 * DIM_, DH,
            bu[br].QKV + DIM_,                      3 * DIM_, (long long)NTOK * 3 * DIM_, DH,
            bu[br].ATTN + (long long)LT_ * NTOK, NTOK, (long long)H_ * NTOK * NTOK, (long long)NTOK * NTOK,
            nullptr, nullptr,
            nullptr, nullptr, 0, 0, 0,
            DH, H_, 0.125f);
        softmax_kernel<<<B_ * H_ * LS_, 128, 0, m>>>(bu[br].ATTN, LT_, LS_);

        // P @ V needs softmax rows<64 too
        cudaStreamWaitEvent(m, evSM64[br], 0);
        gemm_kernel<false, 0, false, true><<<dim3(DH / BN, NTOK / BM, B_ * H_), 256, 0, m>>>(
            bu[br].ATTN, NTOK, (long long)H_ * NTOK * NTOK, (long long)NTOK * NTOK,
            bu[br].QKV + 2 * DIM_, 3 * DIM_, (long long)NTOK * 3 * DIM_, DH,
            bu[br].O, DIM_, (long long)NTOK * DIM_, DH,
            bu[br].Oh, bu[br].Ol,
            nullptr, nullptr, 0, 0, 0,
            NTOK, H_, 1.0f);

        // X1 = x + O @ Wproj + bproj (tc)
        tc_gemm2<0, false><<<dim3(DIM_ / 128, B_ * NTOK / 128), TC_THREADS, TC_SMEM_TOTAL, m>>>(
            bu[br].Oh, bu[br].Ol, DIM_, w.WprojTh, w.WprojTl, DIM_,
            bu[br].X1, DIM_, nullptr, nullptr, bproj, xIn[br], DIM_, DIM_, 0);

        // gather needs sort
        cudaStreamWaitEvent(m, evSORT[br], 0);
        gather_kernel<<<dim3(B_, N2), 256, 0, m>>>(bu[br].X1, bu[br].ORD, bu[br].X2);
        ln_kernel<<<B_ * N2, 256, 0, m>>>(bu[br].X2, g2, b2,
                                          bu[br].XLN2, bu[br].XLN2h, bu[br].XLN2l);
        tc_gemm2<1, true><<<dim3(4 * DIM_ / 128, B_ * N2 / 128), TC_THREADS, TC_SMEM_TOTAL, m>>>(
            bu[br].XLN2h, bu[br].XLN2l, DIM_, w.W1Th, w.W1Tl, DIM_,
            nullptr, 4 * DIM_, bu[br].H1h, bu[br].H1l, bm1, nullptr, 0, DIM_, 0);
        tc_gemm2<0, false><<<dim3(DIM_ / 128, B_ * N2 / 128), TC_THREADS, TC_SMEM_TOTAL, m>>>(
            bu[br].H1h, bu[br].H1l, 4 * DIM_, w.W2Th, w.W2Tl, 4 * DIM_,
            outX[br], DIM_, nullptr, nullptr, bm2, bu[br].X2, DIM_, 4 * DIM_, 0);
    }

    // join all side streams into origin
    cudaEventRecord(g_sp.evEnd1, g_sp.m1);
    cudaStreamWaitEvent(m0, g_sp.evEnd1, 0);
    cudaStreamWaitEvent(m0, g_sp.evSEnd0, 0);
    cudaStreamWaitEvent(m0, g_sp.evSEnd1, 0);
}

// round 13
// speedup vs baseline: 1.1891x; 1.0096x over previous
#include <cuda_runtime.h>
#include <cuda_bf16.h>
#include <math.h>
#include <stdint.h>

// ---------------- problem constants ----------------
#define B_    32
#define LT_   64
#define LS_   256
#define NTOK  320      // LT + LS
#define DIM_  768
#define H_    12
#define DH    64
#define LK_   180
#define LR_   76
#define N2    244      // LT + LK

#if defined(__CUDA_ARCH__) && defined(__CUDA_ARCH_FEAT_SM103_ALL)
#define HAS_TCGEN05 1
#else
#define HAS_TCGEN05 0
#endif

typedef __nv_bfloat16 bf16;
typedef unsigned long long u64;

// ---------------- scratch (per-branch duplicated) ----------------
__device__ float g_XLN [2][B_ * NTOK * DIM_];
__device__ float g_QKV [2][B_ * NTOK * 3 * DIM_];
__device__ float g_Q64 [2][B_ * LT_ * DIM_];
__device__ float g_ATTN[2][(size_t)B_ * H_ * NTOK * NTOK];
__device__ float g_O   [2][B_ * NTOK * DIM_];
__device__ float g_X1  [2][B_ * NTOK * DIM_];
__device__ float g_S   [2][B_ * LS_];
__device__ int   g_ORD [2][B_ * LS_];
__device__ float g_X2  [2][B_ * N2 * DIM_];
__device__ float g_XLN2[2][B_ * N2 * DIM_];

__device__ unsigned short g_XLNh [2][B_ * NTOK * DIM_];
__device__ unsigned short g_XLNl [2][B_ * NTOK * DIM_];
__device__ unsigned short g_Oh   [2][B_ * NTOK * DIM_];
__device__ unsigned short g_Ol   [2][B_ * NTOK * DIM_];
__device__ unsigned short g_XLN2h[2][B_ * N2 * DIM_];
__device__ unsigned short g_XLN2l[2][B_ * N2 * DIM_];
__device__ unsigned short g_H1h  [2][B_ * N2 * 4 * DIM_];
__device__ unsigned short g_H1l  [2][B_ * N2 * 4 * DIM_];

// shared weight splits
__device__ unsigned short g_WqkvTh[3 * DIM_ * DIM_];
__device__ unsigned short g_WqkvTl[3 * DIM_ * DIM_];
__device__ unsigned short g_WprojTh[DIM_ * DIM_];
__device__ unsigned short g_WprojTl[DIM_ * DIM_];
__device__ unsigned short g_W1Th [4 * DIM_ * DIM_];
__device__ unsigned short g_W1Tl [4 * DIM_ * DIM_];
__device__ unsigned short g_W2Th [4 * DIM_ * DIM_];
__device__ unsigned short g_W2Tl [4 * DIM_ * DIM_];

__device__ __forceinline__ void split_bf16(float v, bf16& h, bf16& l) {
    h = __float2bfloat16(v);
    l = __float2bfloat16(v - __bfloat162float(h));
}

// ---------------- packed f32x2 helpers (sm_100+ PTX) ----------------
#define PK_FMA2(d, a, b, c) \
    asm("fma.rn.f32x2 %0, %1, %2, %3;" : "=l"(d) : "l"(a), "l"(b), "l"(c))
#define PK_ADD2(d, a, b) \
    asm("add.rn.f32x2 %0, %1, %2;" : "=l"(d) : "l"(a), "l"(b))
#define PK_SUB2(d, a, b) \
    asm("sub.rn.f32x2 %0, %1, %2;" : "=l"(d) : "l"(a), "l"(b))
#define PK_PACK(d, lo, hi) \
    asm("mov.b64 %0, {%1, %2};" : "=l"(d) : "f"(lo), "f"(hi))
#define PK_UNPACK(lo, hi, s) \
    asm("mov.b64 {%0, %1}, %2;" : "=f"(lo), "=f"(hi) : "l"(s))

// =====================================================================
// tcgen05 helpers (sm_103a pass only)
// =====================================================================
#if HAS_TCGEN05
__device__ __forceinline__ uint32_t elect_one_pred() {
    uint32_t pred;
    asm volatile(
        "{\n\t.reg .pred p;\n\telect.sync _|p, 0xFFFFFFFF;\n\tselp.b32 %0, 1, 0, p;\n\t}"
        : "=r"(pred));
    return pred;
}
__device__ __forceinline__ uint32_t smem_to_u32(const void* smem_ptr) {
    uint32_t addr;
    asm("{ .reg .u64 tmp; cvta.to.shared.u64 tmp, %1; cvt.u32.u64 %0, tmp; }"
        : "=r"(addr) : "l"(smem_ptr));
    return addr;
}
__device__ __forceinline__ void cp16(uint32_t s, const void* g) {
    asm volatile("cp.async.cg.shared.global [%0], [%1], 16;" :: "r"(s), "l"(g) : "memory");
}
#define CP_COMMIT() asm volatile("cp.async.commit_group;" ::: "memory")
#define CP_WAIT(n)  asm volatile("cp.async.wait_group %0;" :: "n"(n) : "memory")

#define TCGEN05_ALLOC(a, n) \
    asm volatile("tcgen05.alloc.cta_group::1.sync.aligned.shared::cta.b32 [%0], %1;" \
        :: "r"((uint32_t)(a)), "r"((uint32_t)(n)) : "memory")
#define TCGEN05_DEALLOC(t, n) \
    asm volatile("tcgen05.dealloc.cta_group::1.sync.aligned.b32 %0, %1;" \
        :: "r"(t), "r"((uint32_t)(n)))
#define TCGEN05_RELINQUISH_ALLOC_PERMIT() \
    asm volatile("tcgen05.relinquish_alloc_permit.cta_group::1.sync.aligned;")
#define TCGEN05_COMMIT(m) \
    asm volatile("tcgen05.commit.cta_group::1.mbarrier::arrive::one.shared::cluster.b64 [%0];" \
        :: "r"((uint32_t)(m)) : "memory")
#define TCGEN05_WAIT_LD()  asm volatile("tcgen05.wait::ld.sync.aligned;" ::: "memory")
#define TCGEN05_FENCE_BEFORE() asm volatile("tcgen05.fence::before_thread_sync;" ::: "memory")
#define TCGEN05_FENCE_AFTER()  asm volatile("tcgen05.fence::after_thread_sync;" ::: "memory")
#define FENCE_PROXY_ASYNC_SHARED_CTA() asm volatile("fence.proxy.async.shared::cta;" ::: "memory")
#define MBARRIER_INIT(m, c) \
    asm volatile("mbarrier.init.shared.b64 [%0], %1;" :: "r"((uint32_t)(m)), "r"((uint32_t)(c)) : "memory")
#define MBARRIER_INVAL(m) \
    asm volatile("mbarrier.inval.shared.b64 [%0];" :: "r"((uint32_t)(m)) : "memory")

#define MBARRIER_WAIT_PARITY(mb, pp) do { \
    uint32_t _mbar = (uint32_t)(mb); \
    uint32_t _parity = (uint32_t)(pp); \
    uint32_t _done; \
    asm volatile( \
        "{\n\t.reg .pred p;\n\t" \
        "mbarrier.try_wait.parity.acquire.cta.shared::cta.b64 p, [%1], %2;\n\t" \
        "selp.b32 %0, 1, 0, p;\n\t}" \
        : "=r"(_done) : "r"(_mbar), "r"(_parity) : "memory"); \
    if (!_done) { \
        asm volatile( \
            "{\n\t.reg .pred P1;\n\t" \
            "WAIT_LOOP_%=:\n\t" \
            "mbarrier.try_wait.parity.acquire.cta.shared::cta.b64 P1, [%0], %1, 0x989680;\n\t" \
            "@P1 bra.uni WAIT_DONE_%=;\n\t" \
            "bra.uni WAIT_LOOP_%=;\n\t" \
            "WAIT_DONE_%=:\n\t}" \
            :: "r"(_mbar), "r"(_parity) : "memory"); \
    } \
} while(0)

#define TCGEN05_LD_32X32B_X32(r, tmem_addr) \
    asm volatile( \
        "tcgen05.ld.sync.aligned.32x32b.x32.b32 " \
        "{%0, %1, %2, %3, %4, %5, %6, %7, " \
        " %8, %9, %10, %11, %12, %13, %14, %15, " \
        " %16, %17, %18, %19, %20, %21, %22, %23, " \
        " %24, %25, %26, %27, %28, %29, %30, %31}, [%32];" \
        : "=r"((r)[0]),  "=r"((r)[1]),  "=r"((r)[2]),  "=r"((r)[3]), \
          "=r"((r)[4]),  "=r"((r)[5]),  "=r"((r)[6]),  "=r"((r)[7]), \
          "=r"((r)[8]),  "=r"((r)[9]),  "=r"((r)[10]), "=r"((r)[11]), \
          "=r"((r)[12]), "=r"((r)[13]), "=r"((r)[14]), "=r"((r)[15]), \
          "=r"((r)[16]), "=r"((r)[17]), "=r"((r)[18]), "=r"((r)[19]), \
          "=r"((r)[20]), "=r"((r)[21]), "=r"((r)[22]), "=r"((r)[23]), \
          "=r"((r)[24]), "=r"((r)[25]), "=r"((r)[26]), "=r"((r)[27]), \
          "=r"((r)[28]), "=r"((r)[29]), "=r"((r)[30]), "=r"((r)[31]) \
        : "r"(tmem_addr))

static constexpr uint64_t SMEM_DESC_BASE_SW128 =
    (uint64_t(2)  << 61) | (uint64_t(1) << 46) | (uint64_t(64) << 32) | (uint64_t(1) << 16);
#define MAKE_SMEM_DESC(base_addr) \
    (SMEM_DESC_BASE_SW128 | ((uint64_t)((base_addr) >> 4) & 0x3FFF))

__device__ __forceinline__ void tc_mma_f16_ss(uint32_t d, uint64_t a, uint64_t b,
                                              uint32_t idesc, uint32_t en)
{
    asm volatile(
        "{\n\t.reg .pred p;\n\tsetp.ne.u32 p, %5, 0;\n\t"
        "tcgen05.mma.cta_group::1.kind::f16 [%0], %1, %2, %3, {%4, %4, %4, %4}, p;\n\t}"
        :: "r"(d), "l"(a), "l"(b), "r"(idesc), "r"(0u), "r"(en) : "memory");
}
#endif // HAS_TCGEN05

// =====================================================================
// tc_gemm2: cp.async pipelined split-bf16 tc GEMM (unchanged from r12).
// =====================================================================
#define TC_THREADS 256
#define TC_SMEM_TOTAL (1024 + 2 * 4 * 16384)   // 132096 bytes
#define TC_IDESC 0x8200490u

template<int ACT, bool OUTSPLIT>
__global__ __launch_bounds__(TC_THREADS)
void tc_gemm2(const bf16* __restrict__ Ah, const bf16* __restrict__ Al, int lda,
              const bf16* __restrict__ Bh, const bf16* __restrict__ Bl, int ldb,
              float* __restrict__ C, int ldc,
              bf16* __restrict__ Ch, bf16* __restrict__ Cl,
              const float* __restrict__ bias,
              const float* __restrict__ Res, int ldr,
              int K, int qv)
{
    const int n0_raw = blockIdx.x * 128;
    int cshift = (qv && n0_raw >= DIM_) ? DIM_ : 0;
    Bh += (long long)cshift * ldb;
    Bl += (long long)cshift * ldb;
#if HAS_TCGEN05
    extern __shared__ char smem[];
    const uint32_t sb = smem_to_u32(smem);
    const int tid = threadIdx.x;
    const int wid = tid >> 5;
    const int lid = tid & 31;
    const int m0 = blockIdx.y * 128;
    const int n0 = n0_raw;

    if (wid == 0) {
        TCGEN05_ALLOC(sb + 0, 128);
        TCGEN05_RELINQUISH_ALLOC_PERMIT();
    }
    if (tid == 0) { MBARRIER_INIT(sb + 16, 1); MBARRIER_INIT(sb + 24, 1); }
    __syncthreads();
    uint32_t tmem;
    asm volatile("ld.shared.b32 %0, [%1];" : "=r"(tmem) : "r"(sb));

    const int nk = K >> 6;
    const int lr  = tid >> 3;
    const int lcq = (tid & 7) * 8;

    #define TC_ISSUE_CHUNK(ktv)  do {                                              \
        const int _buf = (ktv) & 1;                                                \
        uint32_t _db = sb + 1024 + _buf * 65536;                                   \
        const bf16* _Agh = Ah + (long long)m0 * lda + (ktv) * 64;                  \
        const bf16* _Agl = Al + (long long)m0 * lda + (ktv) * 64;                  \
        const bf16* _Bgh = Bh + (long long)n0 * ldb + (ktv) * 64;                  \
        const bf16* _Bgl = Bl + (long long)n0 * ldb + (ktv) * 64;                  \
        _Pragma("unroll")                                                          \
        for (int _i = 0; _i < 4; _i++) {                                           \
            int _r = lr + _i * 32;                                                 \
            uint32_t _bo = _r * 128 + lcq * 2;                                     \
            uint32_t _so = _bo ^ ((_bo >> 3) & 0x70);                              \
            cp16(_db + _so,          _Agh + (long long)_r * lda + lcq);            \
            cp16(_db + 16384 + _so,  _Agl + (long long)_r * lda + lcq);            \
            cp16(_db + 32768 + _so,  _Bgh + (long long)_r * ldb + lcq);            \
            cp16(_db + 49152 + _so,  _Bgl + (long long)_r * ldb + lcq);            \
        }                                                                          \
        CP_COMMIT();                                                               \
    } while (0)

    TC_ISSUE_CHUNK(0);
    for (int kt = 0; kt < nk; kt++) {
        if (kt + 1 < nk) {
            if (kt >= 1)
                MBARRIER_WAIT_PARITY(sb + 16 + 8 * ((kt - 1) & 1), ((kt - 1) >> 1) & 1);
            TC_ISSUE_CHUNK(kt + 1);
            CP_WAIT(1);
        } else {
            CP_WAIT(0);
        }
        FENCE_PROXY_ASYNC_SHARED_CTA();
        __syncthreads();

        if (wid == 0) {
            if (elect_one_pred()) {
                uint32_t ab = sb + 1024 + (kt & 1) * 65536;
                uint64_t dAh = MAKE_SMEM_DESC(ab);
                uint64_t dAl = MAKE_SMEM_DESC(ab + 16384);
                uint64_t dBh = MAKE_SMEM_DESC(ab + 32768);
                uint64_t dBl = MAKE_SMEM_DESC(ab + 49152);
                #pragma unroll
                for (int k = 0; k < 4; k++)
                    tc_mma_f16_ss(tmem, dAh + k * 2, dBh + k * 2, TC_IDESC,
                                  (kt == 0 && k == 0) ? 0u : 1u);
                #pragma unroll
                for (int k = 0; k < 4; k++)
                    tc_mma_f16_ss(tmem, dAh + k * 2, dBl + k * 2, TC_IDESC, 1u);
                #pragma unroll
                for (int k = 0; k < 4; k++)
                    tc_mma_f16_ss(tmem, dAl + k * 2, dBh + k * 2, TC_IDESC, 1u);
                TCGEN05_COMMIT(sb + 16 + 8 * (kt & 1));
            }
        }
    }
    #undef TC_ISSUE_CHUNK

    if (nk >= 2)
        MBARRIER_WAIT_PARITY(sb + 16 + 8 * ((nk - 2) & 1), ((nk - 2) >> 1) & 1);
    MBARRIER_WAIT_PARITY(sb + 16 + 8 * ((nk - 1) & 1), ((nk - 1) >> 1) & 1);
    TCGEN05_FENCE_AFTER();

    if (wid < 4) {
        int m = m0 + wid * 32 + lid;
        float* Crow = C ? (C + (long long)m * ldc + n0 + cshift) : (float*)0;
        bf16* Chrow = OUTSPLIT ? (Ch + (long long)m * ldc + n0) : (bf16*)0;
        bf16* Clrow = OUTSPLIT ? (Cl + (long long)m * ldc + n0) : (bf16*)0;
        const float* Rrow = Res ? (Res + (long long)m * ldr + n0) : (const float*)0;
        #pragma unroll
        for (int cb = 0; cb < 128; cb += 32) {
            uint32_t d[32];
            TCGEN05_LD_32X32B_X32(d, tmem + cb);
            TCGEN05_WAIT_LD();
            float vout[32];
            #pragma unroll
            for (int j = 0; j < 32; j++) {
                float v = __uint_as_float(d[j]);
                if (bias) v += bias[n0 + cshift + cb + j];
                if (Rrow) v += Rrow[cb + j];
                if (ACT == 1) v = 0.5f * v * (1.0f + erff(v * 0.70710678118654752f));
                vout[j] = v;
            }
            if (Crow) {
                #pragma unroll
                for (int q = 0; q < 32; q += 4)
                    *(float4*)&Crow[cb + q] = *(float4*)&vout[q];
            }
            if (OUTSPLIT) {
                #pragma unroll
                for (int q = 0; q < 32; q += 2) {
                    bf16 h0, l0, h1, l1;
                    split_bf16(vout[q], h0, l0);
                    split_bf16(vout[q + 1], h1, l1);
                    unsigned int hw = (unsigned int)__bfloat16_as_ushort(h0) |
                                      ((unsigned int)__bfloat16_as_ushort(h1) << 16);
                    unsigned int lw = (unsigned int)__bfloat16_as_ushort(l0) |
                                      ((unsigned int)__bfloat16_as_ushort(l1) << 16);
                    *(unsigned int*)&Chrow[cb + q] = hw;
                    *(unsigned int*)&Clrow[cb + q] = lw;
                }
            }
        }
        TCGEN05_FENCE_BEFORE();
    }
    __syncthreads();
    if (tid == 0) { MBARRIER_INVAL(sb + 16); MBARRIER_INVAL(sb + 24); }
    __syncthreads();
    if (wid == 0) TCGEN05_DEALLOC(tmem, 128);
#else
    // fp32 fallback (never runs on GB300)
    const int tid = threadIdx.x;
    const int m0 = blockIdx.y * 128;
    const int n0 = n0_raw;
    for (int e = tid; e < 128 * 128; e += TC_THREADS) {
        int mi = e >> 7, ni = e & 127;
        int m = m0 + mi, n = n0 + ni;
        float s = 0.f;
        for (int k = 0; k < K; k++)
            s += (__bfloat162float(Ah[(long long)m * lda + k]) + __bfloat162float(Al[(long long)m * lda + k])) *
                 (__bfloat162float(Bh[(long long)n * ldb + k]) + __bfloat162float(Bl[(long long)n * ldb + k]));
        if (bias) s += bias[n + cshift];
        if (Res)  s += Res[(long long)m * ldr + n];
        if (ACT == 1) s = 0.5f * s * (1.0f + erff(s * 0.70710678118654752f));
        if (C) C[(long long)m * ldc + n + cshift] = s;
        if (OUTSPLIT) {
            bf16 h, l; split_bf16(s, h, l);
            Ch[(long long)m * ldc + n] = h;
            Cl[(long long)m * ldc + n] = l;
        }
    }
#endif
}

// ================= 64x64 GEMM (Kahan-capable, packed f32x2) =================
#define BM 64
#define BN 64
#define BK 16

template<bool TRANSB, int ACT, bool KAHAN, bool OUTSPLIT>
__global__ __launch_bounds__(256)
void gemm_kernel(const float* __restrict__ A, int lda, long long sA1, long long sA2,
                 const float* __restrict__ Bm, int ldb, long long sB1, long long sB2,
                 float* __restrict__ C, int ldc, long long sC1, long long sC2,
                 bf16* __restrict__ Ch, bf16* __restrict__ Cl,
                 const float* __restrict__ bias,
                 const float* __restrict__ Res, int ldr, long long sR1, long long sR2,
                 int K, int bdiv, float alpha)
{
    __shared__ float As[BK][BM + 4];
    __shared__ float Bs[BK][BN + 4];

    int bz = blockIdx.z;
    int ob = bz / bdiv;
    int ib = bz - ob * bdiv;
    A  += ob * sA1 + ib * sA2;
    Bm += ob * sB1 + ib * sB2;
    C  += ob * sC1 + ib * sC2;
    if (OUTSPLIT) { Ch += ob * sC1 + ib * sC2; Cl += ob * sC1 + ib * sC2; }
    if (Res) Res += ob * sR1 + ib * sR2;

    int bm = blockIdx.y * BM;
    int bn = blockIdx.x * BN;
    int tid = threadIdx.x;
    int tx = tid & 15, ty = tid >> 4;

    // packed accumulators: acc2[i][j2] holds cols (tx*4 + 2*j2, +1)
    u64 acc2[4][2] = {};
    u64 ncmp2[4][2] = {};   // negated Kahan compensation

    for (int k0 = 0; k0 < K; k0 += BK) {
        #pragma unroll
        for (int i = 0; i < 4; i++) {
            int idx = tid + i * 256;
            int m  = idx >> 4;
            int kk = idx & 15;
            As[kk][m] = A[(long long)(bm + m) * lda + k0 + kk];
        }
        if (TRANSB) {
            #pragma unroll
            for (int i = 0; i < 4; i++) {
                int idx = tid + i * 256;
                int n  = idx >> 4;
                int kk = idx & 15;
                Bs[kk][n] = Bm[(long long)(bn + n) * ldb + k0 + kk];
            }
        } else {
            #pragma unroll
            for (int i = 0; i < 4; i++) {
                int idx = tid + i * 256;
                int kk = idx >> 6;
                int n  = idx & 63;
                Bs[kk][n] = Bm[(long long)(k0 + kk) * ldb + bn + n];
            }
        }
        __syncthreads();

        #pragma unroll
        for (int kk = 0; kk < BK; kk++) {
            float4 av = *(const float4*)&As[kk][ty * 4];
            float a4[4] = {av.x, av.y, av.z, av.w};
            // b pairs packed straight from the 16B-aligned smem row
            const u64* bp = (const u64*)&Bs[kk][tx * 4];
            u64 b2[2] = {bp[0], bp[1]};
            #pragma unroll
            for (int i = 0; i < 4; i++) {
                u64 a2;
                PK_PACK(a2, a4[i], a4[i]);
                #pragma unroll
                for (int j2 = 0; j2 < 2; j2++) {
                    if (KAHAN) {
                        // bit-identical two-lane Kahan with negated compensation:
                        // y = fma(a,b,ncmp); t = acc+y; d = t-acc; ncmp = y-d; acc = t
                        u64 y, t, d;
                        PK_FMA2(y, a2, b2[j2], ncmp2[i][j2]);
                        PK_ADD2(t, acc2[i][j2], y);
                        PK_SUB2(d, t, acc2[i][j2]);
                        PK_SUB2(ncmp2[i][j2], y, d);
                        acc2[i][j2] = t;
                    } else {
                        PK_FMA2(acc2[i][j2], a2, b2[j2], acc2[i][j2]);
                    }
                }
            }
        }
        __syncthreads();
    }

    #pragma unroll
    for (int i = 0; i < 4; i++) {
        int m = bm + ty * 4 + i;
        float accs[4];
        PK_UNPACK(accs[0], accs[1], acc2[i][0]);
        PK_UNPACK(accs[2], accs[3], acc2[i][1]);
        #pragma unroll
        for (int j = 0; j < 4; j++) {
            int n = bn + tx * 4 + j;
            float v = accs[j] * alpha;
            if (bias) v += bias[n];
            if (Res)  v += Res[(long long)m * ldr + n];
            if (ACT == 1) v = 0.5f * v * (1.0f + erff(v * 0.70710678118654752f));
            C[(long long)m * ldc + n] = v;
            if (OUTSPLIT) {
                bf16 h, l;
                split_bf16(v, h, l);
                Ch[(long long)m * ldc + n] = h;
                Cl[(long long)m * ldc + n] = l;
            }
        }
    }
}

// ---------------- transpose + split (weights) ----------------
__global__ __launch_bounds__(256)
void tsplit_kernel(const float* __restrict__ in, int K, int N,
                   bf16* __restrict__ oh, bf16* __restrict__ ol)
{
    __shared__ float tile[32][33];
    int nb = blockIdx.x * 32, kb = blockIdx.y * 32;
    int tx = threadIdx.x & 31, ty = threadIdx.x >> 5;
    #pragma unroll
    for (int i = 0; i < 32; i += 8)
        tile[ty + i][tx] = in[(long long)(kb + ty + i) * N + nb + tx];
    __syncthreads();
    #pragma unroll
    for (int i = 0; i < 32; i += 8) {
        int n = nb + ty + i, k = kb + tx;
        float v = tile[tx][ty + i];
        bf16 h, l;
        split_bf16(v, h, l);
        oh[(long long)n * K + k] = h;
        ol[(long long)n * K + k] = l;
    }
}

// ---------------- LayerNorm, fp64 stats, fp32 + split out ----------------
__global__ __launch_bounds__(256)
void ln_kernel(const float* __restrict__ x, const float* __restrict__ g,
               const float* __restrict__ b, float* __restrict__ y,
               bf16* __restrict__ yh, bf16* __restrict__ yl)
{
    long long row = blockIdx.x;
    const float* xr = x + row * DIM_;
    float* yr = y + row * DIM_;
    bf16* yhr = yh + row * DIM_;
    bf16* ylr = yl + row * DIM_;
    int t = threadIdx.x;
    float v0 = xr[t], v1 = xr[t + 256], v2 = xr[t + 512];
    double s = (double)v0 + (double)v1 + (double)v2;
    double q = (double)v0 * v0 + (double)v1 * v1 + (double)v2 * v2;
    __shared__ double sh[16];
    __shared__ float  par[2];
    #pragma unroll
    for (int o = 16; o > 0; o >>= 1) {
        s += __shfl_down_sync(~0u, s, o);
        q += __shfl_down_sync(~0u, q, o);
    }
    int wid = t >> 5, lane = t & 31;
    if (lane == 0) { sh[wid] = s; sh[wid + 8] = q; }
    __syncthreads();
    if (t == 0) {
        double ss = 0., qq = 0.;
        #pragma unroll
        for (int i = 0; i < 8; i++) { ss += sh[i]; qq += sh[i + 8]; }
        double mu = ss / DIM_;
        double var = qq / DIM_ - mu * mu;
        par[0] = (float)mu;
        par[1] = (float)(1.0 / sqrt(var + 1e-5));
    }
    __syncthreads();
    float mu = par[0], r = par[1];
    #pragma unroll
    for (int i = 0; i < 3; i++) {
        int c = t + i * 256;
        float vv = (i == 0 ? v0 : (i == 1 ? v1 : v2));
        float o = (vv - mu) * r * g[c] + b[c];
        yr[c] = o;
        bf16 h, l;
        split_bf16(o, h, l);
        yhr[c] = h;
        ylr[c] = l;
    }
}

// ---------------- row softmax over 320, row subset [tbase, tbase+tcnt) ----------------
__global__ __launch_bounds__(128)
void softmax_kernel(float* __restrict__ attn, int tbase, int tcnt)
{
    int blk = blockIdx.x;
    int bh = blk / tcnt;
    int t_q = tbase + (blk - bh * tcnt);
    long long row = (long long)bh * NTOK + t_q;
    float* p = attn + row * NTOK;
    int t = threadIdx.x;
    float v[3];
    float m = -1e30f;
    #pragma unroll
    for (int i = 0; i < 3; i++) {
        int c = t + i * 128;
        v[i] = (c < NTOK) ? p[c] : -1e30f;
        m = fmaxf(m, v[i]);
    }
    __shared__ float shm[4];
    __shared__ double shd[4];
    #pragma unroll
    for (int o = 16; o > 0; o >>= 1) m = fmaxf(m, __shfl_xor_sync(~0u, m, o));
    if ((t & 31) == 0) shm[t >> 5] = m;
    __syncthreads();
    m = fmaxf(fmaxf(shm[0], shm[1]), fmaxf(shm[2], shm[3]));
    __syncthreads();

    if (t_q < LT_) {
        double e[3];
        double s = 0.0;
        #pragma unroll
        for (int i = 0; i < 3; i++) {
            int c = t + i * 128;
            if (c < NTOK) { e[i] = exp((double)v[i] - (double)m); s += e[i]; }
            else e[i] = 0.0;
        }
        #pragma unroll
        for (int o = 16; o > 0; o >>= 1) s += __shfl_xor_sync(~0u, s, o);
        if ((t & 31) == 0) shd[t >> 5] = s;
        __syncthreads();
        s = shd[0] + shd[1] + shd[2] + shd[3];
        double inv = 1.0 / s;
        #pragma unroll
        for (int i = 0; i < 3; i++) {
            int c = t + i * 128;
            if (c < NTOK) p[c] = (float)(e[i] * inv);
        }
    } else {
        float e[3];
        float s = 0.0f;
        #pragma unroll
        for (int i = 0; i < 3; i++) {
            int c = t + i * 128;
            if (c < NTOK) { e[i] = __expf(v[i] - m); s += e[i]; }
            else e[i] = 0.0f;
        }
        #pragma unroll
        for (int o = 16; o > 0; o >>= 1) s += __shfl_xor_sync(~0u, s, o);
        if ((t & 31) == 0) shm[t >> 5] = s;
        __syncthreads();
        s = shm[0] + shm[1] + shm[2] + shm[3];
        float inv = 1.0f / s;
        #pragma unroll
        for (int i = 0; i < 3; i++) {
            int c = t + i * 128;
            if (c < NTOK) p[c] = e[i] * inv;
        }
    }
}

// ---------------- CE scores (fp64) ----------------
__global__ __launch_bounds__(256)
void ce_score_kernel(const float* __restrict__ attn, const unsigned char* __restrict__ maskp,
                     float* __restrict__ S)
{
    int b = blockIdx.x;
    int j = threadIdx.x;
    __shared__ float mf[LT_];
    __shared__ double cntsh;
    __shared__ int mode;
    if (j == 0) {
        const unsigned int* w = (const unsigned int*)maskp;
        bool all_int = true, all_flt = true;
        for (int i = 0; i < 512; i++) {
            unsigned int v = w[i];
            if (v != 0u && v != 1u) all_int = false;
            if (v != 0u && v != 0x3F800000u) all_flt = false;
        }
        mode = all_int ? 0 : (all_flt ? 1 : 2);
    }
    __syncthreads();
    if (j < LT_) {
        int mv;
        if (mode == 0)      mv = ((const int*)maskp)[b * LT_ + j] != 0;
        else if (mode == 1) mv = ((const float*)maskp)[b * LT_ + j] != 0.0f;
        else                mv = maskp[b * LT_ + j] != 0;
        mf[j] = mv ? 1.0f : 0.0f;
    }
    __syncthreads();
    if (j == 0) {
        double c = 0.;
        for (int t = 0; t < LT_; t++) c += (double)mf[t];
        cntsh = c;
    }
    __syncthreads();
    double cnt = cntsh;
    double stot = 0.0;
    const float* base = attn + (long long)b * H_ * NTOK * NTOK + LT_ + j;
    for (int h = 0; h < H_; h++) {
        const float* ph = base + (long long)h * NTOK * NTOK;
        double sh = 0.0;
        #pragma unroll 4
        for (int t = 0; t < LT_; t++)
            sh += (double)ph[(long long)t * NTOK] * (double)mf[t];
        stot += sh / cnt;
    }
    S[b * LS_ + j] = (float)(stot / H_);
}

// ---------------- bitonic sort ----------------
__global__ __launch_bounds__(256)
void sort_kernel(const float* __restrict__ S, int* __restrict__ order)
{
    int b = blockIdx.x, t = threadIdx.x;
    __shared__ float val[256];
    __shared__ int   idx[256];
    val[t] = S[b * LS_ + t];
    idx[t] = t;
    __syncthreads();
    for (int k = 2; k <= 256; k <<= 1) {
        for (int j = k >> 1; j > 0; j >>= 1) {
            int p = t ^ j;
            if (p > t) {
                bool desc = ((t & k) == 0);
                float va = val[t], vb = val[p];
                int ia = idx[t], ib = idx[p];
                bool aFirst = (va > vb) || (va == vb && ia < ib);
                if (aFirst != desc) {
                    val[t] = vb; val[p] = va;
                    idx[t] = ib; idx[p] = ia;
                }
            }
            __syncthreads();
        }
    }
    order[b * LS_ + t] = idx[t];
}

// ---------------- gather ----------------
__global__ __launch_bounds__(256)
void gather_kernel(const float* __restrict__ X1, const int* __restrict__ ord,
                   float* __restrict__ X2)
{
    int b = blockIdx.x, t = blockIdx.y;
    int src = (t < LT_) ? t : (LT_ + ord[b * LS_ + (t - LT_)]);
    const float* s = X1 + ((long long)b * NTOK + src) * DIM_;
    float* d = X2 + ((long long)b * N2 + t) * DIM_;
    int i = threadIdx.x;
    d[i] = s[i];
    d[i + 256] = s[i + 256];
    d[i + 512] = s[i + 512];
}

// ---------------- index outputs ----------------
__global__ __launch_bounds__(256)
void indices_kernel(const int* __restrict__ ord, const int* __restrict__ gsi,
                    float* __restrict__ outK, float* __restrict__ outR)
{
    int b = blockIdx.x, t = threadIdx.x;
    if (t < LK_) outK[b * LK_ + t] = (float)gsi[b * LS_ + ord[b * LS_ + t]];
    if (t < LR_) outR[b * LR_ + t] = (float)gsi[b * LS_ + ord[b * LS_ + LK_ + t]];
}

__global__ __launch_bounds__(256)
void git_kernel(const int* __restrict__ git, float* __restrict__ out)
{
    int i = blockIdx.x * 256 + threadIdx.x;
    if (i < B_ * LT_) out[i] = (float)git[i];
}

// ---------------- streams/events (created pre-main) ----------------
struct StreamPool {
    cudaStream_t f, m1, s0, s1;
    cudaEvent_t evFork, evLN0, evLN1, evK0, evK1,
                evSM64_0, evSM64_1, evSORT0, evSORT1,
                evSEnd0, evSEnd1, evEnd1;
    StreamPool() {
        cudaStreamCreateWithFlags(&f,  cudaStreamNonBlocking);
        cudaStreamCreateWithFlags(&m1, cudaStreamNonBlocking);
        cudaStreamCreateWithFlags(&s0, cudaStreamNonBlocking);
        cudaStreamCreateWithFlags(&s1, cudaStreamNonBlocking);
        cudaEvent_t* evs[12] = {&evFork, &evLN0, &evLN1, &evK0, &evK1,
                                &evSM64_0, &evSM64_1, &evSORT0, &evSORT1,
                                &evSEnd0, &evSEnd1, &evEnd1};
        for (int i = 0; i < 12; i++)
            cudaEventCreateWithFlags(evs[i], cudaEventDisableTiming);
    }
};
static StreamPool g_sp;

// ---------------- per-branch buffers ----------------
struct BranchBufs {
    float *XLN, *QKV, *Q64, *ATTN, *O, *X1, *S, *X2, *XLN2;
    int* ORD;
    bf16 *XLNh, *XLNl, *Oh, *Ol, *XLN2h, *XLN2l, *H1h, *H1l;
};
struct Weights {
    bf16 *WqkvTh, *WqkvTl, *WprojTh, *WprojTl, *W1Th, *W1Tl, *W2Th, *W2Tl;
};

static void get_branch_bufs(int br, BranchBufs& bu)
{
    char* p;
    cudaGetSymbolAddress((void**)&p, g_XLN);  bu.XLN  = (float*)p + (size_t)br * B_ * NTOK * DIM_;
    cudaGetSymbolAddress((void**)&p, g_QKV);  bu.QKV  = (float*)p + (size_t)br * B_ * NTOK * 3 * DIM_;
    cudaGetSymbolAddress((void**)&p, g_Q64);  bu.Q64  = (float*)p + (size_t)br * B_ * LT_ * DIM_;
    cudaGetSymbolAddress((void**)&p, g_ATTN); bu.ATTN = (float*)p + (size_t)br * B_ * H_ * NTOK * NTOK;
    cudaGetSymbolAddress((void**)&p, g_O);    bu.O    = (float*)p + (size_t)br * B_ * NTOK * DIM_;
    cudaGetSymbolAddress((void**)&p, g_X1);   bu.X1   = (float*)p + (size_t)br * B_ * NTOK * DIM_;
    cudaGetSymbolAddress((void**)&p, g_S);    bu.S    = (float*)p + (size_t)br * B_ * LS_;
    cudaGetSymbolAddress((void**)&p, g_ORD);  bu.ORD  = (int*)p   + (size_t)br * B_ * LS_;
    cudaGetSymbolAddress((void**)&p, g_X2);   bu.X2   = (float*)p + (size_t)br * B_ * N2 * DIM_;
    cudaGetSymbolAddress((void**)&p, g_XLN2); bu.XLN2 = (float*)p + (size_t)br * B_ * N2 * DIM_;
    cudaGetSymbolAddress((void**)&p, g_XLNh); bu.XLNh = (bf16*)p + (size_t)br * B_ * NTOK * DIM_;
    cudaGetSymbolAddress((void**)&p, g_XLNl); bu.XLNl = (bf16*)p + (size_t)br * B_ * NTOK * DIM_;
    cudaGetSymbolAddress((void**)&p, g_Oh);   bu.Oh   = (bf16*)p + (size_t)br * B_ * NTOK * DIM_;
    cudaGetSymbolAddress((void**)&p, g_Ol);   bu.Ol   = (bf16*)p + (size_t)br * B_ * NTOK * DIM_;
    cudaGetSymbolAddress((void**)&p, g_XLN2h); bu.XLN2h = (bf16*)p + (size_t)br * B_ * N2 * DIM_;
    cudaGetSymbolAddress((void**)&p, g_XLN2l); bu.XLN2l = (bf16*)p + (size_t)br * B_ * N2 * DIM_;
    cudaGetSymbolAddress((void**)&p, g_H1h);  bu.H1h  = (bf16*)p + (size_t)br * B_ * N2 * 4 * DIM_;
    cudaGetSymbolAddress((void**)&p, g_H1l);  bu.H1l  = (bf16*)p + (size_t)br * B_ * N2 * 4 * DIM_;
}

extern "C" void kernel_launch(void* const* d_in, const int* in_sizes, int n_in,
                              void* d_out, int out_size)
{
    const float* x_rgb  = (const float*)d_in[0];
    const float* x_dte  = (const float*)d_in[1];
    const int*   git    = (const int*)d_in[2];
    const int*   gsi_rgb = (const int*)d_in[3];
    const int*   gsi_dte = (const int*)d_in[4];
    const unsigned char* mask = (const unsigned char*)d_in[5];
    const float* g1    = (const float*)d_in[6];
    const float* b1    = (const float*)d_in[7];
    const float* Wqkv  = (const float*)d_in[8];
    const float* bqkv  = (const float*)d_in[9];
    const float* Wproj = (const float*)d_in[10];
    const float* bproj = (const float*)d_in[11];
    const float* g2    = (const float*)d_in[12];
    const float* b2    = (const float*)d_in[13];
    const float* W1    = (const float*)d_in[14];
    const float* bm1   = (const float*)d_in[15];
    const float* W2    = (const float*)d_in[16];
    const float* bm2   = (const float*)d_in[17];

    float* out = (float*)d_out;

    cudaFuncSetAttribute(tc_gemm2<0, false>, cudaFuncAttributeMaxDynamicSharedMemorySize, TC_SMEM_TOTAL);
    cudaFuncSetAttribute(tc_gemm2<1, true>,  cudaFuncAttributeMaxDynamicSharedMemorySize, TC_SMEM_TOTAL);

    Weights w;
    {
        char* p;
        cudaGetSymbolAddress((void**)&p, g_WqkvTh);  w.WqkvTh  = (bf16*)p;
        cudaGetSymbolAddress((void**)&p, g_WqkvTl);  w.WqkvTl  = (bf16*)p;
        cudaGetSymbolAddress((void**)&p, g_WprojTh); w.WprojTh = (bf16*)p;
        cudaGetSymbolAddress((void**)&p, g_WprojTl); w.WprojTl = (bf16*)p;
        cudaGetSymbolAddress((void**)&p, g_W1Th);    w.W1Th    = (bf16*)p;
        cudaGetSymbolAddress((void**)&p, g_W1Tl);    w.W1Tl    = (bf16*)p;
        cudaGetSymbolAddress((void**)&p, g_W2Th);    w.W2Th    = (bf16*)p;
        cudaGetSymbolAddress((void**)&p, g_W2Tl);    w.W2Tl    = (bf16*)p;
    }
    BranchBufs bu[2];
    get_branch_bufs(0, bu[0]);
    get_branch_bufs(1, bu[1]);

    const long long XSZ     = (long long)B_ * N2 * DIM_;
    const long long GIT_OFF = 2 * XSZ;
    const long long K0_OFF  = GIT_OFF + (long long)B_ * LT_;
    const long long K1_OFF  = K0_OFF + (long long)B_ * LK_;
    const long long R0_OFF  = K1_OFF + (long long)B_ * LK_;
    const long long R1_OFF  = R0_OFF + (long long)B_ * LR_;

    cudaStream_t m0 = (cudaStream_t)0;
    cudaStream_t mS[2] = {m0, g_sp.m1};
    cudaStream_t sS[2] = {g_sp.s0, g_sp.s1};
    cudaEvent_t  evLN[2]   = {g_sp.evLN0, g_sp.evLN1};
    cudaEvent_t  evK[2]    = {g_sp.evK0, g_sp.evK1};
    cudaEvent_t  evSM64[2] = {g_sp.evSM64_0, g_sp.evSM64_1};
    cudaEvent_t  evSORT[2] = {g_sp.evSORT0, g_sp.evSORT1};
    cudaEvent_t  evSEnd[2] = {g_sp.evSEnd0, g_sp.evSEnd1};
    const float* xIn[2]    = {x_rgb, x_dte};
    const int*   gsiIn[2]  = {gsi_rgb, gsi_dte};
    float* outX[2] = {out, out + XSZ};
    float* outK[2] = {out + K0_OFF, out + K1_OFF};
    float* outR[2] = {out + R0_OFF, out + R1_OFF};

    // shared prologue on origin stream
    git_kernel<<<(B_ * LT_ + 255) / 256, 256>>>(git, out + GIT_OFF);
    tsplit_kernel<<<dim3(3 * DIM_ / 32, DIM_ / 32), 256>>>(Wqkv, DIM_, 3 * DIM_, w.WqkvTh, w.WqkvTl);
    tsplit_kernel<<<dim3(DIM_ / 32, DIM_ / 32), 256>>>(Wproj, DIM_, DIM_, w.WprojTh, w.WprojTl);
    tsplit_kernel<<<dim3(4 * DIM_ / 32, DIM_ / 32), 256>>>(W1, DIM_, 4 * DIM_, w.W1Th, w.W1Tl);
    tsplit_kernel<<<dim3(DIM_ / 32, 4 * DIM_ / 32), 256>>>(W2, 4 * DIM_, DIM_, w.W2Th, w.W2Tl);

    cudaEventRecord(g_sp.evFork, m0);
    cudaStreamWaitEvent(g_sp.m1, g_sp.evFork, 0);

    // LN1 + merged tc q|v on each main stream
    for (int br = 0; br < 2; br++) {
        ln_kernel<<<B_ * NTOK, 256, 0, mS[br]>>>(xIn[br], g1, b1,
                                                 bu[br].XLN, bu[br].XLNh, bu[br].XLNl);
        cudaEventRecord(evLN[br], mS[br]);
        tc_gemm2<0, false><<<dim3(2 * DIM_ / 128, B_ * NTOK / 128), TC_THREADS, TC_SMEM_TOTAL, mS[br]>>>(
            bu[br].XLNh, bu[br].XLNl, DIM_, w.WqkvTh, w.WqkvTl, DIM_,
            bu[br].QKV, 3 * DIM_, nullptr, nullptr, bqkv, nullptr, 0, DIM_, 1);
    }

    // shared f stream: the two Kahan k GEMMs back-to-back (packed f32x2)
    for (int br = 0; br < 2; br++) {
        cudaStreamWaitEvent(g_sp.f, evLN[br], 0);
        gemm_kernel<false, 0, true, false><<<dim3(DIM_ / BN, B_ * NTOK / BM, 1), 256, 0, g_sp.f>>>(
            bu[br].XLN, DIM_, 0, 0,
            Wqkv + DIM_, 3 * DIM_, 0, 0,
            bu[br].QKV + DIM_, 3 * DIM_, 0, 0,
            nullptr, nullptr,
            bqkv + DIM_, nullptr, 0, 0, 0,
            DIM_, 1, 1.0f);
        cudaEventRecord(evK[br], g_sp.f);
    }

    for (int br = 0; br < 2; br++) {
        cudaStream_t m = mS[br];
        cudaStream_t s = sS[br];

        // ---- score stream ----
        cudaStreamWaitEvent(s, evK[br], 0);
        gemm_kernel<false, 0, true, false><<<dim3(DIM_ / BN, 1, B_), 256, 0, s>>>(
            bu[br].XLN, DIM_, 0, (long long)NTOK * DIM_,
            Wqkv, 3 * DIM_, 0, 0,
            bu[br].Q64, DIM_, 0, (long long)LT_ * DIM_,
            nullptr, nullptr,
            bqkv, nullptr, 0, 0, 0,
            DIM_, B_, 1.0f);
        gemm_kernel<true, 0, true, false><<<dim3(NTOK / BN, 1, B_ * H_), 256, 0, s>>>(
            bu[br].Q64,        DIM_,     (long long)LT_ * DIM_,       DH,
            bu[br].QKV + DIM_, 3 * DIM_, (long long)NTOK * 3 * DIM_,  DH,
            bu[br].ATTN, NTOK, (long long)H_ * NTOK * NTOK, (long long)NTOK * NTOK,
            nullptr, nullptr,
            nullptr, nullptr, 0, 0, 0,
            DH, H_, 0.125f);
        softmax_kernel<<<B_ * H_ * LT_, 128, 0, s>>>(bu[br].ATTN, 0, LT_);
        cudaEventRecord(evSM64[br], s);
        ce_score_kernel<<<B_, 256, 0, s>>>(bu[br].ATTN, mask, bu[br].S);
        sort_kernel<<<B_, 256, 0, s>>>(bu[br].S, bu[br].ORD);
        cudaEventRecord(evSORT[br], s);
        indices_kernel<<<B_, 256, 0, s>>>(bu[br].ORD, gsiIn[br], outK[br], outR[br]);
        cudaEventRecord(evSEnd[br], s);

        // ---- main stream: value path ----
        cudaStreamWaitEvent(m, evK[br], 0);
        gemm_kernel<true, 0, false, false><<<dim3(NTOK / BN, 4, B_ * H_), 256, 0, m>>>(
            bu[br].QKV + (long long)LT_ * 3 * DIM_, 3 * DIM_, (long long)NTOK * 3 * DIM_, DH,
            bu[br].QKV + DIM_,                      3 * DIM_, (long long)NTOK * 3 * DIM_, DH,
            bu[br].ATTN + (long long)LT_ * NTOK, NTOK, (long long)H_ * NTOK * NTOK, (long long)NTOK * NTOK,
            nullptr, nullptr,
            nullptr, nullptr, 0, 0, 0,
            DH, H_, 0.125f);
        softmax_kernel<<<B_ * H_ * LS_, 128, 0, m>>>(bu[br].ATTN, LT_, LS_);

        cudaStreamWaitEvent(m, evSM64[br], 0);
        gemm_kernel<false, 0, false, true><<<dim3(DH / BN, NTOK / BM, B_ * H_), 256, 0, m>>>(
            bu[br].ATTN, NTOK, (long long)H_ * NTOK * NTOK, (long long)NTOK * NTOK,
            bu[br].QKV + 2 * DIM_, 3 * DIM_, (long long)NTOK * 3 * DIM_, DH,
            bu[br].O, DIM_, (long long)NTOK * DIM_, DH,
            bu[br].Oh, bu[br].Ol,
            nullptr, nullptr, 0, 0, 0,
            NTOK, H_, 1.0f);

        tc_gemm2<0, false><<<dim3(DIM_ / 128, B_ * NTOK / 128), TC_THREADS, TC_SMEM_TOTAL, m>>>(
            bu[br].Oh, bu[br].Ol, DIM_, w.WprojTh, w.WprojTl, DIM_,
            bu[br].X1, DIM_, nullptr, nullptr, bproj, xIn[br], DIM_, DIM_, 0);

        cudaStreamWaitEvent(m, evSORT[br], 0);
        gather_kernel<<<dim3(B_, N2), 256, 0, m>>>(bu[br].X1, bu[br].ORD, bu[br].X2);
        ln_kernel<<<B_ * N2, 256, 0, m>>>(bu[br].X2, g2, b2,
                                          bu[br].XLN2, bu[br].XLN2h, bu[br].XLN2l);
        tc_gemm2<1, true><<<dim3(4 * DIM_ / 128, B_ * N2 / 128), TC_THREADS, TC_SMEM_TOTAL, m>>>(
            bu[br].XLN2h, bu[br].XLN2l, DIM_, w.W1Th, w.W1Tl, DIM_,
            nullptr, 4 * DIM_, bu[br].H1h, bu[br].H1l, bm1, nullptr, 0, DIM_, 0);
        tc_gemm2<0, false><<<dim3(DIM_ / 128, B_ * N2 / 128), TC_THREADS, TC_SMEM_TOTAL, m>>>(
            bu[br].H1h, bu[br].H1l, 4 * DIM_, w.W2Th, w.W2Tl, 4 * DIM_,
            outX[br], DIM_, nullptr, nullptr, bm2, bu[br].X2, DIM_, 4 * DIM_, 0);
    }

    // join all side streams into origin
    cudaEventRecord(g_sp.evEnd1, g_sp.m1);
    cudaStreamWaitEvent(m0, g_sp.evEnd1, 0);
    cudaStreamWaitEvent(m0, g_sp.evSEnd0, 0);
    cudaStreamWaitEvent(m0, g_sp.evSEnd1, 0);
}

// round 14
// speedup vs baseline: 1.2847x; 1.0804x over previous
#include <cuda_runtime.h>
#include <cuda_bf16.h>
#include <math.h>
#include <stdint.h>

// ---------------- problem constants ----------------
#define B_    32
#define LT_   64
#define LS_   256
#define NTOK  320      // LT + LS
#define DIM_  768
#define H_    12
#define DH    64
#define LK_   180
#define LR_   76
#define N2    244      // LT + LK

#if defined(__CUDA_ARCH__) && defined(__CUDA_ARCH_FEAT_SM103_ALL)
#define HAS_TCGEN05 1
#else
#define HAS_TCGEN05 0
#endif

typedef __nv_bfloat16 bf16;
typedef unsigned long long u64;

// ---------------- scratch (per-branch duplicated) ----------------
__device__ float g_XLN [2][B_ * NTOK * DIM_];
__device__ float g_QKV [2][B_ * NTOK * 3 * DIM_];
__device__ float g_Q64 [2][B_ * LT_ * DIM_];
__device__ float g_ATTN[2][(size_t)B_ * H_ * NTOK * NTOK];
__device__ float g_O   [2][B_ * NTOK * DIM_];
__device__ float g_X1  [2][B_ * NTOK * DIM_];
__device__ float g_S   [2][B_ * LS_];
__device__ int   g_ORD [2][B_ * LS_];
__device__ float g_X2  [2][B_ * N2 * DIM_];
__device__ float g_XLN2[2][B_ * N2 * DIM_];

__device__ unsigned short g_XLNh [2][B_ * NTOK * DIM_];
__device__ unsigned short g_XLNl [2][B_ * NTOK * DIM_];
__device__ unsigned short g_Oh   [2][B_ * NTOK * DIM_];
__device__ unsigned short g_Ol   [2][B_ * NTOK * DIM_];
__device__ unsigned short g_XLN2h[2][B_ * N2 * DIM_];
__device__ unsigned short g_XLN2l[2][B_ * N2 * DIM_];
__device__ unsigned short g_H1h  [2][B_ * N2 * 4 * DIM_];
__device__ unsigned short g_H1l  [2][B_ * N2 * 4 * DIM_];

// shared weight splits
__device__ unsigned short g_WqkvTh[3 * DIM_ * DIM_];
__device__ unsigned short g_WqkvTl[3 * DIM_ * DIM_];
__device__ unsigned short g_WprojTh[DIM_ * DIM_];
__device__ unsigned short g_WprojTl[DIM_ * DIM_];
__device__ unsigned short g_W1Th [4 * DIM_ * DIM_];
__device__ unsigned short g_W1Tl [4 * DIM_ * DIM_];
__device__ unsigned short g_W2Th [4 * DIM_ * DIM_];
__device__ unsigned short g_W2Tl [4 * DIM_ * DIM_];

__device__ __forceinline__ void split_bf16(float v, bf16& h, bf16& l) {
    h = __float2bfloat16(v);
    l = __float2bfloat16(v - __bfloat162float(h));
}

// ---------------- packed f32x2 helpers (sm_100+ PTX) ----------------
#define PK_FMA2(d, a, b, c) \
    asm("fma.rn.f32x2 %0, %1, %2, %3;" : "=l"(d) : "l"(a), "l"(b), "l"(c))
#define PK_ADD2(d, a, b) \
    asm("add.rn.f32x2 %0, %1, %2;" : "=l"(d) : "l"(a), "l"(b))
#define PK_SUB2(d, a, b) \
    asm("sub.rn.f32x2 %0, %1, %2;" : "=l"(d) : "l"(a), "l"(b))
#define PK_PACK(d, lo, hi) \
    asm("mov.b64 %0, {%1, %2};" : "=l"(d) : "f"(lo), "f"(hi))
#define PK_UNPACK(lo, hi, s) \
    asm("mov.b64 {%0, %1}, %2;" : "=f"(lo), "=f"(hi) : "l"(s))

// =====================================================================
// tcgen05 helpers (sm_103a pass only)
// =====================================================================
#if HAS_TCGEN05
__device__ __forceinline__ uint32_t elect_one_pred() {
    uint32_t pred;
    asm volatile(
        "{\n\t.reg .pred p;\n\telect.sync _|p, 0xFFFFFFFF;\n\tselp.b32 %0, 1, 0, p;\n\t}"
        : "=r"(pred));
    return pred;
}
__device__ __forceinline__ uint32_t smem_to_u32(const void* smem_ptr) {
    uint32_t addr;
    asm("{ .reg .u64 tmp; cvta.to.shared.u64 tmp, %1; cvt.u32.u64 %0, tmp; }"
        : "=r"(addr) : "l"(smem_ptr));
    return addr;
}
__device__ __forceinline__ void cp16(uint32_t s, const void* g) {
    asm volatile("cp.async.cg.shared.global [%0], [%1], 16;" :: "r"(s), "l"(g) : "memory");
}
#define CP_COMMIT() asm volatile("cp.async.commit_group;" ::: "memory")
#define CP_WAIT(n)  asm volatile("cp.async.wait_group %0;" :: "n"(n) : "memory")

#define TCGEN05_ALLOC(a, n) \
    asm volatile("tcgen05.alloc.cta_group::1.sync.aligned.shared::cta.b32 [%0], %1;" \
        :: "r"((uint32_t)(a)), "r"((uint32_t)(n)) : "memory")
#define TCGEN05_DEALLOC(t, n) \
    asm volatile("tcgen05.dealloc.cta_group::1.sync.aligned.b32 %0, %1;" \
        :: "r"(t), "r"((uint32_t)(n)))
#define TCGEN05_RELINQUISH_ALLOC_PERMIT() \
    asm volatile("tcgen05.relinquish_alloc_permit.cta_group::1.sync.aligned;")
#define TCGEN05_COMMIT(m) \
    asm volatile("tcgen05.commit.cta_group::1.mbarrier::arrive::one.shared::cluster.b64 [%0];" \
        :: "r"((uint32_t)(m)) : "memory")
#define TCGEN05_WAIT_LD()  asm volatile("tcgen05.wait::ld.sync.aligned;" ::: "memory")
#define TCGEN05_FENCE_BEFORE() asm volatile("tcgen05.fence::before_thread_sync;" ::: "memory")
#define TCGEN05_FENCE_AFTER()  asm volatile("tcgen05.fence::after_thread_sync;" ::: "memory")
#define FENCE_PROXY_ASYNC_SHARED_CTA() asm volatile("fence.proxy.async.shared::cta;" ::: "memory")
#define MBARRIER_INIT(m, c) \
    asm volatile("mbarrier.init.shared.b64 [%0], %1;" :: "r"((uint32_t)(m)), "r"((uint32_t)(c)) : "memory")
#define MBARRIER_INVAL(m) \
    asm volatile("mbarrier.inval.shared.b64 [%0];" :: "r"((uint32_t)(m)) : "memory")

#define MBARRIER_WAIT_PARITY(mb, pp) do { \
    uint32_t _mbar = (uint32_t)(mb); \
    uint32_t _parity = (uint32_t)(pp); \
    uint32_t _done; \
    asm volatile( \
        "{\n\t.reg .pred p;\n\t" \
        "mbarrier.try_wait.parity.acquire.cta.shared::cta.b64 p, [%1], %2;\n\t" \
        "selp.b32 %0, 1, 0, p;\n\t}" \
        : "=r"(_done) : "r"(_mbar), "r"(_parity) : "memory"); \
    if (!_done) { \
        asm volatile( \
            "{\n\t.reg .pred P1;\n\t" \
            "WAIT_LOOP_%=:\n\t" \
            "mbarrier.try_wait.parity.acquire.cta.shared::cta.b64 P1, [%0], %1, 0x989680;\n\t" \
            "@P1 bra.uni WAIT_DONE_%=;\n\t" \
            "bra.uni WAIT_LOOP_%=;\n\t" \
            "WAIT_DONE_%=:\n\t}" \
            :: "r"(_mbar), "r"(_parity) : "memory"); \
    } \
} while(0)

#define TCGEN05_LD_32X32B_X32(r, tmem_addr) \
    asm volatile( \
        "tcgen05.ld.sync.aligned.32x32b.x32.b32 " \
        "{%0, %1, %2, %3, %4, %5, %6, %7, " \
        " %8, %9, %10, %11, %12, %13, %14, %15, " \
        " %16, %17, %18, %19, %20, %21, %22, %23, " \
        " %24, %25, %26, %27, %28, %29, %30, %31}, [%32];" \
        : "=r"((r)[0]),  "=r"((r)[1]),  "=r"((r)[2]),  "=r"((r)[3]), \
          "=r"((r)[4]),  "=r"((r)[5]),  "=r"((r)[6]),  "=r"((r)[7]), \
          "=r"((r)[8]),  "=r"((r)[9]),  "=r"((r)[10]), "=r"((r)[11]), \
          "=r"((r)[12]), "=r"((r)[13]), "=r"((r)[14]), "=r"((r)[15]), \
          "=r"((r)[16]), "=r"((r)[17]), "=r"((r)[18]), "=r"((r)[19]), \
          "=r"((r)[20]), "=r"((r)[21]), "=r"((r)[22]), "=r"((r)[23]), \
          "=r"((r)[24]), "=r"((r)[25]), "=r"((r)[26]), "=r"((r)[27]), \
          "=r"((r)[28]), "=r"((r)[29]), "=r"((r)[30]), "=r"((r)[31]) \
        : "r"(tmem_addr))

static constexpr uint64_t SMEM_DESC_BASE_SW128 =
    (uint64_t(2)  << 61) | (uint64_t(1) << 46) | (uint64_t(64) << 32) | (uint64_t(1) << 16);
#define MAKE_SMEM_DESC(base_addr) \
    (SMEM_DESC_BASE_SW128 | ((uint64_t)((base_addr) >> 4) & 0x3FFF))

__device__ __forceinline__ void tc_mma_f16_ss(uint32_t d, uint64_t a, uint64_t b,
                                              uint32_t idesc, uint32_t en)
{
    asm volatile(
        "{\n\t.reg .pred p;\n\tsetp.ne.u32 p, %5, 0;\n\t"
        "tcgen05.mma.cta_group::1.kind::f16 [%0], %1, %2, %3, {%4, %4, %4, %4}, p;\n\t}"
        :: "r"(d), "l"(a), "l"(b), "r"(idesc), "r"(0u), "r"(en) : "memory");
}
#endif // HAS_TCGEN05

// =====================================================================
// tc_gemm2: SINGLE-buffer split-bf16 tc GEMM, 2 CTAs/SM co-residency.
// Same SW128 layout / MMA order as the double-buffer version (bit-identical).
// =====================================================================
#define TC_THREADS 256
#define TC_SMEM_TOTAL (1024 + 4 * 16384)   // 66560 bytes -> 2 CTAs/SM
#define TC_IDESC 0x8200490u

template<int ACT, bool OUTSPLIT>
__global__ __launch_bounds__(TC_THREADS, 2)
void tc_gemm2(const bf16* __restrict__ Ah, const bf16* __restrict__ Al, int lda,
              const bf16* __restrict__ Bh, const bf16* __restrict__ Bl, int ldb,
              float* __restrict__ C, int ldc,
              bf16* __restrict__ Ch, bf16* __restrict__ Cl,
              const float* __restrict__ bias,
              const float* __restrict__ Res, int ldr,
              int K, int qv)
{
    const int n0_raw = blockIdx.x * 128;
    int cshift = (qv && n0_raw >= DIM_) ? DIM_ : 0;
    Bh += (long long)cshift * ldb;
    Bl += (long long)cshift * ldb;
#if HAS_TCGEN05
    extern __shared__ char smem[];
    const uint32_t sb = smem_to_u32(smem);
    const int tid = threadIdx.x;
    const int wid = tid >> 5;
    const int lid = tid & 31;
    const int m0 = blockIdx.y * 128;
    const int n0 = n0_raw;

    if (wid == 0) {
        TCGEN05_ALLOC(sb + 0, 128);
        TCGEN05_RELINQUISH_ALLOC_PERMIT();
    }
    if (tid == 0) MBARRIER_INIT(sb + 16, 1);
    __syncthreads();
    uint32_t tmem;
    asm volatile("ld.shared.b32 %0, [%1];" : "=r"(tmem) : "r"(sb));

    const int nk = K >> 6;
    const int lr  = tid >> 3;
    const int lcq = (tid & 7) * 8;
    const uint32_t db = sb + 1024;   // single buffer

    for (int kt = 0; kt < nk; kt++) {
        if (kt >= 1)   // MMA of chunk kt-1 must finish before overwriting buffer
            MBARRIER_WAIT_PARITY(sb + 16, (kt - 1) & 1);
        {
            const bf16* Agh = Ah + (long long)m0 * lda + kt * 64;
            const bf16* Agl = Al + (long long)m0 * lda + kt * 64;
            const bf16* Bgh = Bh + (long long)n0 * ldb + kt * 64;
            const bf16* Bgl = Bl + (long long)n0 * ldb + kt * 64;
            #pragma unroll
            for (int i = 0; i < 4; i++) {
                int r = lr + i * 32;
                uint32_t bo = r * 128 + lcq * 2;
                uint32_t so = bo ^ ((bo >> 3) & 0x70);
                cp16(db + so,          Agh + (long long)r * lda + lcq);
                cp16(db + 16384 + so,  Agl + (long long)r * lda + lcq);
                cp16(db + 32768 + so,  Bgh + (long long)r * ldb + lcq);
                cp16(db + 49152 + so,  Bgl + (long long)r * ldb + lcq);
            }
            CP_COMMIT();
        }
        CP_WAIT(0);
        FENCE_PROXY_ASYNC_SHARED_CTA();
        __syncthreads();

        if (wid == 0) {
            if (elect_one_pred()) {
                uint64_t dAh = MAKE_SMEM_DESC(db);
                uint64_t dAl = MAKE_SMEM_DESC(db + 16384);
                uint64_t dBh = MAKE_SMEM_DESC(db + 32768);
                uint64_t dBl = MAKE_SMEM_DESC(db + 49152);
                #pragma unroll
                for (int k = 0; k < 4; k++)
                    tc_mma_f16_ss(tmem, dAh + k * 2, dBh + k * 2, TC_IDESC,
                                  (kt == 0 && k == 0) ? 0u : 1u);
                #pragma unroll
                for (int k = 0; k < 4; k++)
                    tc_mma_f16_ss(tmem, dAh + k * 2, dBl + k * 2, TC_IDESC, 1u);
                #pragma unroll
                for (int k = 0; k < 4; k++)
                    tc_mma_f16_ss(tmem, dAl + k * 2, dBh + k * 2, TC_IDESC, 1u);
                TCGEN05_COMMIT(sb + 16);
            }
        }
    }

    MBARRIER_WAIT_PARITY(sb + 16, (nk - 1) & 1);
    TCGEN05_FENCE_AFTER();

    if (wid < 4) {
        int m = m0 + wid * 32 + lid;
        float* Crow = C ? (C + (long long)m * ldc + n0 + cshift) : (float*)0;
        bf16* Chrow = OUTSPLIT ? (Ch + (long long)m * ldc + n0) : (bf16*)0;
        bf16* Clrow = OUTSPLIT ? (Cl + (long long)m * ldc + n0) : (bf16*)0;
        const float* Rrow = Res ? (Res + (long long)m * ldr + n0) : (const float*)0;
        #pragma unroll
        for (int cb = 0; cb < 128; cb += 32) {
            uint32_t d[32];
            TCGEN05_LD_32X32B_X32(d, tmem + cb);
            TCGEN05_WAIT_LD();
            float vout[32];
            #pragma unroll
            for (int j = 0; j < 32; j++) {
                float v = __uint_as_float(d[j]);
                if (bias) v += bias[n0 + cshift + cb + j];
                if (Rrow) v += Rrow[cb + j];
                if (ACT == 1) v = 0.5f * v * (1.0f + erff(v * 0.70710678118654752f));
                vout[j] = v;
            }
            if (Crow) {
                #pragma unroll
                for (int q = 0; q < 32; q += 4)
                    *(float4*)&Crow[cb + q] = *(float4*)&vout[q];
            }
            if (OUTSPLIT) {
                #pragma unroll
                for (int q = 0; q < 32; q += 2) {
                    bf16 h0, l0, h1, l1;
                    split_bf16(vout[q], h0, l0);
                    split_bf16(vout[q + 1], h1, l1);
                    unsigned int hw = (unsigned int)__bfloat16_as_ushort(h0) |
                                      ((unsigned int)__bfloat16_as_ushort(h1) << 16);
                    unsigned int lw = (unsigned int)__bfloat16_as_ushort(l0) |
                                      ((unsigned int)__bfloat16_as_ushort(l1) << 16);
                    *(unsigned int*)&Chrow[cb + q] = hw;
                    *(unsigned int*)&Clrow[cb + q] = lw;
                }
            }
        }
        TCGEN05_FENCE_BEFORE();
    }
    __syncthreads();
    if (tid == 0) MBARRIER_INVAL(sb + 16);
    __syncthreads();
    if (wid == 0) TCGEN05_DEALLOC(tmem, 128);
#else
    // fp32 fallback (never runs on GB300)
    const int tid = threadIdx.x;
    const int m0 = blockIdx.y * 128;
    const int n0 = n0_raw;
    for (int e = tid; e < 128 * 128; e += TC_THREADS) {
        int mi = e >> 7, ni = e & 127;
        int m = m0 + mi, n = n0 + ni;
        float s = 0.f;
        for (int k = 0; k < K; k++)
            s += (__bfloat162float(Ah[(long long)m * lda + k]) + __bfloat162float(Al[(long long)m * lda + k])) *
                 (__bfloat162float(Bh[(long long)n * ldb + k]) + __bfloat162float(Bl[(long long)n * ldb + k]));
        if (bias) s += bias[n + cshift];
        if (Res)  s += Res[(long long)m * ldr + n];
        if (ACT == 1) s = 0.5f * s * (1.0f + erff(s * 0.70710678118654752f));
        if (C) C[(long long)m * ldc + n + cshift] = s;
        if (OUTSPLIT) {
            bf16 h, l; split_bf16(s, h, l);
            Ch[(long long)m * ldc + n] = h;
            Cl[(long long)m * ldc + n] = l;
        }
    }
#endif
}

// ================= 64x64 GEMM (Kahan-capable, packed f32x2) =================
#define BM 64
#define BN 64
#define BK 16

template<bool TRANSB, int ACT, bool KAHAN, bool OUTSPLIT>
__global__ __launch_bounds__(256)
void gemm_kernel(const float* __restrict__ A, int lda, long long sA1, long long sA2,
                 const float* __restrict__ Bm, int ldb, long long sB1, long long sB2,
                 float* __restrict__ C, int ldc, long long sC1, long long sC2,
                 bf16* __restrict__ Ch, bf16* __restrict__ Cl,
                 const float* __restrict__ bias,
                 const float* __restrict__ Res, int ldr, long long sR1, long long sR2,
                 int K, int bdiv, float alpha)
{
    __shared__ float As[BK][BM + 4];
    __shared__ float Bs[BK][BN + 4];

    int bz = blockIdx.z;
    int ob = bz / bdiv;
    int ib = bz - ob * bdiv;
    A  += ob * sA1 + ib * sA2;
    Bm += ob * sB1 + ib * sB2;
    C  += ob * sC1 + ib * sC2;
    if (OUTSPLIT) { Ch += ob * sC1 + ib * sC2; Cl += ob * sC1 + ib * sC2; }
    if (Res) Res += ob * sR1 + ib * sR2;

    int bm = blockIdx.y * BM;
    int bn = blockIdx.x * BN;
    int tid = threadIdx.x;
    int tx = tid & 15, ty = tid >> 4;

    u64 acc2[4][2] = {};
    u64 ncmp2[4][2] = {};

    for (int k0 = 0; k0 < K; k0 += BK) {
        #pragma unroll
        for (int i = 0; i < 4; i++) {
            int idx = tid + i * 256;
            int m  = idx >> 4;
            int kk = idx & 15;
            As[kk][m] = A[(long long)(bm + m) * lda + k0 + kk];
        }
        if (TRANSB) {
            #pragma unroll
            for (int i = 0; i < 4; i++) {
                int idx = tid + i * 256;
                int n  = idx >> 4;
                int kk = idx & 15;
                Bs[kk][n] = Bm[(long long)(bn + n) * ldb + k0 + kk];
            }
        } else {
            #pragma unroll
            for (int i = 0; i < 4; i++) {
                int idx = tid + i * 256;
                int kk = idx >> 6;
                int n  = idx & 63;
                Bs[kk][n] = Bm[(long long)(k0 + kk) * ldb + bn + n];
            }
        }
        __syncthreads();

        #pragma unroll
        for (int kk = 0; kk < BK; kk++) {
            float4 av = *(const float4*)&As[kk][ty * 4];
            float a4[4] = {av.x, av.y, av.z, av.w};
            const u64* bp = (const u64*)&Bs[kk][tx * 4];
            u64 b2[2] = {bp[0], bp[1]};
            #pragma unroll
            for (int i = 0; i < 4; i++) {
                u64 a2;
                PK_PACK(a2, a4[i], a4[i]);
                #pragma unroll
                for (int j2 = 0; j2 < 2; j2++) {
                    if (KAHAN) {
                        u64 y, t, d;
                        PK_FMA2(y, a2, b2[j2], ncmp2[i][j2]);
                        PK_ADD2(t, acc2[i][j2], y);
                        PK_SUB2(d, t, acc2[i][j2]);
                        PK_SUB2(ncmp2[i][j2], y, d);
                        acc2[i][j2] = t;
                    } else {
                        PK_FMA2(acc2[i][j2], a2, b2[j2], acc2[i][j2]);
                    }
                }
            }
        }
        __syncthreads();
    }

    #pragma unroll
    for (int i = 0; i < 4; i++) {
        int m = bm + ty * 4 + i;
        float accs[4];
        PK_UNPACK(accs[0], accs[1], acc2[i][0]);
        PK_UNPACK(accs[2], accs[3], acc2[i][1]);
        #pragma unroll
        for (int j = 0; j < 4; j++) {
            int n = bn + tx * 4 + j;
            float v = accs[j] * alpha;
            if (bias) v += bias[n];
            if (Res)  v += Res[(long long)m * ldr + n];
            if (ACT == 1) v = 0.5f * v * (1.0f + erff(v * 0.70710678118654752f));
            C[(long long)m * ldc + n] = v;
            if (OUTSPLIT) {
                bf16 h, l;
                split_bf16(v, h, l);
                Ch[(long long)m * ldc + n] = h;
                Cl[(long long)m * ldc + n] = l;
            }
        }
    }
}

// ---------------- transpose + split (weights) ----------------
__global__ __launch_bounds__(256)
void tsplit_kernel(const float* __restrict__ in, int K, int N,
                   bf16* __restrict__ oh, bf16* __restrict__ ol)
{
    __shared__ float tile[32][33];
    int nb = blockIdx.x * 32, kb = blockIdx.y * 32;
    int tx = threadIdx.x & 31, ty = threadIdx.x >> 5;
    #pragma unroll
    for (int i = 0; i < 32; i += 8)
        tile[ty + i][tx] = in[(long long)(kb + ty + i) * N + nb + tx];
    __syncthreads();
    #pragma unroll
    for (int i = 0; i < 32; i += 8) {
        int n = nb + ty + i, k = kb + tx;
        float v = tile[tx][ty + i];
        bf16 h, l;
        split_bf16(v, h, l);
        oh[(long long)n * K + k] = h;
        ol[(long long)n * K + k] = l;
    }
}

// ---------------- LayerNorm, fp64 stats, fp32 + split out ----------------
__global__ __launch_bounds__(256)
void ln_kernel(const float* __restrict__ x, const float* __restrict__ g,
               const float* __restrict__ b, float* __restrict__ y,
               bf16* __restrict__ yh, bf16* __restrict__ yl)
{
    long long row = blockIdx.x;
    const float* xr = x + row * DIM_;
    float* yr = y + row * DIM_;
    bf16* yhr = yh + row * DIM_;
    bf16* ylr = yl + row * DIM_;
    int t = threadIdx.x;
    float v0 = xr[t], v1 = xr[t + 256], v2 = xr[t + 512];
    double s = (double)v0 + (double)v1 + (double)v2;
    double q = (double)v0 * v0 + (double)v1 * v1 + (double)v2 * v2;
    __shared__ double sh[16];
    __shared__ float  par[2];
    #pragma unroll
    for (int o = 16; o > 0; o >>= 1) {
        s += __shfl_down_sync(~0u, s, o);
        q += __shfl_down_sync(~0u, q, o);
    }
    int wid = t >> 5, lane = t & 31;
    if (lane == 0) { sh[wid] = s; sh[wid + 8] = q; }
    __syncthreads();
    if (t == 0) {
        double ss = 0., qq = 0.;
        #pragma unroll
        for (int i = 0; i < 8; i++) { ss += sh[i]; qq += sh[i + 8]; }
        double mu = ss / DIM_;
        double var = qq / DIM_ - mu * mu;
        par[0] = (float)mu;
        par[1] = (float)(1.0 / sqrt(var + 1e-5));
    }
    __syncthreads();
    float mu = par[0], r = par[1];
    #pragma unroll
    for (int i = 0; i < 3; i++) {
        int c = t + i * 256;
        float vv = (i == 0 ? v0 : (i == 1 ? v1 : v2));
        float o = (vv - mu) * r * g[c] + b[c];
        yr[c] = o;
        bf16 h, l;
        split_bf16(o, h, l);
        yhr[c] = h;
        ylr[c] = l;
    }
}

// ---------------- row softmax over 320, row subset [tbase, tbase+tcnt) ----------------
__global__ __launch_bounds__(128)
void softmax_kernel(float* __restrict__ attn, int tbase, int tcnt)
{
    int blk = blockIdx.x;
    int bh = blk / tcnt;
    int t_q = tbase + (blk - bh * tcnt);
    long long row = (long long)bh * NTOK + t_q;
    float* p = attn + row * NTOK;
    int t = threadIdx.x;
    float v[3];
    float m = -1e30f;
    #pragma unroll
    for (int i = 0; i < 3; i++) {
        int c = t + i * 128;
        v[i] = (c < NTOK) ? p[c] : -1e30f;
        m = fmaxf(m, v[i]);
    }
    __shared__ float shm[4];
    __shared__ double shd[4];
    #pragma unroll
    for (int o = 16; o > 0; o >>= 1) m = fmaxf(m, __shfl_xor_sync(~0u, m, o));
    if ((t & 31) == 0) shm[t >> 5] = m;
    __syncthreads();
    m = fmaxf(fmaxf(shm[0], shm[1]), fmaxf(shm[2], shm[3]));
    __syncthreads();

    if (t_q < LT_) {
        double e[3];
        double s = 0.0;
        #pragma unroll
        for (int i = 0; i < 3; i++) {
            int c = t + i * 128;
            if (c < NTOK) { e[i] = exp((double)v[i] - (double)m); s += e[i]; }
            else e[i] = 0.0;
        }
        #pragma unroll
        for (int o = 16; o > 0; o >>= 1) s += __shfl_xor_sync(~0u, s, o);
        if ((t & 31) == 0) shd[t >> 5] = s;
        __syncthreads();
        s = shd[0] + shd[1] + shd[2] + shd[3];
        double inv = 1.0 / s;
        #pragma unroll
        for (int i = 0; i < 3; i++) {
            int c = t + i * 128;
            if (c < NTOK) p[c] = (float)(e[i] * inv);
        }
    } else {
        float e[3];
        float s = 0.0f;
        #pragma unroll
        for (int i = 0; i < 3; i++) {
            int c = t + i * 128;
            if (c < NTOK) { e[i] = __expf(v[i] - m); s += e[i]; }
            else e[i] = 0.0f;
        }
        #pragma unroll
        for (int o = 16; o > 0; o >>= 1) s += __shfl_xor_sync(~0u, s, o);
        if ((t & 31) == 0) shm[t >> 5] = s;
        __syncthreads();
        s = shm[0] + shm[1] + shm[2] + shm[3];
        float inv = 1.0f / s;
        #pragma unroll
        for (int i = 0; i < 3; i++) {
            int c = t + i * 128;
            if (c < NTOK) p[c] = e[i] * inv;
        }
    }
}

// ---------------- CE scores (fp64) ----------------
__global__ __launch_bounds__(256)
void ce_score_kernel(const float* __restrict__ attn, const unsigned char* __restrict__ maskp,
                     float* __restrict__ S)
{
    int b = blockIdx.x;
    int j = threadIdx.x;
    __shared__ float mf[LT_];
    __shared__ double cntsh;
    __shared__ int mode;
    if (j == 0) {
        const unsigned int* w = (const unsigned int*)maskp;
        bool all_int = true, all_flt = true;
        for (int i = 0; i < 512; i++) {
            unsigned int v = w[i];
            if (v != 0u && v != 1u) all_int = false;
            if (v != 0u && v != 0x3F800000u) all_flt = false;
        }
        mode = all_int ? 0 : (all_flt ? 1 : 2);
    }
    __syncthreads();
    if (j < LT_) {
        int mv;
        if (mode == 0)      mv = ((const int*)maskp)[b * LT_ + j] != 0;
        else if (mode == 1) mv = ((const float*)maskp)[b * LT_ + j] != 0.0f;
        else                mv = maskp[b * LT_ + j] != 0;
        mf[j] = mv ? 1.0f : 0.0f;
    }
    __syncthreads();
    if (j == 0) {
        double c = 0.;
        for (int t = 0; t < LT_; t++) c += (double)mf[t];
        cntsh = c;
    }
    __syncthreads();
    double cnt = cntsh;
    double stot = 0.0;
    const float* base = attn + (long long)b * H_ * NTOK * NTOK + LT_ + j;
    for (int h = 0; h < H_; h++) {
        const float* ph = base + (long long)h * NTOK * NTOK;
        double sh = 0.0;
        #pragma unroll 4
        for (int t = 0; t < LT_; t++)
            sh += (double)ph[(long long)t * NTOK] * (double)mf[t];
        stot += sh / cnt;
    }
    S[b * LS_ + j] = (float)(stot / H_);
}

// ---------------- bitonic sort ----------------
__global__ __launch_bounds__(256)
void sort_kernel(const float* __restrict__ S, int* __restrict__ order)
{
    int b = blockIdx.x, t = threadIdx.x;
    __shared__ float val[256];
    __shared__ int   idx[256];
    val[t] = S[b * LS_ + t];
    idx[t] = t;
    __syncthreads();
    for (int k = 2; k <= 256; k <<= 1) {
        for (int j = k >> 1; j > 0; j >>= 1) {
            int p = t ^ j;
            if (p > t) {
                bool desc = ((t & k) == 0);
                float va = val[t], vb = val[p];
                int ia = idx[t], ib = idx[p];
                bool aFirst = (va > vb) || (va == vb && ia < ib);
                if (aFirst != desc) {
                    val[t] = vb; val[p] = va;
                    idx[t] = ib; idx[p] = ia;
                }
            }
            __syncthreads();
        }
    }
    order[b * LS_ + t] = idx[t];
}

// ---------------- gather ----------------
__global__ __launch_bounds__(256)
void gather_kernel(const float* __restrict__ X1, const int* __restrict__ ord,
                   float* __restrict__ X2)
{
    int b = blockIdx.x, t = blockIdx.y;
    int src = (t < LT_) ? t : (LT_ + ord[b * LS_ + (t - LT_)]);
    const float* s = X1 + ((long long)b * NTOK + src) * DIM_;
    float* d = X2 + ((long long)b * N2 + t) * DIM_;
    int i = threadIdx.x;
    d[i] = s[i];
    d[i + 256] = s[i + 256];
    d[i + 512] = s[i + 512];
}

// ---------------- index outputs ----------------
__global__ __launch_bounds__(256)
void indices_kernel(const int* __restrict__ ord, const int* __restrict__ gsi,
                    float* __restrict__ outK, float* __restrict__ outR)
{
    int b = blockIdx.x, t = threadIdx.x;
    if (t < LK_) outK[b * LK_ + t] = (float)gsi[b * LS_ + ord[b * LS_ + t]];
    if (t < LR_) outR[b * LR_ + t] = (float)gsi[b * LS_ + ord[b * LS_ + LK_ + t]];
}

__global__ __launch_bounds__(256)
void git_kernel(const int* __restrict__ git, float* __restrict__ out)
{
    int i = blockIdx.x * 256 + threadIdx.x;
    if (i < B_ * LT_) out[i] = (float)git[i];
}

// ---------------- streams/events (created pre-main) ----------------
struct StreamPool {
    cudaStream_t f, m1, s0, s1;
    cudaEvent_t evFork, evLN0, evLN1, evK0, evK1,
                evSM64_0, evSM64_1, evSORT0, evSORT1,
                evSEnd0, evSEnd1, evEnd1;
    StreamPool() {
        cudaStreamCreateWithFlags(&f,  cudaStreamNonBlocking);
        cudaStreamCreateWithFlags(&m1, cudaStreamNonBlocking);
        cudaStreamCreateWithFlags(&s0, cudaStreamNonBlocking);
        cudaStreamCreateWithFlags(&s1, cudaStreamNonBlocking);
        cudaEvent_t* evs[12] = {&evFork, &evLN0, &evLN1, &evK0, &evK1,
                                &evSM64_0, &evSM64_1, &evSORT0, &evSORT1,
                                &evSEnd0, &evSEnd1, &evEnd1};
        for (int i = 0; i < 12; i++)
            cudaEventCreateWithFlags(evs[i], cudaEventDisableTiming);
    }
};
static StreamPool g_sp;

// ---------------- per-branch buffers ----------------
struct BranchBufs {
    float *XLN, *QKV, *Q64, *ATTN, *O, *X1, *S, *X2, *XLN2;
    int* ORD;
    bf16 *XLNh, *XLNl, *Oh, *Ol, *XLN2h, *XLN2l, *H1h, *H1l;
};
struct Weights {
    bf16 *WqkvTh, *WqkvTl, *WprojTh, *WprojTl, *W1Th, *W1Tl, *W2Th, *W2Tl;
};

static void get_branch_bufs(int br, BranchBufs& bu)
{
    char* p;
    cudaGetSymbolAddress((void**)&p, g_XLN);  bu.XLN  = (float*)p + (size_t)br * B_ * NTOK * DIM_;
    cudaGetSymbolAddress((void**)&p, g_QKV);  bu.QKV  = (float*)p + (size_t)br * B_ * NTOK * 3 * DIM_;
    cudaGetSymbolAddress((void**)&p, g_Q64);  bu.Q64  = (float*)p + (size_t)br * B_ * LT_ * DIM_;
    cudaGetSymbolAddress((void**)&p, g_ATTN); bu.ATTN = (float*)p + (size_t)br * B_ * H_ * NTOK * NTOK;
    cudaGetSymbolAddress((void**)&p, g_O);    bu.O    = (float*)p + (size_t)br * B_ * NTOK * DIM_;
    cudaGetSymbolAddress((void**)&p, g_X1);   bu.X1   = (float*)p + (size_t)br * B_ * NTOK * DIM_;
    cudaGetSymbolAddress((void**)&p, g_S);    bu.S    = (float*)p + (size_t)br * B_ * LS_;
    cudaGetSymbolAddress((void**)&p, g_ORD);  bu.ORD  = (int*)p   + (size_t)br * B_ * LS_;
    cudaGetSymbolAddress((void**)&p, g_X2);   bu.X2   = (float*)p + (size_t)br * B_ * N2 * DIM_;
    cudaGetSymbolAddress((void**)&p, g_XLN2); bu.XLN2 = (float*)p + (size_t)br * B_ * N2 * DIM_;
    cudaGetSymbolAddress((void**)&p, g_XLNh); bu.XLNh = (bf16*)p + (size_t)br * B_ * NTOK * DIM_;
    cudaGetSymbolAddress((void**)&p, g_XLNl); bu.XLNl = (bf16*)p + (size_t)br * B_ * NTOK * DIM_;
    cudaGetSymbolAddress((void**)&p, g_Oh);   bu.Oh   = (bf16*)p + (size_t)br * B_ * NTOK * DIM_;
    cudaGetSymbolAddress((void**)&p, g_Ol);   bu.Ol   = (bf16*)p + (size_t)br * B_ * NTOK * DIM_;
    cudaGetSymbolAddress((void**)&p, g_XLN2h); bu.XLN2h = (bf16*)p + (size_t)br * B_ * N2 * DIM_;
    cudaGetSymbolAddress((void**)&p, g_XLN2l); bu.XLN2l = (bf16*)p + (size_t)br * B_ * N2 * DIM_;
    cudaGetSymbolAddress((void**)&p, g_H1h);  bu.H1h  = (bf16*)p + (size_t)br * B_ * N2 * 4 * DIM_;
    cudaGetSymbolAddress((void**)&p, g_H1l);  bu.H1l  = (bf16*)p + (size_t)br * B_ * N2 * 4 * DIM_;
}

extern "C" void kernel_launch(void* const* d_in, const int* in_sizes, int n_in,
                              void* d_out, int out_size)
{
    const float* x_rgb  = (const float*)d_in[0];
    const float* x_dte  = (const float*)d_in[1];
    const int*   git    = (const int*)d_in[2];
    const int*   gsi_rgb = (const int*)d_in[3];
    const int*   gsi_dte = (const int*)d_in[4];
    const unsigned char* mask = (const unsigned char*)d_in[5];
    const float* g1    = (const float*)d_in[6];
    const float* b1    = (const float*)d_in[7];
    const float* Wqkv  = (const float*)d_in[8];
    const float* bqkv  = (const float*)d_in[9];
    const float* Wproj = (const float*)d_in[10];
    const float* bproj = (const float*)d_in[11];
    const float* g2    = (const float*)d_in[12];
    const float* b2    = (const float*)d_in[13];
    const float* W1    = (const float*)d_in[14];
    const float* bm1   = (const float*)d_in[15];
    const float* W2    = (const float*)d_in[16];
    const float* bm2   = (const float*)d_in[17];

    float* out = (float*)d_out;

    cudaFuncSetAttribute(tc_gemm2<0, false>, cudaFuncAttributeMaxDynamicSharedMemorySize, TC_SMEM_TOTAL);
    cudaFuncSetAttribute(tc_gemm2<1, true>,  cudaFuncAttributeMaxDynamicSharedMemorySize, TC_SMEM_TOTAL);

    Weights w;
    {
        char* p;
        cudaGetSymbolAddress((void**)&p, g_WqkvTh);  w.WqkvTh  = (bf16*)p;
        cudaGetSymbolAddress((void**)&p, g_WqkvTl);  w.WqkvTl  = (bf16*)p;
        cudaGetSymbolAddress((void**)&p, g_WprojTh); w.WprojTh = (bf16*)p;
        cudaGetSymbolAddress((void**)&p, g_WprojTl); w.WprojTl = (bf16*)p;
        cudaGetSymbolAddress((void**)&p, g_W1Th);    w.W1Th    = (bf16*)p;
        cudaGetSymbolAddress((void**)&p, g_W1Tl);    w.W1Tl    = (bf16*)p;
        cudaGetSymbolAddress((void**)&p, g_W2Th);    w.W2Th    = (bf16*)p;
        cudaGetSymbolAddress((void**)&p, g_W2Tl);    w.W2Tl    = (bf16*)p;
    }
    BranchBufs bu[2];
    get_branch_bufs(0, bu[0]);
    get_branch_bufs(1, bu[1]);

    const long long XSZ     = (long long)B_ * N2 * DIM_;
    const long long GIT_OFF = 2 * XSZ;
    const long long K0_OFF  = GIT_OFF + (long long)B_ * LT_;
    const long long K1_OFF  = K0_OFF + (long long)B_ * LK_;
    const long long R0_OFF  = K1_OFF + (long long)B_ * LK_;
    const long long R1_OFF  = R0_OFF + (long long)B_ * LR_;

    cudaStream_t m0 = (cudaStream_t)0;
    cudaStream_t mS[2] = {m0, g_sp.m1};
    cudaStream_t sS[2] = {g_sp.s0, g_sp.s1};
    cudaEvent_t  evLN[2]   = {g_sp.evLN0, g_sp.evLN1};
    cudaEvent_t  evK[2]    = {g_sp.evK0, g_sp.evK1};
    cudaEvent_t  evSM64[2] = {g_sp.evSM64_0, g_sp.evSM64_1};
    cudaEvent_t  evSORT[2] = {g_sp.evSORT0, g_sp.evSORT1};
    cudaEvent_t  evSEnd[2] = {g_sp.evSEnd0, g_sp.evSEnd1};
    const float* xIn[2]    = {x_rgb, x_dte};
    const int*   gsiIn[2]  = {gsi_rgb, gsi_dte};
    float* outX[2] = {out, out + XSZ};
    float* outK[2] = {out + K0_OFF, out + K1_OFF};
    float* outR[2] = {out + R0_OFF, out + R1_OFF};

    // ---- prologue, ordered so the 6th launch (ncu capture target) is the
    //      branch-0 merged q|v tc_gemm2 ----
    // 1: LN1 branch 0
    ln_kernel<<<B_ * NTOK, 256, 0, m0>>>(xIn[0], g1, b1, bu[0].XLN, bu[0].XLNh, bu[0].XLNl);
    cudaEventRecord(g_sp.evLN0, m0);
    // 2: Wqkv split
    tsplit_kernel<<<dim3(3 * DIM_ / 32, DIM_ / 32), 256, 0, m0>>>(Wqkv, DIM_, 3 * DIM_, w.WqkvTh, w.WqkvTl);
    // 3: git
    git_kernel<<<(B_ * LT_ + 255) / 256, 256, 0, m0>>>(git, out + GIT_OFF);
    // 4: Wproj split
    tsplit_kernel<<<dim3(DIM_ / 32, DIM_ / 32), 256, 0, m0>>>(Wproj, DIM_, DIM_, w.WprojTh, w.WprojTl);
    // 5: W1 split
    tsplit_kernel<<<dim3(4 * DIM_ / 32, DIM_ / 32), 256, 0, m0>>>(W1, DIM_, 4 * DIM_, w.W1Th, w.W1Tl);
    // 6: merged q|v tc GEMM, branch 0  <-- ncu capture (-s 5 -c 1)
    tc_gemm2<0, false><<<dim3(2 * DIM_ / 128, B_ * NTOK / 128), TC_THREADS, TC_SMEM_TOTAL, m0>>>(
        bu[0].XLNh, bu[0].XLNl, DIM_, w.WqkvTh, w.WqkvTl, DIM_,
        bu[0].QKV, 3 * DIM_, nullptr, nullptr, bqkv, nullptr, 0, DIM_, 1);
    // 7: W2 split
    tsplit_kernel<<<dim3(DIM_ / 32, 4 * DIM_ / 32), 256, 0, m0>>>(W2, 4 * DIM_, DIM_, w.W2Th, w.W2Tl);

    cudaEventRecord(g_sp.evFork, m0);
    cudaStreamWaitEvent(g_sp.m1, g_sp.evFork, 0);

    // branch 1: LN1 + merged q|v on m1
    ln_kernel<<<B_ * NTOK, 256, 0, g_sp.m1>>>(xIn[1], g1, b1, bu[1].XLN, bu[1].XLNh, bu[1].XLNl);
    cudaEventRecord(g_sp.evLN1, g_sp.m1);
    tc_gemm2<0, false><<<dim3(2 * DIM_ / 128, B_ * NTOK / 128), TC_THREADS, TC_SMEM_TOTAL, g_sp.m1>>>(
        bu[1].XLNh, bu[1].XLNl, DIM_, w.WqkvTh, w.WqkvTl, DIM_,
        bu[1].QKV, 3 * DIM_, nullptr, nullptr, bqkv, nullptr, 0, DIM_, 1);

    // shared f stream: the two Kahan k GEMMs back-to-back (packed f32x2)
    for (int br = 0; br < 2; br++) {
        cudaStreamWaitEvent(g_sp.f, evLN[br], 0);
        gemm_kernel<false, 0, true, false><<<dim3(DIM_ / BN, B_ * NTOK / BM, 1), 256, 0, g_sp.f>>>(
            bu[br].XLN, DIM_, 0, 0,
            Wqkv + DIM_, 3 * DIM_, 0, 0,
            bu[br].QKV + DIM_, 3 * DIM_, 0, 0,
            nullptr, nullptr,
            bqkv + DIM_, nullptr, 0, 0, 0,
            DIM_, 1, 1.0f);
        cudaEventRecord(evK[br], g_sp.f);
    }

    for (int br = 0; br < 2; br++) {
        cudaStream_t m = mS[br];
        cudaStream_t s = sS[br];

        // ---- score stream ----
        cudaStreamWaitEvent(s, evK[br], 0);
        gemm_kernel<false, 0, true, false><<<dim3(DIM_ / BN, 1, B_), 256, 0, s>>>(
            bu[br].XLN, DIM_, 0, (long long)NTOK * DIM_,
            Wqkv, 3 * DIM_, 0, 0,
            bu[br].Q64, DIM_, 0, (long long)LT_ * DIM_,
            nullptr, nullptr,
            bqkv, nullptr, 0, 0, 0,
            DIM_, B_, 1.0f);
        gemm_kernel<true, 0, true, false><<<dim3(NTOK / BN, 1, B_ * H_), 256, 0, s>>>(
            bu[br].Q64,        DIM_,     (long long)LT_ * DIM_,       DH,
            bu[br].QKV + DIM_, 3 * DIM_, (long long)NTOK * 3 * DIM_,  DH,
            bu[br].ATTN, NTOK, (long long)H_ * NTOK * NTOK, (long long)NTOK * NTOK,
            nullptr, nullptr,
            nullptr, nullptr, 0, 0, 0,
            DH, H_, 0.125f);
        softmax_kernel<<<B_ * H_ * LT_, 128, 0, s>>>(bu[br].ATTN, 0, LT_);
        cudaEventRecord(evSM64[br], s);
        ce_score_kernel<<<B_, 256, 0, s>>>(bu[br].ATTN, mask, bu[br].S);
        sort_kernel<<<B_, 256, 0, s>>>(bu[br].S, bu[br].ORD);
        cudaEventRecord(evSORT[br], s);
        indices_kernel<<<B_, 256, 0, s>>>(bu[br].ORD, gsiIn[br], outK[br], outR[br]);
        cudaEventRecord(evSEnd[br], s);

        // ---- main stream: value path ----
        cudaStreamWaitEvent(m, evK[br], 0);
        gemm_kernel<true, 0, false, false><<<dim3(NTOK / BN, 4, B_ * H_), 256, 0, m>>>(
            bu[br].QKV + (long long)LT_ * 3 * DIM_, 3 * DIM_, (long long)NTOK * 3 * DIM_, DH,
            bu[br].QKV + DIM_,                      3 * DIM_, (long long)NTOK * 3 * DIM_, DH,
            bu[br].ATTN + (long long)LT_ * NTOK, NTOK, (long long)H_ * NTOK * NTOK, (long long)NTOK * NTOK,
            nullptr, nullptr,
            nullptr, nullptr, 0, 0, 0,
            DH, H_, 0.125f);
        softmax_kernel<<<B_ * H_ * LS_, 128, 0, m>>>(bu[br].ATTN, LT_, LS_);

        cudaStreamWaitEvent(m, evSM64[br], 0);
        gemm_kernel<false, 0, false, true><<<dim3(DH / BN, NTOK / BM, B_ * H_), 256, 0, m>>>(
            bu[br].ATTN, NTOK, (long long)H_ * NTOK * NTOK, (long long)NTOK * NTOK,
            bu[br].QKV + 2 * DIM_, 3 * DIM_, (long long)NTOK * 3 * DIM_, DH,
            bu[br].O, DIM_, (long long)NTOK * DIM_, DH,
            bu[br].Oh, bu[br].Ol,
            nullptr, nullptr, 0, 0, 0,
            NTOK, H_, 1.0f);

        tc_gemm2<0, false><<<dim3(DIM_ / 128, B_ * NTOK / 128), TC_THREADS, TC_SMEM_TOTAL, m>>>(
            bu[br].Oh, bu[br].Ol, DIM_, w.WprojTh, w.WprojTl, DIM_,
            bu[br].X1, DIM_, nullptr, nullptr, bproj, xIn[br], DIM_, DIM_, 0);

        cudaStreamWaitEvent(m, evSORT[br], 0);
        gather_kernel<<<dim3(B_, N2), 256, 0, m>>>(bu[br].X1, bu[br].ORD, bu[br].X2);
        ln_kernel<<<B_ * N2, 256, 0, m>>>(bu[br].X2, g2, b2,
                                          bu[br].XLN2, bu[br].XLN2h, bu[br].XLN2l);
        tc_gemm2<1, true><<<dim3(4 * DIM_ / 128, B_ * N2 / 128), TC_THREADS, TC_SMEM_TOTAL, m>>>(
            bu[br].XLN2h, bu[br].XLN2l, DIM_, w.W1Th, w.W1Tl, DIM_,
            nullptr, 4 * DIM_, bu[br].H1h, bu[br].H1l, bm1, nullptr, 0, DIM_, 0);
        tc_gemm2<0, false><<<dim3(DIM_ / 128, B_ * N2 / 128), TC_THREADS, TC_SMEM_TOTAL, m>>>(
            bu[br].H1h, bu[br].H1l, 4 * DIM_, w.W2Th, w.W2Tl, 4 * DIM_,
            outX[br], DIM_, nullptr, nullptr, bm2, bu[br].X2, DIM_, 4 * DIM_, 0);
    }

    // join all side streams into origin
    cudaEventRecord(g_sp.evEnd1, g_sp.m1);
    cudaStreamWaitEvent(m0, g_sp.evEnd1, 0);
    cudaStreamWaitEvent(m0, g_sp.evSEnd0, 0);
    cudaStreamWaitEvent(m0, g_sp.evSEnd1, 0);
}

// round 15
// speedup vs baseline: 1.3277x; 1.0335x over previous
#include <cuda_runtime.h>
#include <cuda_bf16.h>
#include <math.h>
#include <stdint.h>

// ---------------- problem constants ----------------
#define B_    32
#define LT_   64
#define LS_   256
#define NTOK  320      // LT + LS
#define DIM_  768
#define H_    12
#define DH    64
#define LK_   180
#define LR_   76
#define N2    244      // LT + LK

#if defined(__CUDA_ARCH__) && defined(__CUDA_ARCH_FEAT_SM103_ALL)
#define HAS_TCGEN05 1
#else
#define HAS_TCGEN05 0
#endif

typedef __nv_bfloat16 bf16;
typedef unsigned long long u64;

// ---------------- scratch (per-branch duplicated) ----------------
__device__ float g_XLN [2][B_ * NTOK * DIM_];
__device__ float g_QKV [2][B_ * NTOK * 3 * DIM_];
__device__ float g_Q64 [2][B_ * LT_ * DIM_];
__device__ float g_ATTN[2][(size_t)B_ * H_ * NTOK * NTOK];
__device__ float g_O   [2][B_ * NTOK * DIM_];
__device__ float g_X1  [2][B_ * NTOK * DIM_];
__device__ float g_S   [2][B_ * LS_];
__device__ int   g_ORD [2][B_ * LS_];
__device__ float g_X2  [2][B_ * N2 * DIM_];
__device__ float g_XLN2[2][B_ * N2 * DIM_];

__device__ unsigned short g_XLNh [2][B_ * NTOK * DIM_];
__device__ unsigned short g_XLNl [2][B_ * NTOK * DIM_];
__device__ unsigned short g_Oh   [2][B_ * NTOK * DIM_];
__device__ unsigned short g_Ol   [2][B_ * NTOK * DIM_];
__device__ unsigned short g_XLN2h[2][B_ * N2 * DIM_];
__device__ unsigned short g_XLN2l[2][B_ * N2 * DIM_];
__device__ unsigned short g_H1h  [2][B_ * N2 * 4 * DIM_];
__device__ unsigned short g_H1l  [2][B_ * N2 * 4 * DIM_];

// shared weight splits
__device__ unsigned short g_WqkvTh[3 * DIM_ * DIM_];
__device__ unsigned short g_WqkvTl[3 * DIM_ * DIM_];
__device__ unsigned short g_WprojTh[DIM_ * DIM_];
__device__ unsigned short g_WprojTl[DIM_ * DIM_];
__device__ unsigned short g_W1Th [4 * DIM_ * DIM_];
__device__ unsigned short g_W1Tl [4 * DIM_ * DIM_];
__device__ unsigned short g_W2Th [4 * DIM_ * DIM_];
__device__ unsigned short g_W2Tl [4 * DIM_ * DIM_];

__device__ __forceinline__ void split_bf16(float v, bf16& h, bf16& l) {
    h = __float2bfloat16(v);
    l = __float2bfloat16(v - __bfloat162float(h));
}

// ---------------- packed f32x2 helpers (sm_100+ PTX) ----------------
#define PK_FMA2(d, a, b, c) \
    asm("fma.rn.f32x2 %0, %1, %2, %3;" : "=l"(d) : "l"(a), "l"(b), "l"(c))
#define PK_ADD2(d, a, b) \
    asm("add.rn.f32x2 %0, %1, %2;" : "=l"(d) : "l"(a), "l"(b))
#define PK_SUB2(d, a, b) \
    asm("sub.rn.f32x2 %0, %1, %2;" : "=l"(d) : "l"(a), "l"(b))
#define PK_PACK(d, lo, hi) \
    asm("mov.b64 %0, {%1, %2};" : "=l"(d) : "f"(lo), "f"(hi))
#define PK_UNPACK(lo, hi, s) \
    asm("mov.b64 {%0, %1}, %2;" : "=f"(lo), "=f"(hi) : "l"(s))

// =====================================================================
// tcgen05 helpers (sm_103a pass only)
// =====================================================================
#if HAS_TCGEN05
__device__ __forceinline__ uint32_t elect_one_pred() {
    uint32_t pred;
    asm volatile(
        "{\n\t.reg .pred p;\n\telect.sync _|p, 0xFFFFFFFF;\n\tselp.b32 %0, 1, 0, p;\n\t}"
        : "=r"(pred));
    return pred;
}
__device__ __forceinline__ uint32_t smem_to_u32(const void* smem_ptr) {
    uint32_t addr;
    asm("{ .reg .u64 tmp; cvta.to.shared.u64 tmp, %1; cvt.u32.u64 %0, tmp; }"
        : "=r"(addr) : "l"(smem_ptr));
    return addr;
}
__device__ __forceinline__ void cp16(uint32_t s, const void* g) {
    asm volatile("cp.async.cg.shared.global [%0], [%1], 16;" :: "r"(s), "l"(g) : "memory");
}
#define CP_COMMIT() asm volatile("cp.async.commit_group;" ::: "memory")
#define CP_WAIT(n)  asm volatile("cp.async.wait_group %0;" :: "n"(n) : "memory")

#define TCGEN05_ALLOC(a, n) \
    asm volatile("tcgen05.alloc.cta_group::1.sync.aligned.shared::cta.b32 [%0], %1;" \
        :: "r"((uint32_t)(a)), "r"((uint32_t)(n)) : "memory")
#define TCGEN05_DEALLOC(t, n) \
    asm volatile("tcgen05.dealloc.cta_group::1.sync.aligned.b32 %0, %1;" \
        :: "r"(t), "r"((uint32_t)(n)))
#define TCGEN05_RELINQUISH_ALLOC_PERMIT() \
    asm volatile("tcgen05.relinquish_alloc_permit.cta_group::1.sync.aligned;")
#define TCGEN05_COMMIT(m) \
    asm volatile("tcgen05.commit.cta_group::1.mbarrier::arrive::one.shared::cluster.b64 [%0];" \
        :: "r"((uint32_t)(m)) : "memory")
#define TCGEN05_WAIT_LD()  asm volatile("tcgen05.wait::ld.sync.aligned;" ::: "memory")
#define TCGEN05_FENCE_BEFORE() asm volatile("tcgen05.fence::before_thread_sync;" ::: "memory")
#define TCGEN05_FENCE_AFTER()  asm volatile("tcgen05.fence::after_thread_sync;" ::: "memory")
#define FENCE_PROXY_ASYNC_SHARED_CTA() asm volatile("fence.proxy.async.shared::cta;" ::: "memory")
#define MBARRIER_INIT(m, c) \
    asm volatile("mbarrier.init.shared.b64 [%0], %1;" :: "r"((uint32_t)(m)), "r"((uint32_t)(c)) : "memory")
#define MBARRIER_INVAL(m) \
    asm volatile("mbarrier.inval.shared.b64 [%0];" :: "r"((uint32_t)(m)) : "memory")

#define MBARRIER_WAIT_PARITY(mb, pp) do { \
    uint32_t _mbar = (uint32_t)(mb); \
    uint32_t _parity = (uint32_t)(pp); \
    uint32_t _done; \
    asm volatile( \
        "{\n\t.reg .pred p;\n\t" \
        "mbarrier.try_wait.parity.acquire.cta.shared::cta.b64 p, [%1], %2;\n\t" \
        "selp.b32 %0, 1, 0, p;\n\t}" \
        : "=r"(_done) : "r"(_mbar), "r"(_parity) : "memory"); \
    if (!_done) { \
        asm volatile( \
            "{\n\t.reg .pred P1;\n\t" \
            "WAIT_LOOP_%=:\n\t" \
            "mbarrier.try_wait.parity.acquire.cta.shared::cta.b64 P1, [%0], %1, 0x989680;\n\t" \
            "@P1 bra.uni WAIT_DONE_%=;\n\t" \
            "bra.uni WAIT_LOOP_%=;\n\t" \
            "WAIT_DONE_%=:\n\t}" \
            :: "r"(_mbar), "r"(_parity) : "memory"); \
    } \
} while(0)

#define TCGEN05_LD_32X32B_X32(r, tmem_addr) \
    asm volatile( \
        "tcgen05.ld.sync.aligned.32x32b.x32.b32 " \
        "{%0, %1, %2, %3, %4, %5, %6, %7, " \
        " %8, %9, %10, %11, %12, %13, %14, %15, " \
        " %16, %17, %18, %19, %20, %21, %22, %23, " \
        " %24, %25, %26, %27, %28, %29, %30, %31}, [%32];" \
        : "=r"((r)[0]),  "=r"((r)[1]),  "=r"((r)[2]),  "=r"((r)[3]), \
          "=r"((r)[4]),  "=r"((r)[5]),  "=r"((r)[6]),  "=r"((r)[7]), \
          "=r"((r)[8]),  "=r"((r)[9]),  "=r"((r)[10]), "=r"((r)[11]), \
          "=r"((r)[12]), "=r"((r)[13]), "=r"((r)[14]), "=r"((r)[15]), \
          "=r"((r)[16]), "=r"((r)[17]), "=r"((r)[18]), "=r"((r)[19]), \
          "=r"((r)[20]), "=r"((r)[21]), "=r"((r)[22]), "=r"((r)[23]), \
          "=r"((r)[24]), "=r"((r)[25]), "=r"((r)[26]), "=r"((r)[27]), \
          "=r"((r)[28]), "=r"((r)[29]), "=r"((r)[30]), "=r"((r)[31]) \
        : "r"(tmem_addr))

static constexpr uint64_t SMEM_DESC_BASE_SW128 =
    (uint64_t(2)  << 61) | (uint64_t(1) << 46) | (uint64_t(64) << 32) | (uint64_t(1) << 16);
#define MAKE_SMEM_DESC(base_addr) \
    (SMEM_DESC_BASE_SW128 | ((uint64_t)((base_addr) >> 4) & 0x3FFF))

__device__ __forceinline__ void tc_mma_f16_ss(uint32_t d, uint64_t a, uint64_t b,
                                              uint32_t idesc, uint32_t en)
{
    asm volatile(
        "{\n\t.reg .pred p;\n\tsetp.ne.u32 p, %5, 0;\n\t"
        "tcgen05.mma.cta_group::1.kind::f16 [%0], %1, %2, %3, {%4, %4, %4, %4}, p;\n\t}"
        :: "r"(d), "l"(a), "l"(b), "r"(idesc), "r"(0u), "r"(en) : "memory");
}
#endif // HAS_TCGEN05

// =====================================================================
// tc_gemm2: SINGLE-buffer split-bf16 tc GEMM, target 3 CTAs/SM.
// Same SW128 layout / MMA order (bit-identical outputs); slimmed epilogue.
// =====================================================================
#define TC_THREADS 256
#define TC_SMEM_TOTAL (1024 + 4 * 16384)   // 66560 bytes; 3x = 199.7KB/SM
#define TC_IDESC 0x8200490u

template<int ACT, bool OUTSPLIT>
__global__ __launch_bounds__(TC_THREADS, 3)
void tc_gemm2(const bf16* __restrict__ Ah, const bf16* __restrict__ Al, int lda,
              const bf16* __restrict__ Bh, const bf16* __restrict__ Bl, int ldb,
              float* __restrict__ C, int ldc,
              bf16* __restrict__ Ch, bf16* __restrict__ Cl,
              const float* __restrict__ bias,
              const float* __restrict__ Res, int ldr,
              int K, int qv)
{
    const int n0_raw = blockIdx.x * 128;
    int cshift = (qv && n0_raw >= DIM_) ? DIM_ : 0;
    Bh += (long long)cshift * ldb;
    Bl += (long long)cshift * ldb;
#if HAS_TCGEN05
    extern __shared__ char smem[];
    const uint32_t sb = smem_to_u32(smem);
    const int tid = threadIdx.x;
    const int wid = tid >> 5;
    const int lid = tid & 31;
    const int m0 = blockIdx.y * 128;
    const int n0 = n0_raw;

    if (wid == 0) {
        TCGEN05_ALLOC(sb + 0, 128);
        TCGEN05_RELINQUISH_ALLOC_PERMIT();
    }
    if (tid == 0) MBARRIER_INIT(sb + 16, 1);
    __syncthreads();
    uint32_t tmem;
    asm volatile("ld.shared.b32 %0, [%1];" : "=r"(tmem) : "r"(sb));

    const int nk = K >> 6;
    const int lr  = tid >> 3;
    const int lcq = (tid & 7) * 8;
    const uint32_t db = sb + 1024;   // single buffer

    for (int kt = 0; kt < nk; kt++) {
        if (kt >= 1)   // MMA of chunk kt-1 must finish before overwriting buffer
            MBARRIER_WAIT_PARITY(sb + 16, (kt - 1) & 1);
        {
            const bf16* Agh = Ah + (long long)m0 * lda + kt * 64;
            const bf16* Agl = Al + (long long)m0 * lda + kt * 64;
            const bf16* Bgh = Bh + (long long)n0 * ldb + kt * 64;
            const bf16* Bgl = Bl + (long long)n0 * ldb + kt * 64;
            #pragma unroll
            for (int i = 0; i < 4; i++) {
                int r = lr + i * 32;
                uint32_t bo = r * 128 + lcq * 2;
                uint32_t so = bo ^ ((bo >> 3) & 0x70);
                cp16(db + so,          Agh + (long long)r * lda + lcq);
                cp16(db + 16384 + so,  Agl + (long long)r * lda + lcq);
                cp16(db + 32768 + so,  Bgh + (long long)r * ldb + lcq);
                cp16(db + 49152 + so,  Bgl + (long long)r * ldb + lcq);
            }
            CP_COMMIT();
        }
        CP_WAIT(0);
        FENCE_PROXY_ASYNC_SHARED_CTA();
        __syncthreads();

        if (wid == 0) {
            if (elect_one_pred()) {
                uint64_t dAh = MAKE_SMEM_DESC(db);
                uint64_t dAl = MAKE_SMEM_DESC(db + 16384);
                uint64_t dBh = MAKE_SMEM_DESC(db + 32768);
                uint64_t dBl = MAKE_SMEM_DESC(db + 49152);
                #pragma unroll
                for (int k = 0; k < 4; k++)
                    tc_mma_f16_ss(tmem, dAh + k * 2, dBh + k * 2, TC_IDESC,
                                  (kt == 0 && k == 0) ? 0u : 1u);
                #pragma unroll
                for (int k = 0; k < 4; k++)
                    tc_mma_f16_ss(tmem, dAh + k * 2, dBl + k * 2, TC_IDESC, 1u);
                #pragma unroll
                for (int k = 0; k < 4; k++)
                    tc_mma_f16_ss(tmem, dAl + k * 2, dBh + k * 2, TC_IDESC, 1u);
                TCGEN05_COMMIT(sb + 16);
            }
        }
    }

    MBARRIER_WAIT_PARITY(sb + 16, (nk - 1) & 1);
    TCGEN05_FENCE_AFTER();

    if (wid < 4) {
        int m = m0 + wid * 32 + lid;
        float* Crow = C ? (C + (long long)m * ldc + n0 + cshift) : (float*)0;
        bf16* Chrow = OUTSPLIT ? (Ch + (long long)m * ldc + n0) : (bf16*)0;
        bf16* Clrow = OUTSPLIT ? (Cl + (long long)m * ldc + n0) : (bf16*)0;
        const float* Rrow = Res ? (Res + (long long)m * ldr + n0) : (const float*)0;
        #pragma unroll
        for (int cb = 0; cb < 128; cb += 32) {
            uint32_t d[32];
            TCGEN05_LD_32X32B_X32(d, tmem + cb);
            TCGEN05_WAIT_LD();
            // in-place epilogue (no second register array)
            #pragma unroll
            for (int j = 0; j < 32; j++) {
                float v = __uint_as_float(d[j]);
                if (bias) v += bias[n0 + cshift + cb + j];
                if (Rrow) v += Rrow[cb + j];
                if (ACT == 1) v = 0.5f * v * (1.0f + erff(v * 0.70710678118654752f));
                d[j] = __float_as_uint(v);
            }
            if (Crow) {
                #pragma unroll
                for (int q = 0; q < 32; q += 4)
                    *(uint4*)&Crow[cb + q] = *(uint4*)&d[q];
            }
            if (OUTSPLIT) {
                #pragma unroll
                for (int q = 0; q < 32; q += 2) {
                    bf16 h0, l0, h1, l1;
                    split_bf16(__uint_as_float(d[q]), h0, l0);
                    split_bf16(__uint_as_float(d[q + 1]), h1, l1);
                    unsigned int hw = (unsigned int)__bfloat16_as_ushort(h0) |
                                      ((unsigned int)__bfloat16_as_ushort(h1) << 16);
                    unsigned int lw = (unsigned int)__bfloat16_as_ushort(l0) |
                                      ((unsigned int)__bfloat16_as_ushort(l1) << 16);
                    *(unsigned int*)&Chrow[cb + q] = hw;
                    *(unsigned int*)&Clrow[cb + q] = lw;
                }
            }
        }
        TCGEN05_FENCE_BEFORE();
    }
    __syncthreads();
    if (tid == 0) MBARRIER_INVAL(sb + 16);
    __syncthreads();
    if (wid == 0) TCGEN05_DEALLOC(tmem, 128);
#else
    // fp32 fallback (never runs on GB300)
    const int tid = threadIdx.x;
    const int m0 = blockIdx.y * 128;
    const int n0 = n0_raw;
    for (int e = tid; e < 128 * 128; e += TC_THREADS) {
        int mi = e >> 7, ni = e & 127;
        int m = m0 + mi, n = n0 + ni;
        float s = 0.f;
        for (int k = 0; k < K; k++)
            s += (__bfloat162float(Ah[(long long)m * lda + k]) + __bfloat162float(Al[(long long)m * lda + k])) *
                 (__bfloat162float(Bh[(long long)n * ldb + k]) + __bfloat162float(Bl[(long long)n * ldb + k]));
        if (bias) s += bias[n + cshift];
        if (Res)  s += Res[(long long)m * ldr + n];
        if (ACT == 1) s = 0.5f * s * (1.0f + erff(s * 0.70710678118654752f));
        if (C) C[(long long)m * ldc + n + cshift] = s;
        if (OUTSPLIT) {
            bf16 h, l; split_bf16(s, h, l);
            Ch[(long long)m * ldc + n] = h;
            Cl[(long long)m * ldc + n] = l;
        }
    }
#endif
}

// ================= 64x64 GEMM (Kahan-capable, packed f32x2) =================
#define BM 64
#define BN 64
#define BK 16

template<bool TRANSB, int ACT, bool KAHAN, bool OUTSPLIT>
__global__ __launch_bounds__(256)
void gemm_kernel(const float* __restrict__ A, int lda, long long sA1, long long sA2,
                 const float* __restrict__ Bm, int ldb, long long sB1, long long sB2,
                 float* __restrict__ C, int ldc, long long sC1, long long sC2,
                 bf16* __restrict__ Ch, bf16* __restrict__ Cl,
                 const float* __restrict__ bias,
                 const float* __restrict__ Res, int ldr, long long sR1, long long sR2,
                 int K, int bdiv, float alpha)
{
    __shared__ float As[BK][BM + 4];
    __shared__ float Bs[BK][BN + 4];

    int bz = blockIdx.z;
    int ob = bz / bdiv;
    int ib = bz - ob * bdiv;
    A  += ob * sA1 + ib * sA2;
    Bm += ob * sB1 + ib * sB2;
    C  += ob * sC1 + ib * sC2;
    if (OUTSPLIT) { Ch += ob * sC1 + ib * sC2; Cl += ob * sC1 + ib * sC2; }
    if (Res) Res += ob * sR1 + ib * sR2;

    int bm = blockIdx.y * BM;
    int bn = blockIdx.x * BN;
    int tid = threadIdx.x;
    int tx = tid & 15, ty = tid >> 4;

    u64 acc2[4][2] = {};
    u64 ncmp2[4][2] = {};

    for (int k0 = 0; k0 < K; k0 += BK) {
        #pragma unroll
        for (int i = 0; i < 4; i++) {
            int idx = tid + i * 256;
            int m  = idx >> 4;
            int kk = idx & 15;
            As[kk][m] = A[(long long)(bm + m) * lda + k0 + kk];
        }
        if (TRANSB) {
            #pragma unroll
            for (int i = 0; i < 4; i++) {
                int idx = tid + i * 256;
                int n  = idx >> 4;
                int kk = idx & 15;
                Bs[kk][n] = Bm[(long long)(bn + n) * ldb + k0 + kk];
            }
        } else {
            #pragma unroll
            for (int i = 0; i < 4; i++) {
                int idx = tid + i * 256;
                int kk = idx >> 6;
                int n  = idx & 63;
                Bs[kk][n] = Bm[(long long)(k0 + kk) * ldb + bn + n];
            }
        }
        __syncthreads();

        #pragma unroll
        for (int kk = 0; kk < BK; kk++) {
            float4 av = *(const float4*)&As[kk][ty * 4];
            float a4[4] = {av.x, av.y, av.z, av.w};
            const u64* bp = (const u64*)&Bs[kk][tx * 4];
            u64 b2[2] = {bp[0], bp[1]};
            #pragma unroll
            for (int i = 0; i < 4; i++) {
                u64 a2;
                PK_PACK(a2, a4[i], a4[i]);
                #pragma unroll
                for (int j2 = 0; j2 < 2; j2++) {
                    if (KAHAN) {
                        u64 y, t, d;
                        PK_FMA2(y, a2, b2[j2], ncmp2[i][j2]);
                        PK_ADD2(t, acc2[i][j2], y);
                        PK_SUB2(d, t, acc2[i][j2]);
                        PK_SUB2(ncmp2[i][j2], y, d);
                        acc2[i][j2] = t;
                    } else {
                        PK_FMA2(acc2[i][j2], a2, b2[j2], acc2[i][j2]);
                    }
                }
            }
        }
        __syncthreads();
    }

    #pragma unroll
    for (int i = 0; i < 4; i++) {
        int m = bm + ty * 4 + i;
        float accs[4];
        PK_UNPACK(accs[0], accs[1], acc2[i][0]);
        PK_UNPACK(accs[2], accs[3], acc2[i][1]);
        #pragma unroll
        for (int j = 0; j < 4; j++) {
            int n = bn + tx * 4 + j;
            float v = accs[j] * alpha;
            if (bias) v += bias[n];
            if (Res)  v += Res[(long long)m * ldr + n];
            if (ACT == 1) v = 0.5f * v * (1.0f + erff(v * 0.70710678118654752f));
            C[(long long)m * ldc + n] = v;
            if (OUTSPLIT) {
                bf16 h, l;
                split_bf16(v, h, l);
                Ch[(long long)m * ldc + n] = h;
                Cl[(long long)m * ldc + n] = l;
            }
        }
    }
}

// ---------------- transpose + split (weights) ----------------
__global__ __launch_bounds__(256)
void tsplit_kernel(const float* __restrict__ in, int K, int N,
                   bf16* __restrict__ oh, bf16* __restrict__ ol)
{
    __shared__ float tile[32][33];
    int nb = blockIdx.x * 32, kb = blockIdx.y * 32;
    int tx = threadIdx.x & 31, ty = threadIdx.x >> 5;
    #pragma unroll
    for (int i = 0; i < 32; i += 8)
        tile[ty + i][tx] = in[(long long)(kb + ty + i) * N + nb + tx];
    __syncthreads();
    #pragma unroll
    for (int i = 0; i < 32; i += 8) {
        int n = nb + ty + i, k = kb + tx;
        float v = tile[tx][ty + i];
        bf16 h, l;
        split_bf16(v, h, l);
        oh[(long long)n * K + k] = h;
        ol[(long long)n * K + k] = l;
    }
}

// ---------------- LayerNorm, fp64 stats, fp32 + split out ----------------
__global__ __launch_bounds__(256)
void ln_kernel(const float* __restrict__ x, const float* __restrict__ g,
               const float* __restrict__ b, float* __restrict__ y,
               bf16* __restrict__ yh, bf16* __restrict__ yl)
{
    long long row = blockIdx.x;
    const float* xr = x + row * DIM_;
    float* yr = y + row * DIM_;
    bf16* yhr = yh + row * DIM_;
    bf16* ylr = yl + row * DIM_;
    int t = threadIdx.x;
    float v0 = xr[t], v1 = xr[t + 256], v2 = xr[t + 512];
    double s = (double)v0 + (double)v1 + (double)v2;
    double q = (double)v0 * v0 + (double)v1 * v1 + (double)v2 * v2;
    __shared__ double sh[16];
    __shared__ float  par[2];
    #pragma unroll
    for (int o = 16; o > 0; o >>= 1) {
        s += __shfl_down_sync(~0u, s, o);
        q += __shfl_down_sync(~0u, q, o);
    }
    int wid = t >> 5, lane = t & 31;
    if (lane == 0) { sh[wid] = s; sh[wid + 8] = q; }
    __syncthreads();
    if (t == 0) {
        double ss = 0., qq = 0.;
        #pragma unroll
        for (int i = 0; i < 8; i++) { ss += sh[i]; qq += sh[i + 8]; }
        double mu = ss / DIM_;
        double var = qq / DIM_ - mu * mu;
        par[0] = (float)mu;
        par[1] = (float)(1.0 / sqrt(var + 1e-5));
    }
    __syncthreads();
    float mu = par[0], r = par[1];
    #pragma unroll
    for (int i = 0; i < 3; i++) {
        int c = t + i * 256;
        float vv = (i == 0 ? v0 : (i == 1 ? v1 : v2));
        float o = (vv - mu) * r * g[c] + b[c];
        yr[c] = o;
        bf16 h, l;
        split_bf16(o, h, l);
        yhr[c] = h;
        ylr[c] = l;
    }
}

// ---------------- row softmax over 320, row subset [tbase, tbase+tcnt) ----------------
__global__ __launch_bounds__(128)
void softmax_kernel(float* __restrict__ attn, int tbase, int tcnt)
{
    int blk = blockIdx.x;
    int bh = blk / tcnt;
    int t_q = tbase + (blk - bh * tcnt);
    long long row = (long long)bh * NTOK + t_q;
    float* p = attn + row * NTOK;
    int t = threadIdx.x;
    float v[3];
    float m = -1e30f;
    #pragma unroll
    for (int i = 0; i < 3; i++) {
        int c = t + i * 128;
        v[i] = (c < NTOK) ? p[c] : -1e30f;
        m = fmaxf(m, v[i]);
    }
    __shared__ float shm[4];
    __shared__ double shd[4];
    #pragma unroll
    for (int o = 16; o > 0; o >>= 1) m = fmaxf(m, __shfl_xor_sync(~0u, m, o));
    if ((t & 31) == 0) shm[t >> 5] = m;
    __syncthreads();
    m = fmaxf(fmaxf(shm[0], shm[1]), fmaxf(shm[2], shm[3]));
    __syncthreads();

    if (t_q < LT_) {
        double e[3];
        double s = 0.0;
        #pragma unroll
        for (int i = 0; i < 3; i++) {
            int c = t + i * 128;
            if (c < NTOK) { e[i] = exp((double)v[i] - (double)m); s += e[i]; }
            else e[i] = 0.0;
        }
        #pragma unroll
        for (int o = 16; o > 0; o >>= 1) s += __shfl_xor_sync(~0u, s, o);
        if ((t & 31) == 0) shd[t >> 5] = s;
        __syncthreads();
        s = shd[0] + shd[1] + shd[2] + shd[3];
        double inv = 1.0 / s;
        #pragma unroll
        for (int i = 0; i < 3; i++) {
            int c = t + i * 128;
            if (c < NTOK) p[c] = (float)(e[i] * inv);
        }
    } else {
        float e[3];
        float s = 0.0f;
        #pragma unroll
        for (int i = 0; i < 3; i++) {
            int c = t + i * 128;
            if (c < NTOK) { e[i] = __expf(v[i] - m); s += e[i]; }
            else e[i] = 0.0f;
        }
        #pragma unroll
        for (int o = 16; o > 0; o >>= 1) s += __shfl_xor_sync(~0u, s, o);
        if ((t & 31) == 0) shm[t >> 5] = s;
        __syncthreads();
        s = shm[0] + shm[1] + shm[2] + shm[3];
        float inv = 1.0f / s;
        #pragma unroll
        for (int i = 0; i < 3; i++) {
            int c = t + i * 128;
            if (c < NTOK) p[c] = e[i] * inv;
        }
    }
}

// ---------------- CE scores (fp64) ----------------
__global__ __launch_bounds__(256)
void ce_score_kernel(const float* __restrict__ attn, const unsigned char* __restrict__ maskp,
                     float* __restrict__ S)
{
    int b = blockIdx.x;
    int j = threadIdx.x;
    __shared__ float mf[LT_];
    __shared__ double cntsh;
    __shared__ int mode;
    if (j == 0) {
        const unsigned int* w = (const unsigned int*)maskp;
        bool all_int = true, all_flt = true;
        for (int i = 0; i < 512; i++) {
            unsigned int v = w[i];
            if (v != 0u && v != 1u) all_int = false;
            if (v != 0u && v != 0x3F800000u) all_flt = false;
        }
        mode = all_int ? 0 : (all_flt ? 1 : 2);
    }
    __syncthreads();
    if (j < LT_) {
        int mv;
        if (mode == 0)      mv = ((const int*)maskp)[b * LT_ + j] != 0;
        else if (mode == 1) mv = ((const float*)maskp)[b * LT_ + j] != 0.0f;
        else                mv = maskp[b * LT_ + j] != 0;
        mf[j] = mv ? 1.0f : 0.0f;
    }
    __syncthreads();
    if (j == 0) {
        double c = 0.;
        for (int t = 0; t < LT_; t++) c += (double)mf[t];
        cntsh = c;
    }
    __syncthreads();
    double cnt = cntsh;
    double stot = 0.0;
    const float* base = attn + (long long)b * H_ * NTOK * NTOK + LT_ + j;
    for (int h = 0; h < H_; h++) {
        const float* ph = base + (long long)h * NTOK * NTOK;
        double sh = 0.0;
        #pragma unroll 4
        for (int t = 0; t < LT_; t++)
            sh += (double)ph[(long long)t * NTOK] * (double)mf[t];
        stot += sh / cnt;
    }
    S[b * LS_ + j] = (float)(stot / H_);
}

// ---------------- bitonic sort ----------------
__global__ __launch_bounds__(256)
void sort_kernel(const float* __restrict__ S, int* __restrict__ order)
{
    int b = blockIdx.x, t = threadIdx.x;
    __shared__ float val[256];
    __shared__ int   idx[256];
    val[t] = S[b * LS_ + t];
    idx[t] = t;
    __syncthreads();
    for (int k = 2; k <= 256; k <<= 1) {
        for (int j = k >> 1; j > 0; j >>= 1) {
            int p = t ^ j;
            if (p > t) {
                bool desc = ((t & k) == 0);
                float va = val[t], vb = val[p];
                int ia = idx[t], ib = idx[p];
                bool aFirst = (va > vb) || (va == vb && ia < ib);
                if (aFirst != desc) {
                    val[t] = vb; val[p] = va;
                    idx[t] = ib; idx[p] = ia;
                }
            }
            __syncthreads();
        }
    }
    order[b * LS_ + t] = idx[t];
}

// ---------------- gather ----------------
__global__ __launch_bounds__(256)
void gather_kernel(const float* __restrict__ X1, const int* __restrict__ ord,
                   float* __restrict__ X2)
{
    int b = blockIdx.x, t = blockIdx.y;
    int src = (t < LT_) ? t : (LT_ + ord[b * LS_ + (t - LT_)]);
    const float* s = X1 + ((long long)b * NTOK + src) * DIM_;
    float* d = X2 + ((long long)b * N2 + t) * DIM_;
    int i = threadIdx.x;
    d[i] = s[i];
    d[i + 256] = s[i + 256];
    d[i + 512] = s[i + 512];
}

// ---------------- index outputs ----------------
__global__ __launch_bounds__(256)
void indices_kernel(const int* __restrict__ ord, const int* __restrict__ gsi,
                    float* __restrict__ outK, float* __restrict__ outR)
{
    int b = blockIdx.x, t = threadIdx.x;
    if (t < LK_) outK[b * LK_ + t] = (float)gsi[b * LS_ + ord[b * LS_ + t]];
    if (t < LR_) outR[b * LR_ + t] = (float)gsi[b * LS_ + ord[b * LS_ + LK_ + t]];
}

__global__ __launch_bounds__(256)
void git_kernel(const int* __restrict__ git, float* __restrict__ out)
{
    int i = blockIdx.x * 256 + threadIdx.x;
    if (i < B_ * LT_) out[i] = (float)git[i];
}

// ---------------- streams/events (created pre-main) ----------------
struct StreamPool {
    cudaStream_t f, m1, s0, s1;
    cudaEvent_t evFork, evLN0, evLN1, evK0, evK1,
                evSM64_0, evSM64_1, evSORT0, evSORT1,
                evSEnd0, evSEnd1, evEnd1;
    StreamPool() {
        cudaStreamCreateWithFlags(&f,  cudaStreamNonBlocking);
        cudaStreamCreateWithFlags(&m1, cudaStreamNonBlocking);
        cudaStreamCreateWithFlags(&s0, cudaStreamNonBlocking);
        cudaStreamCreateWithFlags(&s1, cudaStreamNonBlocking);
        cudaEvent_t* evs[12] = {&evFork, &evLN0, &evLN1, &evK0, &evK1,
                                &evSM64_0, &evSM64_1, &evSORT0, &evSORT1,
                                &evSEnd0, &evSEnd1, &evEnd1};
        for (int i = 0; i < 12; i++)
            cudaEventCreateWithFlags(evs[i], cudaEventDisableTiming);
    }
};
static StreamPool g_sp;

// ---------------- per-branch buffers ----------------
struct BranchBufs {
    float *XLN, *QKV, *Q64, *ATTN, *O, *X1, *S, *X2, *XLN2;
    int* ORD;
    bf16 *XLNh, *XLNl, *Oh, *Ol, *XLN2h, *XLN2l, *H1h, *H1l;
};
struct Weights {
    bf16 *WqkvTh, *WqkvTl, *WprojTh, *WprojTl, *W1Th, *W1Tl, *W2Th, *W2Tl;
};

static void get_branch_bufs(int br, BranchBufs& bu)
{
    char* p;
    cudaGetSymbolAddress((void**)&p, g_XLN);  bu.XLN  = (float*)p + (size_t)br * B_ * NTOK * DIM_;
    cudaGetSymbolAddress((void**)&p, g_QKV);  bu.QKV  = (float*)p + (size_t)br * B_ * NTOK * 3 * DIM_;
    cudaGetSymbolAddress((void**)&p, g_Q64);  bu.Q64  = (float*)p + (size_t)br * B_ * LT_ * DIM_;
    cudaGetSymbolAddress((void**)&p, g_ATTN); bu.ATTN = (float*)p + (size_t)br * B_ * H_ * NTOK * NTOK;
    cudaGetSymbolAddress((void**)&p, g_O);    bu.O    = (float*)p + (size_t)br * B_ * NTOK * DIM_;
    cudaGetSymbolAddress((void**)&p, g_X1);   bu.X1   = (float*)p + (size_t)br * B_ * NTOK * DIM_;
    cudaGetSymbolAddress((void**)&p, g_S);    bu.S    = (float*)p + (size_t)br * B_ * LS_;
    cudaGetSymbolAddress((void**)&p, g_ORD);  bu.ORD  = (int*)p   + (size_t)br * B_ * LS_;
    cudaGetSymbolAddress((void**)&p, g_X2);   bu.X2   = (float*)p + (size_t)br * B_ * N2 * DIM_;
    cudaGetSymbolAddress((void**)&p, g_XLN2); bu.XLN2 = (float*)p + (size_t)br * B_ * N2 * DIM_;
    cudaGetSymbolAddress((void**)&p, g_XLNh); bu.XLNh = (bf16*)p + (size_t)br * B_ * NTOK * DIM_;
    cudaGetSymbolAddress((void**)&p, g_XLNl); bu.XLNl = (bf16*)p + (size_t)br * B_ * NTOK * DIM_;
    cudaGetSymbolAddress((void**)&p, g_Oh);   bu.Oh   = (bf16*)p + (size_t)br * B_ * NTOK * DIM_;
    cudaGetSymbolAddress((void**)&p, g_Ol);   bu.Ol   = (bf16*)p + (size_t)br * B_ * NTOK * DIM_;
    cudaGetSymbolAddress((void**)&p, g_XLN2h); bu.XLN2h = (bf16*)p + (size_t)br * B_ * N2 * DIM_;
    cudaGetSymbolAddress((void**)&p, g_XLN2l); bu.XLN2l = (bf16*)p + (size_t)br * B_ * N2 * DIM_;
    cudaGetSymbolAddress((void**)&p, g_H1h);  bu.H1h  = (bf16*)p + (size_t)br * B_ * N2 * 4 * DIM_;
    cudaGetSymbolAddress((void**)&p, g_H1l);  bu.H1l  = (bf16*)p + (size_t)br * B_ * N2 * 4 * DIM_;
}

extern "C" void kernel_launch(void* const* d_in, const int* in_sizes, int n_in,
                              void* d_out, int out_size)
{
    const float* x_rgb  = (const float*)d_in[0];
    const float* x_dte  = (const float*)d_in[1];
    const int*   git    = (const int*)d_in[2];
    const int*   gsi_rgb = (const int*)d_in[3];
    const int*   gsi_dte = (const int*)d_in[4];
    const unsigned char* mask = (const unsigned char*)d_in[5];
    const float* g1    = (const float*)d_in[6];
    const float* b1    = (const float*)d_in[7];
    const float* Wqkv  = (const float*)d_in[8];
    const float* bqkv  = (const float*)d_in[9];
    const float* Wproj = (const float*)d_in[10];
    const float* bproj = (const float*)d_in[11];
    const float* g2    = (const float*)d_in[12];
    const float* b2    = (const float*)d_in[13];
    const float* W1    = (const float*)d_in[14];
    const float* bm1   = (const float*)d_in[15];
    const float* W2    = (const float*)d_in[16];
    const float* bm2   = (const float*)d_in[17];

    float* out = (float*)d_out;

    cudaFuncSetAttribute(tc_gemm2<0, false>, cudaFuncAttributeMaxDynamicSharedMemorySize, TC_SMEM_TOTAL);
    cudaFuncSetAttribute(tc_gemm2<1, true>,  cudaFuncAttributeMaxDynamicSharedMemorySize, TC_SMEM_TOTAL);

    Weights w;
    {
        char* p;
        cudaGetSymbolAddress((void**)&p, g_WqkvTh);  w.WqkvTh  = (bf16*)p;
        cudaGetSymbolAddress((void**)&p, g_WqkvTl);  w.WqkvTl  = (bf16*)p;
        cudaGetSymbolAddress((void**)&p, g_WprojTh); w.WprojTh = (bf16*)p;
        cudaGetSymbolAddress((void**)&p, g_WprojTl); w.WprojTl = (bf16*)p;
        cudaGetSymbolAddress((void**)&p, g_W1Th);    w.W1Th    = (bf16*)p;
        cudaGetSymbolAddress((void**)&p, g_W1Tl);    w.W1Tl    = (bf16*)p;
        cudaGetSymbolAddress((void**)&p, g_W2Th);    w.W2Th    = (bf16*)p;
        cudaGetSymbolAddress((void**)&p, g_W2Tl);    w.W2Tl    = (bf16*)p;
    }
    BranchBufs bu[2];
    get_branch_bufs(0, bu[0]);
    get_branch_bufs(1, bu[1]);

    const long long XSZ     = (long long)B_ * N2 * DIM_;
    const long long GIT_OFF = 2 * XSZ;
    const long long K0_OFF  = GIT_OFF + (long long)B_ * LT_;
    const long long K1_OFF  = K0_OFF + (long long)B_ * LK_;
    const long long R0_OFF  = K1_OFF + (long long)B_ * LK_;
    const long long R1_OFF  = R0_OFF + (long long)B_ * LR_;

    cudaStream_t m0 = (cudaStream_t)0;
    cudaStream_t mS[2] = {m0, g_sp.m1};
    cudaStream_t sS[2] = {g_sp.s0, g_sp.s1};
    cudaEvent_t  evLN[2]   = {g_sp.evLN0, g_sp.evLN1};
    cudaEvent_t  evK[2]    = {g_sp.evK0, g_sp.evK1};
    cudaEvent_t  evSM64[2] = {g_sp.evSM64_0, g_sp.evSM64_1};
    cudaEvent_t  evSORT[2] = {g_sp.evSORT0, g_sp.evSORT1};
    cudaEvent_t  evSEnd[2] = {g_sp.evSEnd0, g_sp.evSEnd1};
    const float* xIn[2]    = {x_rgb, x_dte};
    const int*   gsiIn[2]  = {gsi_rgb, gsi_dte};
    float* outX[2] = {out, out + XSZ};
    float* outK[2] = {out + K0_OFF, out + K1_OFF};
    float* outR[2] = {out + R0_OFF, out + R1_OFF};

    // prologue on origin stream
    ln_kernel<<<B_ * NTOK, 256, 0, m0>>>(xIn[0], g1, b1, bu[0].XLN, bu[0].XLNh, bu[0].XLNl);
    cudaEventRecord(g_sp.evLN0, m0);
    tsplit_kernel<<<dim3(3 * DIM_ / 32, DIM_ / 32), 256, 0, m0>>>(Wqkv, DIM_, 3 * DIM_, w.WqkvTh, w.WqkvTl);
    git_kernel<<<(B_ * LT_ + 255) / 256, 256, 0, m0>>>(git, out + GIT_OFF);
    tsplit_kernel<<<dim3(DIM_ / 32, DIM_ / 32), 256, 0, m0>>>(Wproj, DIM_, DIM_, w.WprojTh, w.WprojTl);
    tsplit_kernel<<<dim3(4 * DIM_ / 32, DIM_ / 32), 256, 0, m0>>>(W1, DIM_, 4 * DIM_, w.W1Th, w.W1Tl);
    // merged q|v tc GEMM, branch 0
    tc_gemm2<0, false><<<dim3(2 * DIM_ / 128, B_ * NTOK / 128), TC_THREADS, TC_SMEM_TOTAL, m0>>>(
        bu[0].XLNh, bu[0].XLNl, DIM_, w.WqkvTh, w.WqkvTl, DIM_,
        bu[0].QKV, 3 * DIM_, nullptr, nullptr, bqkv, nullptr, 0, DIM_, 1);
    tsplit_kernel<<<dim3(DIM_ / 32, 4 * DIM_ / 32), 256, 0, m0>>>(W2, 4 * DIM_, DIM_, w.W2Th, w.W2Tl);

    cudaEventRecord(g_sp.evFork, m0);
    cudaStreamWaitEvent(g_sp.m1, g_sp.evFork, 0);

    // branch 1: LN1 + merged q|v on m1
    ln_kernel<<<B_ * NTOK, 256, 0, g_sp.m1>>>(xIn[1], g1, b1, bu[1].XLN, bu[1].XLNh, bu[1].XLNl);
    cudaEventRecord(g_sp.evLN1, g_sp.m1);
    tc_gemm2<0, false><<<dim3(2 * DIM_ / 128, B_ * NTOK / 128), TC_THREADS, TC_SMEM_TOTAL, g_sp.m1>>>(
        bu[1].XLNh, bu[1].XLNl, DIM_, w.WqkvTh, w.WqkvTl, DIM_,
        bu[1].QKV, 3 * DIM_, nullptr, nullptr, bqkv, nullptr, 0, DIM_, 1);

    // shared f stream: the two Kahan k GEMMs back-to-back
    for (int br = 0; br < 2; br++) {
        cudaStreamWaitEvent(g_sp.f, evLN[br], 0);
        gemm_kernel<false, 0, true, false><<<dim3(DIM_ / BN, B_ * NTOK / BM, 1), 256, 0, g_sp.f>>>(
            bu[br].XLN, DIM_, 0, 0,
            Wqkv + DIM_, 3 * DIM_, 0, 0,
            bu[br].QKV + DIM_, 3 * DIM_, 0, 0,
            nullptr, nullptr,
            bqkv + DIM_, nullptr, 0, 0, 0,
            DIM_, 1, 1.0f);
        cudaEventRecord(evK[br], g_sp.f);
    }

    for (int br = 0; br < 2; br++) {
        cudaStream_t m = mS[br];
        cudaStream_t s = sS[br];

        // ---- score stream ----
        cudaStreamWaitEvent(s, evK[br], 0);
        gemm_kernel<false, 0, true, false><<<dim3(DIM_ / BN, 1, B_), 256, 0, s>>>(
            bu[br].XLN, DIM_, 0, (long long)NTOK * DIM_,
            Wqkv, 3 * DIM_, 0, 0,
            bu[br].Q64, DIM_, 0, (long long)LT_ * DIM_,
            nullptr, nullptr,
            bqkv, nullptr, 0, 0, 0,
            DIM_, B_, 1.0f);
        gemm_kernel<true, 0, true, false><<<dim3(NTOK / BN, 1, B_ * H_), 256, 0, s>>>(
            bu[br].Q64,        DIM_,     (long long)LT_ * DIM_,       DH,
            bu[br].QKV + DIM_, 3 * DIM_, (long long)NTOK * 3 * DIM_,  DH,
            bu[br].ATTN, NTOK, (long long)H_ * NTOK * NTOK, (long long)NTOK * NTOK,
            nullptr, nullptr,
            nullptr, nullptr, 0, 0, 0,
            DH, H_, 0.125f);
        softmax_kernel<<<B_ * H_ * LT_, 128, 0, s>>>(bu[br].ATTN, 0, LT_);
        cudaEventRecord(evSM64[br], s);
        ce_score_kernel<<<B_, 256, 0, s>>>(bu[br].ATTN, mask, bu[br].S);
        sort_kernel<<<B_, 256, 0, s>>>(bu[br].S, bu[br].ORD);
        cudaEventRecord(evSORT[br], s);
        indices_kernel<<<B_, 256, 0, s>>>(bu[br].ORD, gsiIn[br], outK[br], outR[br]);
        cudaEventRecord(evSEnd[br], s);

        // ---- main stream: value path ----
        cudaStreamWaitEvent(m, evK[br], 0);
        gemm_kernel<true, 0, false, false><<<dim3(NTOK / BN, 4, B_ * H_), 256, 0, m>>>(
            bu[br].QKV + (long long)LT_ * 3 * DIM_, 3 * DIM_, (long long)NTOK * 3 * DIM_, DH,
            bu[br].QKV + DIM_,                      3 * DIM_, (long long)NTOK * 3 * DIM_, DH,
            bu[br].ATTN + (long long)LT_ * NTOK, NTOK, (long long)H_ * NTOK * NTOK, (long long)NTOK * NTOK,
            nullptr, nullptr,
            nullptr, nullptr, 0, 0, 0,
            DH, H_, 0.125f);
        softmax_kernel<<<B_ * H_ * LS_, 128, 0, m>>>(bu[br].ATTN, LT_, LS_);

        cudaStreamWaitEvent(m, evSM64[br], 0);
        gemm_kernel<false, 0, false, true><<<dim3(DH / BN, NTOK / BM, B_ * H_), 256, 0, m>>>(
            bu[br].ATTN, NTOK, (long long)H_ * NTOK * NTOK, (long long)NTOK * NTOK,
            bu[br].QKV + 2 * DIM_, 3 * DIM_, (long long)NTOK * 3 * DIM_, DH,
            bu[br].O, DIM_, (long long)NTOK * DIM_, DH,
            bu[br].Oh, bu[br].Ol,
            nullptr, nullptr, 0, 0, 0,
            NTOK, H_, 1.0f);

        tc_gemm2<0, false><<<dim3(DIM_ / 128, B_ * NTOK / 128), TC_THREADS, TC_SMEM_TOTAL, m>>>(
            bu[br].Oh, bu[br].Ol, DIM_, w.WprojTh, w.WprojTl, DIM_,
            bu[br].X1, DIM_, nullptr, nullptr, bproj, xIn[br], DIM_, DIM_, 0);

        cudaStreamWaitEvent(m, evSORT[br], 0);
        gather_kernel<<<dim3(B_, N2), 256, 0, m>>>(bu[br].X1, bu[br].ORD, bu[br].X2);
        ln_kernel<<<B_ * N2, 256, 0, m>>>(bu[br].X2, g2, b2,
                                          bu[br].XLN2, bu[br].XLN2h, bu[br].XLN2l);
        tc_gemm2<1, true><<<dim3(4 * DIM_ / 128, B_ * N2 / 128), TC_THREADS, TC_SMEM_TOTAL, m>>>(
            bu[br].XLN2h, bu[br].XLN2l, DIM_, w.W1Th, w.W1Tl, DIM_,
            nullptr, 4 * DIM_, bu[br].H1h, bu[br].H1l, bm1, nullptr, 0, DIM_, 0);
        tc_gemm2<0, false><<<dim3(DIM_ / 128, B_ * N2 / 128), TC_THREADS, TC_SMEM_TOTAL, m>>>(
            bu[br].H1h, bu[br].H1l, 4 * DIM_, w.W2Th, w.W2Tl, 4 * DIM_,
            outX[br], DIM_, nullptr, nullptr, bm2, bu[br].X2, DIM_, 4 * DIM_, 0);
    }

    // join all side streams into origin
    cudaEventRecord(g_sp.evEnd1, g_sp.m1);
    cudaStreamWaitEvent(m0, g_sp.evEnd1, 0);
    cudaStreamWaitEvent(m0, g_sp.evSEnd0, 0);
    cudaStreamWaitEvent(m0, g_sp.evSEnd1, 0);
}